// round 1
// baseline (speedup 1.0000x reference)
#include <cuda_runtime.h>
#include <cstdint>

#define H128 128
static const int CAP_N = 50000;
static const int CAP_E = 800000;

// ---------------- scratch (device globals; no allocation allowed) ----------------
__device__ float g_h  [CAP_N * H128];
__device__ float g_acc[CAP_N * H128];
__device__ float g_A1 [CAP_N * H128];
__device__ float g_A2 [CAP_N * H128];
__device__ float g_A3 [CAP_N * H128];
__device__ float g_B2 [CAP_N * H128];
__device__ float g_B3 [CAP_N * H128];
__device__ float g_e  [CAP_E * H128];
__device__ float g_tmp[CAP_E * H128];

// ---------------- helpers ----------------
__device__ __forceinline__ unsigned long long ffma2(unsigned long long a, unsigned long long b,
                                                    unsigned long long c) {
    unsigned long long d;
    asm("fma.rn.f32x2 %0, %1, %2, %3;" : "=l"(d) : "l"(a), "l"(b), "l"(c));
    return d;
}
__device__ __forceinline__ unsigned long long pack2(float lo, float hi) {
    unsigned long long d;
    asm("mov.b64 %0, {%1, %2};" : "=l"(d) : "f"(lo), "f"(hi));
    return d;
}
__device__ __forceinline__ void red_add_v4(float* p, const float* v) {
    asm volatile("red.global.add.v4.f32 [%0], {%1, %2, %3, %4};"
                 :: "l"(p), "f"(v[0]), "f"(v[1]), "f"(v[2]), "f"(v[3]) : "memory");
}
__device__ __forceinline__ void ld4(float* d, const float* p) {
    float4 v = *reinterpret_cast<const float4*>(p);
    d[0] = v.x; d[1] = v.y; d[2] = v.z; d[3] = v.w;
}
__device__ __forceinline__ void st4(float* p, const float* d) {
    float4 v; v.x = d[0]; v.y = d[1]; v.z = d[2]; v.w = d[3];
    *reinterpret_cast<float4*>(p) = v;
}

// ---------------- zero ----------------
__global__ void zero_kernel(float* __restrict__ p, int n) {
    int i = (blockIdx.x * blockDim.x + threadIdx.x) * 4;
    if (i < n) *reinterpret_cast<float4*>(p + i) = make_float4(0.f, 0.f, 0.f, 0.f);
}

// ---------------- GEMM: out[M,128] = A[M,128] @ W[128,128] (+ bias) ----------------
// 64-row tile, full W in smem, 256 threads, each computes 4 rows x 8 cols via f32x2.
__global__ void __launch_bounds__(256) gemm128_kernel(
    const float* __restrict__ A, const float* __restrict__ W,
    const float* __restrict__ bias, float* __restrict__ out, int M)
{
    extern __shared__ float sm[];
    float* ws = sm;            // 128*128
    float* as = sm + 16384;    // [128][68] transposed A tile (pad 68)
    const int tid = threadIdx.x;

    {   // load W (row-major, same layout as global)
        const float4* W4 = reinterpret_cast<const float4*>(W);
        float4* ws4 = reinterpret_cast<float4*>(ws);
        #pragma unroll
        for (int i = 0; i < 16; i++) ws4[tid + 256 * i] = W4[tid + 256 * i];
    }
    const int brow = blockIdx.x * 64;
    {   // load A tile transposed: as[k][r]
        #pragma unroll
        for (int ii = 0; ii < 8; ii++) {
            int i = tid + 256 * ii;
            int r = i >> 5, k4 = i & 31;
            int gr = brow + r;
            float4 v = make_float4(0.f, 0.f, 0.f, 0.f);
            if (gr < M) v = reinterpret_cast<const float4*>(A)[(size_t)gr * 32 + k4];
            int k = k4 * 4;
            as[(k + 0) * 68 + r] = v.x;
            as[(k + 1) * 68 + r] = v.y;
            as[(k + 2) * 68 + r] = v.z;
            as[(k + 3) * 68 + r] = v.w;
        }
    }
    __syncthreads();

    const int r0 = (tid >> 4) * 4;   // 0..60
    const int c0 = (tid & 15) * 8;   // 0..120
    unsigned long long acc[4][4];
    {
        unsigned long long b0 = 0, b1 = 0, b2 = 0, b3 = 0;
        if (bias) {
            ulonglong2 u0 = *reinterpret_cast<const ulonglong2*>(bias + c0);
            ulonglong2 u1 = *reinterpret_cast<const ulonglong2*>(bias + c0 + 4);
            b0 = u0.x; b1 = u0.y; b2 = u1.x; b3 = u1.y;
        }
        #pragma unroll
        for (int r = 0; r < 4; r++) { acc[r][0] = b0; acc[r][1] = b1; acc[r][2] = b2; acc[r][3] = b3; }
    }

    #pragma unroll 4
    for (int k = 0; k < 128; k++) {
        const float4 a4 = *reinterpret_cast<const float4*>(&as[k * 68 + r0]);
        const ulonglong2 w0 = *reinterpret_cast<const ulonglong2*>(&ws[k * 128 + c0]);
        const ulonglong2 w1 = *reinterpret_cast<const ulonglong2*>(&ws[k * 128 + c0 + 4]);
        unsigned long long av[4];
        av[0] = pack2(a4.x, a4.x); av[1] = pack2(a4.y, a4.y);
        av[2] = pack2(a4.z, a4.z); av[3] = pack2(a4.w, a4.w);
        #pragma unroll
        for (int r = 0; r < 4; r++) {
            acc[r][0] = ffma2(av[r], w0.x, acc[r][0]);
            acc[r][1] = ffma2(av[r], w0.y, acc[r][1]);
            acc[r][2] = ffma2(av[r], w1.x, acc[r][2]);
            acc[r][3] = ffma2(av[r], w1.y, acc[r][3]);
        }
    }

    #pragma unroll
    for (int r = 0; r < 4; r++) {
        int gr = brow + r0 + r;
        if (gr < M) {
            float* po = out + (size_t)gr * 128 + c0;
            ulonglong2 v0; v0.x = acc[r][0]; v0.y = acc[r][1];
            ulonglong2 v1; v1.x = acc[r][2]; v1.y = acc[r][3];
            *reinterpret_cast<ulonglong2*>(po) = v0;
            *reinterpret_cast<ulonglong2*>(po + 4) = v1;
        }
    }
}

// ---------------- embed stage1: out = LN(relu(in @ W + b)) ----------------
// warp per row; thread handles 4 output cols; row vals broadcast via shuffle.
__global__ void __launch_bounds__(256) embed_ln_kernel(
    const float* __restrict__ in, const float* __restrict__ W, const float* __restrict__ bias,
    const float* __restrict__ lng, const float* __restrict__ lnb,
    float* __restrict__ out, int M, int Kin)
{
    const int w = blockIdx.x * 8 + (threadIdx.x >> 5);
    const int lane = threadIdx.x & 31;
    if (w >= M) return;
    const float* xr = in + (size_t)w * Kin;
    float x0 = (lane < Kin) ? xr[lane] : 0.f;
    float x1 = (lane + 32 < Kin) ? xr[lane + 32] : 0.f;

    float a[4];
    ld4(a, bias + lane * 4);
    for (int k = 0; k < Kin; k++) {
        float xk = __shfl_sync(0xffffffffu, (k < 32) ? x0 : x1, k & 31);
        float4 wv = *reinterpret_cast<const float4*>(W + k * 128 + lane * 4);
        a[0] = fmaf(xk, wv.x, a[0]);
        a[1] = fmaf(xk, wv.y, a[1]);
        a[2] = fmaf(xk, wv.z, a[2]);
        a[3] = fmaf(xk, wv.w, a[3]);
    }
    float s = 0.f, q = 0.f;
    #pragma unroll
    for (int i = 0; i < 4; i++) {
        a[i] = fmaxf(a[i], 0.f);
        s += a[i]; q = fmaf(a[i], a[i], q);
    }
    #pragma unroll
    for (int o = 16; o; o >>= 1) {
        s += __shfl_xor_sync(0xffffffffu, s, o);
        q += __shfl_xor_sync(0xffffffffu, q, o);
    }
    const float inv = 1.f / 128.f;
    float m = s * inv;
    float is = rsqrtf(fmaxf(q * inv - m * m, 0.f) + 1e-5f);
    float gg[4], gb[4], o4[4];
    ld4(gg, lng + lane * 4); ld4(gb, lnb + lane * 4);
    #pragma unroll
    for (int i = 0; i < 4; i++) o4[i] = (a[i] - m) * is * gg[i] + gb[i];
    st4(out + (size_t)w * 128 + lane * 4, o4);
}

// ---------------- edge layer (warp per edge) ----------------
__global__ void __launch_bounds__(256) edge_layer_kernel(
    const int* __restrict__ rows, const int* __restrict__ cols,
    float* __restrict__ e, const float* __restrict__ b1e,
    const float* __restrict__ A2, const float* __restrict__ A3,
    const float* __restrict__ B2, const float* __restrict__ B3,
    const float* __restrict__ lng, const float* __restrict__ lnb,
    float* __restrict__ acc, int E_)
{
    const int w = blockIdx.x * 8 + (threadIdx.x >> 5);
    const int lane = threadIdx.x & 31;
    if (w >= E_) return;
    const int r = rows[w], c = cols[w];
    const size_t eo = (size_t)w * 128 + lane * 4;
    const size_t ro = (size_t)r * 128 + lane * 4;
    const size_t co = (size_t)c * 128 + lane * 4;

    float ev[4], b1[4], b2r[4], b3r[4], a2r[4], b2c[4], b3c[4], a3c[4];
    ld4(ev, e + eo);  ld4(b1, b1e + eo);
    ld4(b2r, B2 + ro); ld4(b3r, B3 + ro); ld4(a2r, A2 + ro);
    ld4(b2c, B2 + co); ld4(b3c, B3 + co); ld4(a3c, A3 + co);

    float gji[4], gik[4];
    float s1 = 0.f, q1 = 0.f, s2 = 0.f, q2 = 0.f;
    #pragma unroll
    for (int i = 0; i < 4; i++) {
        float u = fmaxf(b1[i] + b2r[i] + b3c[i], 0.f);
        float v = fmaxf(b1[i] + b2c[i] + b3r[i], 0.f);
        gji[i] = u; gik[i] = v;
        s1 += u; q1 = fmaf(u, u, q1);
        s2 += v; q2 = fmaf(v, v, q2);
    }
    #pragma unroll
    for (int o = 16; o; o >>= 1) {
        s1 += __shfl_xor_sync(0xffffffffu, s1, o);
        q1 += __shfl_xor_sync(0xffffffffu, q1, o);
        s2 += __shfl_xor_sync(0xffffffffu, s2, o);
        q2 += __shfl_xor_sync(0xffffffffu, q2, o);
    }
    const float inv = 1.f / 128.f;
    float m1 = s1 * inv, m2 = s2 * inv;
    float is1 = rsqrtf(fmaxf(q1 * inv - m1 * m1, 0.f) + 1e-5f);
    float is2 = rsqrtf(fmaxf(q2 * inv - m2 * m2, 0.f) + 1e-5f);

    float gg[4], gb[4];
    ld4(gg, lng + lane * 4); ld4(gb, lnb + lane * 4);

    float eji[4], sg1[4], sg2[4];
    float t1 = 0.f, t2 = 0.f;
    #pragma unroll
    for (int i = 0; i < 4; i++) {
        eji[i]    = ev[i] + (gji[i] - m1) * is1 * gg[i] + gb[i];
        float eik = ev[i] + (gik[i] - m2) * is2 * gg[i] + gb[i];
        sg1[i] = __fdividef(1.f, 1.f + __expf(-eji[i])); t1 += sg1[i];
        sg2[i] = __fdividef(1.f, 1.f + __expf(-eik));    t2 += sg2[i];
    }
    #pragma unroll
    for (int o = 16; o; o >>= 1) {
        t1 += __shfl_xor_sync(0xffffffffu, t1, o);
        t2 += __shfl_xor_sync(0xffffffffu, t2, o);
    }
    float w1 = __fdividef(1.f, t1 + 1e-6f);
    float w2 = __fdividef(1.f, t2 + 1e-6f);

    float mji[4], mik[4];
    #pragma unroll
    for (int i = 0; i < 4; i++) {
        mji[i] = a2r[i] * sg1[i] * w1;   // -> segment_sum over col
        mik[i] = a3c[i] * sg2[i] * w2;   // -> segment_sum over row
    }
    red_add_v4(acc + co, mji);
    red_add_v4(acc + ro, mik);
    st4(e + eo, eji);   // new e for next layer
}

// ---------------- node update: h += LN(relu(A1h + acc)); acc = 0 ----------------
__global__ void __launch_bounds__(256) node_update_kernel(
    const float* __restrict__ A1, float* __restrict__ acc, float* __restrict__ h,
    const float* __restrict__ lng, const float* __restrict__ lnb, int M)
{
    const int w = blockIdx.x * 8 + (threadIdx.x >> 5);
    const int lane = threadIdx.x & 31;
    if (w >= M) return;
    const size_t off = (size_t)w * 128 + lane * 4;
    float a[4], cc[4], t[4];
    ld4(a, A1 + off); ld4(cc, acc + off);
    float s = 0.f, q = 0.f;
    #pragma unroll
    for (int i = 0; i < 4; i++) {
        t[i] = fmaxf(a[i] + cc[i], 0.f);
        s += t[i]; q = fmaf(t[i], t[i], q);
    }
    #pragma unroll
    for (int o = 16; o; o >>= 1) {
        s += __shfl_xor_sync(0xffffffffu, s, o);
        q += __shfl_xor_sync(0xffffffffu, q, o);
    }
    const float inv = 1.f / 128.f;
    float m = s * inv;
    float is = rsqrtf(fmaxf(q * inv - m * m, 0.f) + 1e-5f);
    float gg[4], gb[4], hv[4];
    ld4(gg, lng + lane * 4); ld4(gb, lnb + lane * 4);
    ld4(hv, h + off);
    #pragma unroll
    for (int i = 0; i < 4; i++) hv[i] += (t[i] - m) * is * gg[i] + gb[i];
    st4(h + off, hv);
    float z[4] = {0.f, 0.f, 0.f, 0.f};
    st4(acc + off, z);   // ready for next layer / next replay
}

// ---------------- final scorer (warp per edge) ----------------
__global__ void __launch_bounds__(256) final_kernel(
    const int* __restrict__ rows, const int* __restrict__ cols,
    const float* __restrict__ ha, const float* __restrict__ hb, const float* __restrict__ ec,
    const float* __restrict__ s1b, const float* __restrict__ s2w, const float* __restrict__ s2b,
    float* __restrict__ out, int E_)
{
    const int w = blockIdx.x * 8 + (threadIdx.x >> 5);
    const int lane = threadIdx.x & 31;
    if (w >= E_) return;
    const int r = rows[w], c = cols[w];
    float A[4], B[4], C[4], b4[4], wv[4];
    ld4(A, ha + (size_t)r * 128 + lane * 4);
    ld4(B, hb + (size_t)c * 128 + lane * 4);
    ld4(C, ec + (size_t)w * 128 + lane * 4);
    ld4(b4, s1b + lane * 4);
    ld4(wv, s2w + lane * 4);
    float p = 0.f;
    #pragma unroll
    for (int i = 0; i < 4; i++) {
        float u = fmaxf(A[i] + B[i] + C[i] + b4[i], 0.f);
        p = fmaf(u, wv[i], p);
    }
    #pragma unroll
    for (int o = 16; o; o >>= 1) p += __shfl_xor_sync(0xffffffffu, p, o);
    if (lane == 0) out[w] = p + s2b[0];
}

// ---------------- host ----------------
extern "C" void kernel_launch(void* const* d_in, const int* in_sizes, int n_in,
                              void* d_out, int out_size)
{
    const float* x    = (const float*)d_in[0];
    const float* ea   = (const float*)d_in[1];
    const int*   ei   = (const int*)  d_in[2];
    const float* W11w = (const float*)d_in[3];
    const float* W11b = (const float*)d_in[4];
    const float* W12w = (const float*)d_in[5];
    const float* W12b = (const float*)d_in[6];
    const float* W21w = (const float*)d_in[7];
    const float* W21b = (const float*)d_in[8];
    const float* W22w = (const float*)d_in[9];
    const float* W22b = (const float*)d_in[10];
    const float* ln1g = (const float*)d_in[11];
    const float* ln1b = (const float*)d_in[12];
    const float* ln2g = (const float*)d_in[13];
    const float* ln2b = (const float*)d_in[14];
    const float* Aw   = (const float*)d_in[15];
    const float* Ab   = (const float*)d_in[16];
    const float* Bw   = (const float*)d_in[17];
    const float* Bb   = (const float*)d_in[18];
    const float* lnhg = (const float*)d_in[19];
    const float* lnhb = (const float*)d_in[20];
    const float* lneg = (const float*)d_in[21];
    const float* lneb = (const float*)d_in[22];
    const float* s1w  = (const float*)d_in[23];
    const float* s1b  = (const float*)d_in[24];
    const float* s2w  = (const float*)d_in[25];
    const float* s2b  = (const float*)d_in[26];

    int Nn = in_sizes[0] / 64;
    int Ee = in_sizes[2] / 2;
    if (Nn > CAP_N) Nn = CAP_N;
    if (Ee > CAP_E) Ee = CAP_E;

    float *ph, *pacc, *pA1, *pA2, *pA3, *pB2, *pB3, *pe, *ptmp;
    cudaGetSymbolAddress((void**)&ph,   g_h);
    cudaGetSymbolAddress((void**)&pacc, g_acc);
    cudaGetSymbolAddress((void**)&pA1,  g_A1);
    cudaGetSymbolAddress((void**)&pA2,  g_A2);
    cudaGetSymbolAddress((void**)&pA3,  g_A3);
    cudaGetSymbolAddress((void**)&pB2,  g_B2);
    cudaGetSymbolAddress((void**)&pB3,  g_B3);
    cudaGetSymbolAddress((void**)&pe,   g_e);
    cudaGetSymbolAddress((void**)&ptmp, g_tmp);

    const int SMEM = (16384 + 128 * 68) * (int)sizeof(float);   // 100352 B
    cudaFuncSetAttribute(gemm128_kernel, cudaFuncAttributeMaxDynamicSharedMemorySize, SMEM);

    auto gemm = [&](const float* A, const float* W, const float* b, float* o, int M) {
        gemm128_kernel<<<(M + 63) / 64, 256, SMEM>>>(A, W, b, o, M);
    };

    // node embed: h = LN(relu(x@W11+b)) @ W12 + b     (uses acc as temp)
    embed_ln_kernel<<<(Nn + 7) / 8, 256>>>(x, W11w, W11b, ln1g, ln1b, pacc, Nn, 64);
    gemm(pacc, W12w, W12b, ph, Nn);
    // edge embed: e = LN(relu(ea@W21+b)) @ W22 + b
    embed_ln_kernel<<<(Ee + 7) / 8, 256>>>(ea, W21w, W21b, ln2g, ln2b, ptmp, Ee, 32);
    gemm(ptmp, W22w, W22b, pe, Ee);

    // zero the scatter accumulator
    zero_kernel<<<(Nn * 128 / 4 + 255) / 256, 256>>>(pacc, Nn * 128);

    for (int l = 0; l < 3; l++) {
        const float* Awl = Aw + (size_t)l * 3 * 128 * 128;
        const float* Abl = Ab + (size_t)l * 3 * 128;
        const float* Bwl = Bw + (size_t)l * 3 * 128 * 128;
        const float* Bbl = Bb + (size_t)l * 3 * 128;
        gemm(ph, Awl,          Abl,        pA1, Nn);   // A1h
        gemm(ph, Awl + 16384,  Abl + 128,  pA2, Nn);   // A2h
        gemm(ph, Awl + 32768,  Abl + 256,  pA3, Nn);   // A3h
        gemm(ph, Bwl + 16384,  Bbl + 128,  pB2, Nn);   // B2h
        gemm(ph, Bwl + 32768,  Bbl + 256,  pB3, Nn);   // B3h
        gemm(pe, Bwl,          Bbl,        ptmp, Ee);  // B1e
        edge_layer_kernel<<<(Ee + 7) / 8, 256>>>(ei, ei + Ee, pe, ptmp, pA2, pA3, pB2, pB3,
                                                 lneg + l * 128, lneb + l * 128, pacc, Ee);
        node_update_kernel<<<(Nn + 7) / 8, 256>>>(pA1, pacc, ph,
                                                  lnhg + l * 128, lnhb + l * 128, Nn);
    }

    // final scorer: score = relu(h[row]@Sa + h[col]@Sb + e@Sc + s1b) @ s2w + s2b
    gemm(ph, s1w,           nullptr, pA1,  Nn);   // ha
    gemm(ph, s1w + 16384,   nullptr, pA2,  Nn);   // hb
    gemm(pe, s1w + 32768,   nullptr, ptmp, Ee);   // ec
    final_kernel<<<(Ee + 7) / 8, 256>>>(ei, ei + Ee, pA1, pA2, ptmp,
                                        s1b, s2w, s2b, (float*)d_out, Ee);
}

// round 2
// speedup vs baseline: 1.4123x; 1.4123x over previous
#include <cuda_runtime.h>
#include <cstdint>

#define H128 128
static const int CAP_N = 50000;
static const int CAP_E = 800000;

// ---------------- scratch (device globals; no allocation allowed) ----------------
__device__ float g_h  [CAP_N * H128];
__device__ float g_acc[CAP_N * H128];
__device__ float g_A1 [CAP_N * H128];
__device__ float g_A2 [CAP_N * H128];
__device__ float g_A3 [CAP_N * H128];
__device__ float g_B2 [CAP_N * H128];
__device__ float g_B3 [CAP_N * H128];
__device__ float g_e  [CAP_E * H128];
__device__ float g_tmp[CAP_E * H128];

// ---------------- helpers ----------------
__device__ __forceinline__ unsigned long long ffma2(unsigned long long a, unsigned long long b,
                                                    unsigned long long c) {
    unsigned long long d;
    asm("fma.rn.f32x2 %0, %1, %2, %3;" : "=l"(d) : "l"(a), "l"(b), "l"(c));
    return d;
}
__device__ __forceinline__ unsigned long long pack2(float lo, float hi) {
    unsigned long long d;
    asm("mov.b64 %0, {%1, %2};" : "=l"(d) : "f"(lo), "f"(hi));
    return d;
}
__device__ __forceinline__ void red_add_v4(float* p, const float* v) {
    asm volatile("red.global.add.v4.f32 [%0], {%1, %2, %3, %4};"
                 :: "l"(p), "f"(v[0]), "f"(v[1]), "f"(v[2]), "f"(v[3]) : "memory");
}
__device__ __forceinline__ void ld4(float* d, const float* p) {
    float4 v = *reinterpret_cast<const float4*>(p);
    d[0] = v.x; d[1] = v.y; d[2] = v.z; d[3] = v.w;
}
__device__ __forceinline__ void st4(float* p, const float* d) {
    float4 v; v.x = d[0]; v.y = d[1]; v.z = d[2]; v.w = d[3];
    *reinterpret_cast<float4*>(p) = v;
}

// ---------------- zero ----------------
__global__ void zero_kernel(float* __restrict__ p, int n) {
    int i = (blockIdx.x * blockDim.x + threadIdx.x) * 4;
    if (i < n) *reinterpret_cast<float4*>(p + i) = make_float4(0.f, 0.f, 0.f, 0.f);
}

// ---------------- multi-weight GEMM ----------------
// out_w[M,128] = A[M,128] @ W_w[128,128] (+ bias_w)  for w < nw (<=5)
// 128 threads, block tile 128x128, thread tile 8 rows x 16 cols.
// rows = rt*4 + {0..3} and +64 ; cols = ct*4 + 32*m, m=0..3  (conflict-free LDS)
struct G5 {
    const float* W[5];
    const float* B[5];
    float*       O[5];
    int nw;
};

__global__ void __launch_bounds__(128) gemm_multi_kernel(
    const float* __restrict__ A, G5 g, int M)
{
    extern __shared__ float sm[];
    float* ws = sm;             // [64][128] W chunk (32768 B)
    float* as = sm + 8192;      // [128][132] A tile row-major (67584 B)
    float4* as4 = reinterpret_cast<float4*>(as);
    const int t = threadIdx.x;
    const int rt = t >> 3;          // 0..15
    const int ct = t & 7;           // 0..7
    const int brow = blockIdx.x * 128;

    // load A tile (row-major, stride 132 floats = 33 float4)
    {
        const float4* A4 = reinterpret_cast<const float4*>(A);
        #pragma unroll
        for (int j = 0; j < 32; j++) {
            int flat = j * 128 + t;
            int row = flat >> 5, k4 = flat & 31;
            float4 v = make_float4(0.f, 0.f, 0.f, 0.f);
            int gr = brow + row;
            if (gr < M) v = A4[(size_t)gr * 32 + k4];
            as4[row * 33 + k4] = v;
        }
    }

    int rowg[8];
    #pragma unroll
    for (int r8 = 0; r8 < 8; r8++) rowg[r8] = rt * 4 + (r8 & 3) + ((r8 >> 2) << 6);

    for (int w = 0; w < g.nw; w++) {
        const float* W = g.W[w];
        const float* bias = g.B[w];
        unsigned long long acc[8][8];
        {
            unsigned long long b[8];
            #pragma unroll
            for (int m = 0; m < 4; m++) {
                if (bias) {
                    ulonglong2 u = *reinterpret_cast<const ulonglong2*>(bias + ct * 4 + 32 * m);
                    b[2 * m] = u.x; b[2 * m + 1] = u.y;
                } else { b[2 * m] = 0ull; b[2 * m + 1] = 0ull; }
            }
            #pragma unroll
            for (int r8 = 0; r8 < 8; r8++)
                #pragma unroll
                for (int c = 0; c < 8; c++) acc[r8][c] = b[c];
        }

        #pragma unroll 1
        for (int ch = 0; ch < 2; ch++) {
            const int kc = ch * 64;
            __syncthreads();
            // load W chunk [64][128]
            {
                const float4* W4 = reinterpret_cast<const float4*>(W);
                float4* ws4 = reinterpret_cast<float4*>(ws);
                #pragma unroll
                for (int j = 0; j < 16; j++) {
                    int flat = j * 128 + t;
                    int wk = flat >> 5, c4 = flat & 31;
                    ws4[wk * 32 + c4] = W4[(size_t)(kc + wk) * 32 + c4];
                }
            }
            __syncthreads();

            #pragma unroll 2
            for (int k4 = 0; k4 < 16; k4++) {
                float4 a[8];
                const int kq = (kc >> 2) + k4;
                #pragma unroll
                for (int r8 = 0; r8 < 8; r8++) a[r8] = as4[rowg[r8] * 33 + kq];
                #pragma unroll
                for (int kk = 0; kk < 4; kk++) {
                    unsigned long long av[8];
                    #pragma unroll
                    for (int r8 = 0; r8 < 8; r8++) {
                        float s = (kk == 0) ? a[r8].x : (kk == 1) ? a[r8].y :
                                  (kk == 2) ? a[r8].z : a[r8].w;
                        av[r8] = pack2(s, s);
                    }
                    const float* wr = ws + (k4 * 4 + kk) * 128 + ct * 4;
                    #pragma unroll
                    for (int m = 0; m < 4; m++) {
                        ulonglong2 u = *reinterpret_cast<const ulonglong2*>(wr + 32 * m);
                        #pragma unroll
                        for (int r8 = 0; r8 < 8; r8++) {
                            acc[r8][2 * m]     = ffma2(av[r8], u.x, acc[r8][2 * m]);
                            acc[r8][2 * m + 1] = ffma2(av[r8], u.y, acc[r8][2 * m + 1]);
                        }
                    }
                }
            }
        }

        // store
        float* out = g.O[w];
        #pragma unroll
        for (int r8 = 0; r8 < 8; r8++) {
            int gr = brow + rowg[r8];
            if (gr < M) {
                float* po = out + (size_t)gr * 128 + ct * 4;
                #pragma unroll
                for (int m = 0; m < 4; m++) {
                    ulonglong2 u; u.x = acc[r8][2 * m]; u.y = acc[r8][2 * m + 1];
                    *reinterpret_cast<ulonglong2*>(po + 32 * m) = u;
                }
            }
        }
    }
}

// ---------------- embed stage1: out = LN(relu(in @ W + b)) ----------------
__global__ void __launch_bounds__(256) embed_ln_kernel(
    const float* __restrict__ in, const float* __restrict__ W, const float* __restrict__ bias,
    const float* __restrict__ lng, const float* __restrict__ lnb,
    float* __restrict__ out, int M, int Kin)
{
    const int w = blockIdx.x * 8 + (threadIdx.x >> 5);
    const int lane = threadIdx.x & 31;
    if (w >= M) return;
    const float* xr = in + (size_t)w * Kin;
    float x0 = (lane < Kin) ? xr[lane] : 0.f;
    float x1 = (lane + 32 < Kin) ? xr[lane + 32] : 0.f;

    float a[4];
    ld4(a, bias + lane * 4);
    for (int k = 0; k < Kin; k++) {
        float xk = __shfl_sync(0xffffffffu, (k < 32) ? x0 : x1, k & 31);
        float4 wv = *reinterpret_cast<const float4*>(W + k * 128 + lane * 4);
        a[0] = fmaf(xk, wv.x, a[0]);
        a[1] = fmaf(xk, wv.y, a[1]);
        a[2] = fmaf(xk, wv.z, a[2]);
        a[3] = fmaf(xk, wv.w, a[3]);
    }
    float s = 0.f, q = 0.f;
    #pragma unroll
    for (int i = 0; i < 4; i++) {
        a[i] = fmaxf(a[i], 0.f);
        s += a[i]; q = fmaf(a[i], a[i], q);
    }
    #pragma unroll
    for (int o = 16; o; o >>= 1) {
        s += __shfl_xor_sync(0xffffffffu, s, o);
        q += __shfl_xor_sync(0xffffffffu, q, o);
    }
    const float inv = 1.f / 128.f;
    float m = s * inv;
    float is = rsqrtf(fmaxf(q * inv - m * m, 0.f) + 1e-5f);
    float gg[4], gb[4], o4[4];
    ld4(gg, lng + lane * 4); ld4(gb, lnb + lane * 4);
    #pragma unroll
    for (int i = 0; i < 4; i++) o4[i] = (a[i] - m) * is * gg[i] + gb[i];
    st4(out + (size_t)w * 128 + lane * 4, o4);
}

// ---------------- edge layer (warp per edge) ----------------
__global__ void __launch_bounds__(256) edge_layer_kernel(
    const int* __restrict__ rows, const int* __restrict__ cols,
    float* __restrict__ e, const float* __restrict__ b1e,
    const float* __restrict__ A2, const float* __restrict__ A3,
    const float* __restrict__ B2, const float* __restrict__ B3,
    const float* __restrict__ lng, const float* __restrict__ lnb,
    float* __restrict__ acc, int E_)
{
    const int w = blockIdx.x * 8 + (threadIdx.x >> 5);
    const int lane = threadIdx.x & 31;
    if (w >= E_) return;
    const int r = rows[w], c = cols[w];
    const size_t eo = (size_t)w * 128 + lane * 4;
    const size_t ro = (size_t)r * 128 + lane * 4;
    const size_t co = (size_t)c * 128 + lane * 4;

    float ev[4], b1[4], b2r[4], b3r[4], a2r[4], b2c[4], b3c[4], a3c[4];
    ld4(ev, e + eo);  ld4(b1, b1e + eo);
    ld4(b2r, B2 + ro); ld4(b3r, B3 + ro); ld4(a2r, A2 + ro);
    ld4(b2c, B2 + co); ld4(b3c, B3 + co); ld4(a3c, A3 + co);

    float gji[4], gik[4];
    float s1 = 0.f, q1 = 0.f, s2 = 0.f, q2 = 0.f;
    #pragma unroll
    for (int i = 0; i < 4; i++) {
        float u = fmaxf(b1[i] + b2r[i] + b3c[i], 0.f);
        float v = fmaxf(b1[i] + b2c[i] + b3r[i], 0.f);
        gji[i] = u; gik[i] = v;
        s1 += u; q1 = fmaf(u, u, q1);
        s2 += v; q2 = fmaf(v, v, q2);
    }
    #pragma unroll
    for (int o = 16; o; o >>= 1) {
        s1 += __shfl_xor_sync(0xffffffffu, s1, o);
        q1 += __shfl_xor_sync(0xffffffffu, q1, o);
        s2 += __shfl_xor_sync(0xffffffffu, s2, o);
        q2 += __shfl_xor_sync(0xffffffffu, q2, o);
    }
    const float inv = 1.f / 128.f;
    float m1 = s1 * inv, m2 = s2 * inv;
    float is1 = rsqrtf(fmaxf(q1 * inv - m1 * m1, 0.f) + 1e-5f);
    float is2 = rsqrtf(fmaxf(q2 * inv - m2 * m2, 0.f) + 1e-5f);

    float gg[4], gb[4];
    ld4(gg, lng + lane * 4); ld4(gb, lnb + lane * 4);

    float eji[4], sg1[4], sg2[4];
    float t1 = 0.f, t2 = 0.f;
    #pragma unroll
    for (int i = 0; i < 4; i++) {
        eji[i]    = ev[i] + (gji[i] - m1) * is1 * gg[i] + gb[i];
        float eik = ev[i] + (gik[i] - m2) * is2 * gg[i] + gb[i];
        sg1[i] = __fdividef(1.f, 1.f + __expf(-eji[i])); t1 += sg1[i];
        sg2[i] = __fdividef(1.f, 1.f + __expf(-eik));    t2 += sg2[i];
    }
    #pragma unroll
    for (int o = 16; o; o >>= 1) {
        t1 += __shfl_xor_sync(0xffffffffu, t1, o);
        t2 += __shfl_xor_sync(0xffffffffu, t2, o);
    }
    float w1 = __fdividef(1.f, t1 + 1e-6f);
    float w2 = __fdividef(1.f, t2 + 1e-6f);

    float mji[4], mik[4];
    #pragma unroll
    for (int i = 0; i < 4; i++) {
        mji[i] = a2r[i] * sg1[i] * w1;
        mik[i] = a3c[i] * sg2[i] * w2;
    }
    red_add_v4(acc + co, mji);
    red_add_v4(acc + ro, mik);
    st4(e + eo, eji);
}

// ---------------- node update: h += LN(relu(A1h + acc)); acc = 0 ----------------
__global__ void __launch_bounds__(256) node_update_kernel(
    const float* __restrict__ A1, float* __restrict__ acc, float* __restrict__ h,
    const float* __restrict__ lng, const float* __restrict__ lnb, int M)
{
    const int w = blockIdx.x * 8 + (threadIdx.x >> 5);
    const int lane = threadIdx.x & 31;
    if (w >= M) return;
    const size_t off = (size_t)w * 128 + lane * 4;
    float a[4], cc[4], t[4];
    ld4(a, A1 + off); ld4(cc, acc + off);
    float s = 0.f, q = 0.f;
    #pragma unroll
    for (int i = 0; i < 4; i++) {
        t[i] = fmaxf(a[i] + cc[i], 0.f);
        s += t[i]; q = fmaf(t[i], t[i], q);
    }
    #pragma unroll
    for (int o = 16; o; o >>= 1) {
        s += __shfl_xor_sync(0xffffffffu, s, o);
        q += __shfl_xor_sync(0xffffffffu, q, o);
    }
    const float inv = 1.f / 128.f;
    float m = s * inv;
    float is = rsqrtf(fmaxf(q * inv - m * m, 0.f) + 1e-5f);
    float gg[4], gb[4], hv[4];
    ld4(gg, lng + lane * 4); ld4(gb, lnb + lane * 4);
    ld4(hv, h + off);
    #pragma unroll
    for (int i = 0; i < 4; i++) hv[i] += (t[i] - m) * is * gg[i] + gb[i];
    st4(h + off, hv);
    float z[4] = {0.f, 0.f, 0.f, 0.f};
    st4(acc + off, z);
}

// ---------------- final scorer (warp per edge) ----------------
__global__ void __launch_bounds__(256) final_kernel(
    const int* __restrict__ rows, const int* __restrict__ cols,
    const float* __restrict__ ha, const float* __restrict__ hb, const float* __restrict__ ec,
    const float* __restrict__ s1b, const float* __restrict__ s2w, const float* __restrict__ s2b,
    float* __restrict__ out, int E_)
{
    const int w = blockIdx.x * 8 + (threadIdx.x >> 5);
    const int lane = threadIdx.x & 31;
    if (w >= E_) return;
    const int r = rows[w], c = cols[w];
    float A[4], B[4], C[4], b4[4], wv[4];
    ld4(A, ha + (size_t)r * 128 + lane * 4);
    ld4(B, hb + (size_t)c * 128 + lane * 4);
    ld4(C, ec + (size_t)w * 128 + lane * 4);
    ld4(b4, s1b + lane * 4);
    ld4(wv, s2w + lane * 4);
    float p = 0.f;
    #pragma unroll
    for (int i = 0; i < 4; i++) {
        float u = fmaxf(A[i] + B[i] + C[i] + b4[i], 0.f);
        p = fmaf(u, wv[i], p);
    }
    #pragma unroll
    for (int o = 16; o; o >>= 1) p += __shfl_xor_sync(0xffffffffu, p, o);
    if (lane == 0) out[w] = p + s2b[0];
}

// ---------------- host ----------------
extern "C" void kernel_launch(void* const* d_in, const int* in_sizes, int n_in,
                              void* d_out, int out_size)
{
    const float* x    = (const float*)d_in[0];
    const float* ea   = (const float*)d_in[1];
    const int*   ei   = (const int*)  d_in[2];
    const float* W11w = (const float*)d_in[3];
    const float* W11b = (const float*)d_in[4];
    const float* W12w = (const float*)d_in[5];
    const float* W12b = (const float*)d_in[6];
    const float* W21w = (const float*)d_in[7];
    const float* W21b = (const float*)d_in[8];
    const float* W22w = (const float*)d_in[9];
    const float* W22b = (const float*)d_in[10];
    const float* ln1g = (const float*)d_in[11];
    const float* ln1b = (const float*)d_in[12];
    const float* ln2g = (const float*)d_in[13];
    const float* ln2b = (const float*)d_in[14];
    const float* Aw   = (const float*)d_in[15];
    const float* Ab   = (const float*)d_in[16];
    const float* Bw   = (const float*)d_in[17];
    const float* Bb   = (const float*)d_in[18];
    const float* lnhg = (const float*)d_in[19];
    const float* lnhb = (const float*)d_in[20];
    const float* lneg = (const float*)d_in[21];
    const float* lneb = (const float*)d_in[22];
    const float* s1w  = (const float*)d_in[23];
    const float* s1b  = (const float*)d_in[24];
    const float* s2w  = (const float*)d_in[25];
    const float* s2b  = (const float*)d_in[26];

    int Nn = in_sizes[0] / 64;
    int Ee = in_sizes[2] / 2;
    if (Nn > CAP_N) Nn = CAP_N;
    if (Ee > CAP_E) Ee = CAP_E;

    float *ph, *pacc, *pA1, *pA2, *pA3, *pB2, *pB3, *pe, *ptmp;
    cudaGetSymbolAddress((void**)&ph,   g_h);
    cudaGetSymbolAddress((void**)&pacc, g_acc);
    cudaGetSymbolAddress((void**)&pA1,  g_A1);
    cudaGetSymbolAddress((void**)&pA2,  g_A2);
    cudaGetSymbolAddress((void**)&pA3,  g_A3);
    cudaGetSymbolAddress((void**)&pB2,  g_B2);
    cudaGetSymbolAddress((void**)&pB3,  g_B3);
    cudaGetSymbolAddress((void**)&pe,   g_e);
    cudaGetSymbolAddress((void**)&ptmp, g_tmp);

    const int SMEM = (8192 + 128 * 132) * (int)sizeof(float);  // 100352 B
    static int smem_set = 0;
    cudaFuncSetAttribute(gemm_multi_kernel, cudaFuncAttributeMaxDynamicSharedMemorySize, SMEM);
    (void)smem_set;

    auto gemm1 = [&](const float* A, const float* W, const float* b, float* o, int M) {
        G5 g; g.nw = 1; g.W[0] = W; g.B[0] = b; g.O[0] = o;
        gemm_multi_kernel<<<(M + 127) / 128, 128, SMEM>>>(A, g, M);
    };

    // node embed: h = LN(relu(x@W11+b)) @ W12 + b     (uses acc as temp)
    embed_ln_kernel<<<(Nn + 7) / 8, 256>>>(x, W11w, W11b, ln1g, ln1b, pacc, Nn, 64);
    gemm1(pacc, W12w, W12b, ph, Nn);
    // edge embed: e = LN(relu(ea@W21+b)) @ W22 + b
    embed_ln_kernel<<<(Ee + 7) / 8, 256>>>(ea, W21w, W21b, ln2g, ln2b, ptmp, Ee, 32);
    gemm1(ptmp, W22w, W22b, pe, Ee);

    // zero the scatter accumulator
    zero_kernel<<<(Nn * 128 / 4 + 255) / 256, 256>>>(pacc, Nn * 128);

    for (int l = 0; l < 3; l++) {
        const float* Awl = Aw + (size_t)l * 3 * 128 * 128;
        const float* Abl = Ab + (size_t)l * 3 * 128;
        const float* Bwl = Bw + (size_t)l * 3 * 128 * 128;
        const float* Bbl = Bb + (size_t)l * 3 * 128;
        {
            G5 g; g.nw = 5;
            g.W[0] = Awl;          g.B[0] = Abl;        g.O[0] = pA1;
            g.W[1] = Awl + 16384;  g.B[1] = Abl + 128;  g.O[1] = pA2;
            g.W[2] = Awl + 32768;  g.B[2] = Abl + 256;  g.O[2] = pA3;
            g.W[3] = Bwl + 16384;  g.B[3] = Bbl + 128;  g.O[3] = pB2;
            g.W[4] = Bwl + 32768;  g.B[4] = Bbl + 256;  g.O[4] = pB3;
            gemm_multi_kernel<<<(Nn + 127) / 128, 128, SMEM>>>(ph, g, Nn);
        }
        gemm1(pe, Bwl, Bbl, ptmp, Ee);   // B1e
        edge_layer_kernel<<<(Ee + 7) / 8, 256>>>(ei, ei + Ee, pe, ptmp, pA2, pA3, pB2, pB3,
                                                 lneg + l * 128, lneb + l * 128, pacc, Ee);
        node_update_kernel<<<(Nn + 7) / 8, 256>>>(pA1, pacc, ph,
                                                  lnhg + l * 128, lnhb + l * 128, Nn);
    }

    // final scorer: score = relu(h[row]@Sa + h[col]@Sb + e@Sc + s1b) @ s2w + s2b
    {
        G5 g; g.nw = 2;
        g.W[0] = s1w;          g.B[0] = nullptr; g.O[0] = pA1;
        g.W[1] = s1w + 16384;  g.B[1] = nullptr; g.O[1] = pA2;
        gemm_multi_kernel<<<(Nn + 127) / 128, 128, SMEM>>>(ph, g, Nn);
    }
    gemm1(pe, s1w + 32768, nullptr, ptmp, Ee);   // ec
    final_kernel<<<(Ee + 7) / 8, 256>>>(ei, ei + Ee, pA1, pA2, ptmp,
                                        s1b, s2w, s2b, (float*)d_out, Ee);
}

// round 3
// speedup vs baseline: 1.4144x; 1.0015x over previous
#include <cuda_runtime.h>
#include <cstdint>

#define H128 128
static const int CAP_N = 50000;
static const int CAP_E = 800000;

// ---------------- scratch (device globals; no allocation allowed) ----------------
__device__ float g_h  [CAP_N * H128];
__device__ float g_acc[CAP_N * H128];
__device__ float g_A1 [CAP_N * H128];
__device__ float g_A2 [CAP_N * H128];
__device__ float g_A3 [CAP_N * H128];
__device__ float g_B2 [CAP_N * H128];
__device__ float g_B3 [CAP_N * H128];
__device__ float g_e  [CAP_E * H128];
__device__ float g_tmp[CAP_E * H128];

// ---------------- helpers ----------------
__device__ __forceinline__ unsigned long long ffma2(unsigned long long a, unsigned long long b,
                                                    unsigned long long c) {
    unsigned long long d;
    asm("fma.rn.f32x2 %0, %1, %2, %3;" : "=l"(d) : "l"(a), "l"(b), "l"(c));
    return d;
}
__device__ __forceinline__ unsigned long long pack2(float lo, float hi) {
    unsigned long long d;
    asm("mov.b64 %0, {%1, %2};" : "=l"(d) : "f"(lo), "f"(hi));
    return d;
}
__device__ __forceinline__ void red_add_v4(float* p, const float* v) {
    asm volatile("red.global.add.v4.f32 [%0], {%1, %2, %3, %4};"
                 :: "l"(p), "f"(v[0]), "f"(v[1]), "f"(v[2]), "f"(v[3]) : "memory");
}
__device__ __forceinline__ void ld4(float* d, const float* p) {
    float4 v = *reinterpret_cast<const float4*>(p);
    d[0] = v.x; d[1] = v.y; d[2] = v.z; d[3] = v.w;
}
__device__ __forceinline__ void st4(float* p, const float* d) {
    float4 v; v.x = d[0]; v.y = d[1]; v.z = d[2]; v.w = d[3];
    *reinterpret_cast<float4*>(p) = v;
}

// ---------------- zero ----------------
__global__ void zero_kernel(float* __restrict__ p, int n) {
    int i = (blockIdx.x * blockDim.x + threadIdx.x) * 4;
    if (i < n) *reinterpret_cast<float4*>(p + i) = make_float4(0.f, 0.f, 0.f, 0.f);
}

// ---------------- multi-weight GEMM ----------------
// out_w[M,128] = A[M,128] @ W_w[128,128] (+ bias_w)  for w < nw (<=5)
// 128 threads, block tile 128x128, thread tile 8 rows x 16 cols.
// rows = rt*4 + {0..3} and +64 ; cols = ct*4 + 32*m, m=0..3  (conflict-free LDS)
struct G5 {
    const float* W[5];
    const float* B[5];
    float*       O[5];
    int nw;
};

__global__ void __launch_bounds__(128) gemm_multi_kernel(
    const float* __restrict__ A, G5 g, int M)
{
    extern __shared__ float sm[];
    float* ws = sm;             // [64][128] W chunk (32768 B)
    float* as = sm + 8192;      // [128][132] A tile row-major (67584 B)
    float4* as4 = reinterpret_cast<float4*>(as);
    const int t = threadIdx.x;
    const int rt = t >> 3;          // 0..15
    const int ct = t & 7;           // 0..7
    const int brow = blockIdx.x * 128;

    // load A tile (row-major, stride 132 floats = 33 float4)
    {
        const float4* A4 = reinterpret_cast<const float4*>(A);
        #pragma unroll
        for (int j = 0; j < 32; j++) {
            int flat = j * 128 + t;
            int row = flat >> 5, k4 = flat & 31;
            float4 v = make_float4(0.f, 0.f, 0.f, 0.f);
            int gr = brow + row;
            if (gr < M) v = A4[(size_t)gr * 32 + k4];
            as4[row * 33 + k4] = v;
        }
    }

    int rowg[8];
    #pragma unroll
    for (int r8 = 0; r8 < 8; r8++) rowg[r8] = rt * 4 + (r8 & 3) + ((r8 >> 2) << 6);

    for (int w = 0; w < g.nw; w++) {
        const float* W = g.W[w];
        const float* bias = g.B[w];
        unsigned long long acc[8][8];
        {
            unsigned long long b[8];
            #pragma unroll
            for (int m = 0; m < 4; m++) {
                if (bias) {
                    ulonglong2 u = *reinterpret_cast<const ulonglong2*>(bias + ct * 4 + 32 * m);
                    b[2 * m] = u.x; b[2 * m + 1] = u.y;
                } else { b[2 * m] = 0ull; b[2 * m + 1] = 0ull; }
            }
            #pragma unroll
            for (int r8 = 0; r8 < 8; r8++)
                #pragma unroll
                for (int c = 0; c < 8; c++) acc[r8][c] = b[c];
        }

        #pragma unroll 1
        for (int ch = 0; ch < 2; ch++) {
            const int kc = ch * 64;
            __syncthreads();
            // load W chunk [64][128]
            {
                const float4* W4 = reinterpret_cast<const float4*>(W);
                float4* ws4 = reinterpret_cast<float4*>(ws);
                #pragma unroll
                for (int j = 0; j < 16; j++) {
                    int flat = j * 128 + t;
                    int wk = flat >> 5, c4 = flat & 31;
                    ws4[wk * 32 + c4] = W4[(size_t)(kc + wk) * 32 + c4];
                }
            }
            __syncthreads();

            #pragma unroll 2
            for (int k4 = 0; k4 < 16; k4++) {
                float4 a[8];
                const int kq = (kc >> 2) + k4;
                #pragma unroll
                for (int r8 = 0; r8 < 8; r8++) a[r8] = as4[rowg[r8] * 33 + kq];
                #pragma unroll
                for (int kk = 0; kk < 4; kk++) {
                    unsigned long long av[8];
                    #pragma unroll
                    for (int r8 = 0; r8 < 8; r8++) {
                        float s = (kk == 0) ? a[r8].x : (kk == 1) ? a[r8].y :
                                  (kk == 2) ? a[r8].z : a[r8].w;
                        av[r8] = pack2(s, s);
                    }
                    const float* wr = ws + (k4 * 4 + kk) * 128 + ct * 4;
                    #pragma unroll
                    for (int m = 0; m < 4; m++) {
                        ulonglong2 u = *reinterpret_cast<const ulonglong2*>(wr + 32 * m);
                        #pragma unroll
                        for (int r8 = 0; r8 < 8; r8++) {
                            acc[r8][2 * m]     = ffma2(av[r8], u.x, acc[r8][2 * m]);
                            acc[r8][2 * m + 1] = ffma2(av[r8], u.y, acc[r8][2 * m + 1]);
                        }
                    }
                }
            }
        }

        // store
        float* out = g.O[w];
        #pragma unroll
        for (int r8 = 0; r8 < 8; r8++) {
            int gr = brow + rowg[r8];
            if (gr < M) {
                float* po = out + (size_t)gr * 128 + ct * 4;
                #pragma unroll
                for (int m = 0; m < 4; m++) {
                    ulonglong2 u; u.x = acc[r8][2 * m]; u.y = acc[r8][2 * m + 1];
                    *reinterpret_cast<ulonglong2*>(po + 32 * m) = u;
                }
            }
        }
    }
}

// ---------------- embed stage1: out = LN(relu(in @ W + b)) ----------------
__global__ void __launch_bounds__(256) embed_ln_kernel(
    const float* __restrict__ in, const float* __restrict__ W, const float* __restrict__ bias,
    const float* __restrict__ lng, const float* __restrict__ lnb,
    float* __restrict__ out, int M, int Kin)
{
    const int w = blockIdx.x * 8 + (threadIdx.x >> 5);
    const int lane = threadIdx.x & 31;
    if (w >= M) return;
    const float* xr = in + (size_t)w * Kin;
    float x0 = (lane < Kin) ? xr[lane] : 0.f;
    float x1 = (lane + 32 < Kin) ? xr[lane + 32] : 0.f;

    float a[4];
    ld4(a, bias + lane * 4);
    for (int k = 0; k < Kin; k++) {
        float xk = __shfl_sync(0xffffffffu, (k < 32) ? x0 : x1, k & 31);
        float4 wv = *reinterpret_cast<const float4*>(W + k * 128 + lane * 4);
        a[0] = fmaf(xk, wv.x, a[0]);
        a[1] = fmaf(xk, wv.y, a[1]);
        a[2] = fmaf(xk, wv.z, a[2]);
        a[3] = fmaf(xk, wv.w, a[3]);
    }
    float s = 0.f, q = 0.f;
    #pragma unroll
    for (int i = 0; i < 4; i++) {
        a[i] = fmaxf(a[i], 0.f);
        s += a[i]; q = fmaf(a[i], a[i], q);
    }
    #pragma unroll
    for (int o = 16; o; o >>= 1) {
        s += __shfl_xor_sync(0xffffffffu, s, o);
        q += __shfl_xor_sync(0xffffffffu, q, o);
    }
    const float inv = 1.f / 128.f;
    float m = s * inv;
    float is = rsqrtf(fmaxf(q * inv - m * m, 0.f) + 1e-5f);
    float gg[4], gb[4], o4[4];
    ld4(gg, lng + lane * 4); ld4(gb, lnb + lane * 4);
    #pragma unroll
    for (int i = 0; i < 4; i++) o4[i] = (a[i] - m) * is * gg[i] + gb[i];
    st4(out + (size_t)w * 128 + lane * 4, o4);
}

// ---------------- edge layer (warp per edge) ----------------
__global__ void __launch_bounds__(256) edge_layer_kernel(
    const int* __restrict__ rows, const int* __restrict__ cols,
    float* __restrict__ e, const float* __restrict__ b1e,
    const float* __restrict__ A2, const float* __restrict__ A3,
    const float* __restrict__ B2, const float* __restrict__ B3,
    const float* __restrict__ lng, const float* __restrict__ lnb,
    float* __restrict__ acc, int E_)
{
    const int w = blockIdx.x * 8 + (threadIdx.x >> 5);
    const int lane = threadIdx.x & 31;
    if (w >= E_) return;
    const int r = rows[w], c = cols[w];
    const size_t eo = (size_t)w * 128 + lane * 4;
    const size_t ro = (size_t)r * 128 + lane * 4;
    const size_t co = (size_t)c * 128 + lane * 4;

    float ev[4], b1[4], b2r[4], b3r[4], a2r[4], b2c[4], b3c[4], a3c[4];
    ld4(ev, e + eo);  ld4(b1, b1e + eo);
    ld4(b2r, B2 + ro); ld4(b3r, B3 + ro); ld4(a2r, A2 + ro);
    ld4(b2c, B2 + co); ld4(b3c, B3 + co); ld4(a3c, A3 + co);

    float gji[4], gik[4];
    float s1 = 0.f, q1 = 0.f, s2 = 0.f, q2 = 0.f;
    #pragma unroll
    for (int i = 0; i < 4; i++) {
        float u = fmaxf(b1[i] + b2r[i] + b3c[i], 0.f);
        float v = fmaxf(b1[i] + b2c[i] + b3r[i], 0.f);
        gji[i] = u; gik[i] = v;
        s1 += u; q1 = fmaf(u, u, q1);
        s2 += v; q2 = fmaf(v, v, q2);
    }
    #pragma unroll
    for (int o = 16; o; o >>= 1) {
        s1 += __shfl_xor_sync(0xffffffffu, s1, o);
        q1 += __shfl_xor_sync(0xffffffffu, q1, o);
        s2 += __shfl_xor_sync(0xffffffffu, s2, o);
        q2 += __shfl_xor_sync(0xffffffffu, q2, o);
    }
    const float inv = 1.f / 128.f;
    float m1 = s1 * inv, m2 = s2 * inv;
    float is1 = rsqrtf(fmaxf(q1 * inv - m1 * m1, 0.f) + 1e-5f);
    float is2 = rsqrtf(fmaxf(q2 * inv - m2 * m2, 0.f) + 1e-5f);

    float gg[4], gb[4];
    ld4(gg, lng + lane * 4); ld4(gb, lnb + lane * 4);

    float eji[4], sg1[4], sg2[4];
    float t1 = 0.f, t2 = 0.f;
    #pragma unroll
    for (int i = 0; i < 4; i++) {
        eji[i]    = ev[i] + (gji[i] - m1) * is1 * gg[i] + gb[i];
        float eik = ev[i] + (gik[i] - m2) * is2 * gg[i] + gb[i];
        sg1[i] = __fdividef(1.f, 1.f + __expf(-eji[i])); t1 += sg1[i];
        sg2[i] = __fdividef(1.f, 1.f + __expf(-eik));    t2 += sg2[i];
    }
    #pragma unroll
    for (int o = 16; o; o >>= 1) {
        t1 += __shfl_xor_sync(0xffffffffu, t1, o);
        t2 += __shfl_xor_sync(0xffffffffu, t2, o);
    }
    float w1 = __fdividef(1.f, t1 + 1e-6f);
    float w2 = __fdividef(1.f, t2 + 1e-6f);

    float mji[4], mik[4];
    #pragma unroll
    for (int i = 0; i < 4; i++) {
        mji[i] = a2r[i] * sg1[i] * w1;
        mik[i] = a3c[i] * sg2[i] * w2;
    }
    red_add_v4(acc + co, mji);
    red_add_v4(acc + ro, mik);
    st4(e + eo, eji);
}

// ---------------- node update: h += LN(relu(A1h + acc)); acc = 0 ----------------
__global__ void __launch_bounds__(256) node_update_kernel(
    const float* __restrict__ A1, float* __restrict__ acc, float* __restrict__ h,
    const float* __restrict__ lng, const float* __restrict__ lnb, int M)
{
    const int w = blockIdx.x * 8 + (threadIdx.x >> 5);
    const int lane = threadIdx.x & 31;
    if (w >= M) return;
    const size_t off = (size_t)w * 128 + lane * 4;
    float a[4], cc[4], t[4];
    ld4(a, A1 + off); ld4(cc, acc + off);
    float s = 0.f, q = 0.f;
    #pragma unroll
    for (int i = 0; i < 4; i++) {
        t[i] = fmaxf(a[i] + cc[i], 0.f);
        s += t[i]; q = fmaf(t[i], t[i], q);
    }
    #pragma unroll
    for (int o = 16; o; o >>= 1) {
        s += __shfl_xor_sync(0xffffffffu, s, o);
        q += __shfl_xor_sync(0xffffffffu, q, o);
    }
    const float inv = 1.f / 128.f;
    float m = s * inv;
    float is = rsqrtf(fmaxf(q * inv - m * m, 0.f) + 1e-5f);
    float gg[4], gb[4], hv[4];
    ld4(gg, lng + lane * 4); ld4(gb, lnb + lane * 4);
    ld4(hv, h + off);
    #pragma unroll
    for (int i = 0; i < 4; i++) hv[i] += (t[i] - m) * is * gg[i] + gb[i];
    st4(h + off, hv);
    float z[4] = {0.f, 0.f, 0.f, 0.f};
    st4(acc + off, z);
}

// ---------------- final scorer (warp per edge) ----------------
__global__ void __launch_bounds__(256) final_kernel(
    const int* __restrict__ rows, const int* __restrict__ cols,
    const float* __restrict__ ha, const float* __restrict__ hb, const float* __restrict__ ec,
    const float* __restrict__ s1b, const float* __restrict__ s2w, const float* __restrict__ s2b,
    float* __restrict__ out, int E_)
{
    const int w = blockIdx.x * 8 + (threadIdx.x >> 5);
    const int lane = threadIdx.x & 31;
    if (w >= E_) return;
    const int r = rows[w], c = cols[w];
    float A[4], B[4], C[4], b4[4], wv[4];
    ld4(A, ha + (size_t)r * 128 + lane * 4);
    ld4(B, hb + (size_t)c * 128 + lane * 4);
    ld4(C, ec + (size_t)w * 128 + lane * 4);
    ld4(b4, s1b + lane * 4);
    ld4(wv, s2w + lane * 4);
    float p = 0.f;
    #pragma unroll
    for (int i = 0; i < 4; i++) {
        float u = fmaxf(A[i] + B[i] + C[i] + b4[i], 0.f);
        p = fmaf(u, wv[i], p);
    }
    #pragma unroll
    for (int o = 16; o; o >>= 1) p += __shfl_xor_sync(0xffffffffu, p, o);
    if (lane == 0) out[w] = p + s2b[0];
}

// ---------------- host ----------------
extern "C" void kernel_launch(void* const* d_in, const int* in_sizes, int n_in,
                              void* d_out, int out_size)
{
    const float* x    = (const float*)d_in[0];
    const float* ea   = (const float*)d_in[1];
    const int*   ei   = (const int*)  d_in[2];
    const float* W11w = (const float*)d_in[3];
    const float* W11b = (const float*)d_in[4];
    const float* W12w = (const float*)d_in[5];
    const float* W12b = (const float*)d_in[6];
    const float* W21w = (const float*)d_in[7];
    const float* W21b = (const float*)d_in[8];
    const float* W22w = (const float*)d_in[9];
    const float* W22b = (const float*)d_in[10];
    const float* ln1g = (const float*)d_in[11];
    const float* ln1b = (const float*)d_in[12];
    const float* ln2g = (const float*)d_in[13];
    const float* ln2b = (const float*)d_in[14];
    const float* Aw   = (const float*)d_in[15];
    const float* Ab   = (const float*)d_in[16];
    const float* Bw   = (const float*)d_in[17];
    const float* Bb   = (const float*)d_in[18];
    const float* lnhg = (const float*)d_in[19];
    const float* lnhb = (const float*)d_in[20];
    const float* lneg = (const float*)d_in[21];
    const float* lneb = (const float*)d_in[22];
    const float* s1w  = (const float*)d_in[23];
    const float* s1b  = (const float*)d_in[24];
    const float* s2w  = (const float*)d_in[25];
    const float* s2b  = (const float*)d_in[26];

    int Nn = in_sizes[0] / 64;
    int Ee = in_sizes[2] / 2;
    if (Nn > CAP_N) Nn = CAP_N;
    if (Ee > CAP_E) Ee = CAP_E;

    float *ph, *pacc, *pA1, *pA2, *pA3, *pB2, *pB3, *pe, *ptmp;
    cudaGetSymbolAddress((void**)&ph,   g_h);
    cudaGetSymbolAddress((void**)&pacc, g_acc);
    cudaGetSymbolAddress((void**)&pA1,  g_A1);
    cudaGetSymbolAddress((void**)&pA2,  g_A2);
    cudaGetSymbolAddress((void**)&pA3,  g_A3);
    cudaGetSymbolAddress((void**)&pB2,  g_B2);
    cudaGetSymbolAddress((void**)&pB3,  g_B3);
    cudaGetSymbolAddress((void**)&pe,   g_e);
    cudaGetSymbolAddress((void**)&ptmp, g_tmp);

    const int SMEM = (8192 + 128 * 132) * (int)sizeof(float);  // 100352 B
    static int smem_set = 0;
    cudaFuncSetAttribute(gemm_multi_kernel, cudaFuncAttributeMaxDynamicSharedMemorySize, SMEM);
    (void)smem_set;

    auto gemm1 = [&](const float* A, const float* W, const float* b, float* o, int M) {
        G5 g; g.nw = 1; g.W[0] = W; g.B[0] = b; g.O[0] = o;
        gemm_multi_kernel<<<(M + 127) / 128, 128, SMEM>>>(A, g, M);
    };

    // node embed: h = LN(relu(x@W11+b)) @ W12 + b     (uses acc as temp)
    embed_ln_kernel<<<(Nn + 7) / 8, 256>>>(x, W11w, W11b, ln1g, ln1b, pacc, Nn, 64);
    gemm1(pacc, W12w, W12b, ph, Nn);
    // edge embed: e = LN(relu(ea@W21+b)) @ W22 + b
    embed_ln_kernel<<<(Ee + 7) / 8, 256>>>(ea, W21w, W21b, ln2g, ln2b, ptmp, Ee, 32);
    gemm1(ptmp, W22w, W22b, pe, Ee);

    // zero the scatter accumulator
    zero_kernel<<<(Nn * 128 / 4 + 255) / 256, 256>>>(pacc, Nn * 128);

    for (int l = 0; l < 3; l++) {
        const float* Awl = Aw + (size_t)l * 3 * 128 * 128;
        const float* Abl = Ab + (size_t)l * 3 * 128;
        const float* Bwl = Bw + (size_t)l * 3 * 128 * 128;
        const float* Bbl = Bb + (size_t)l * 3 * 128;
        {
            G5 g; g.nw = 5;
            g.W[0] = Awl;          g.B[0] = Abl;        g.O[0] = pA1;
            g.W[1] = Awl + 16384;  g.B[1] = Abl + 128;  g.O[1] = pA2;
            g.W[2] = Awl + 32768;  g.B[2] = Abl + 256;  g.O[2] = pA3;
            g.W[3] = Bwl + 16384;  g.B[3] = Bbl + 128;  g.O[3] = pB2;
            g.W[4] = Bwl + 32768;  g.B[4] = Bbl + 256;  g.O[4] = pB3;
            gemm_multi_kernel<<<(Nn + 127) / 128, 128, SMEM>>>(ph, g, Nn);
        }
        gemm1(pe, Bwl, Bbl, ptmp, Ee);   // B1e
        edge_layer_kernel<<<(Ee + 7) / 8, 256>>>(ei, ei + Ee, pe, ptmp, pA2, pA3, pB2, pB3,
                                                 lneg + l * 128, lneb + l * 128, pacc, Ee);
        node_update_kernel<<<(Nn + 7) / 8, 256>>>(pA1, pacc, ph,
                                                  lnhg + l * 128, lnhb + l * 128, Nn);
    }

    // final scorer: score = relu(h[row]@Sa + h[col]@Sb + e@Sc + s1b) @ s2w + s2b
    {
        G5 g; g.nw = 2;
        g.W[0] = s1w;          g.B[0] = nullptr; g.O[0] = pA1;
        g.W[1] = s1w + 16384;  g.B[1] = nullptr; g.O[1] = pA2;
        gemm_multi_kernel<<<(Nn + 127) / 128, 128, SMEM>>>(ph, g, Nn);
    }
    gemm1(pe, s1w + 32768, nullptr, ptmp, Ee);   // ec
    final_kernel<<<(Ee + 7) / 8, 256>>>(ei, ei + Ee, pA1, pA2, ptmp,
                                        s1b, s2w, s2b, (float*)d_out, Ee);
}

// round 4
// speedup vs baseline: 1.4182x; 1.0027x over previous
#include <cuda_runtime.h>
#include <cstdint>

#define H128 128
static const int CAP_N = 50000;
static const int CAP_E = 800000;

// ---------------- scratch (device globals; no allocation allowed) ----------------
__device__ float g_h  [CAP_N * H128];
__device__ float g_acc[CAP_N * H128];
__device__ float g_A1 [CAP_N * H128];
__device__ float g_A2 [CAP_N * H128];
__device__ float g_A3 [CAP_N * H128];
__device__ float g_B2 [CAP_N * H128];
__device__ float g_B3 [CAP_N * H128];
__device__ float g_e  [CAP_E * H128];
__device__ float g_tmp[CAP_E * H128];

// ---------------- helpers ----------------
__device__ __forceinline__ unsigned long long ffma2(unsigned long long a, unsigned long long b,
                                                    unsigned long long c) {
    unsigned long long d;
    asm("fma.rn.f32x2 %0, %1, %2, %3;" : "=l"(d) : "l"(a), "l"(b), "l"(c));
    return d;
}
__device__ __forceinline__ unsigned long long pack2(float lo, float hi) {
    unsigned long long d;
    asm("mov.b64 %0, {%1, %2};" : "=l"(d) : "f"(lo), "f"(hi));
    return d;
}
__device__ __forceinline__ void red_add_v4(float* p, const float* v) {
    asm volatile("red.global.add.v4.f32 [%0], {%1, %2, %3, %4};"
                 :: "l"(p), "f"(v[0]), "f"(v[1]), "f"(v[2]), "f"(v[3]) : "memory");
}
__device__ __forceinline__ void ld4(float* d, const float* p) {
    float4 v = *reinterpret_cast<const float4*>(p);
    d[0] = v.x; d[1] = v.y; d[2] = v.z; d[3] = v.w;
}
__device__ __forceinline__ void st4(float* p, const float* d) {
    float4 v; v.x = d[0]; v.y = d[1]; v.z = d[2]; v.w = d[3];
    *reinterpret_cast<float4*>(p) = v;
}

// ---------------- zero ----------------
__global__ void zero_kernel(float* __restrict__ p, int n) {
    int i = (blockIdx.x * blockDim.x + threadIdx.x) * 4;
    if (i < n) *reinterpret_cast<float4*>(p + i) = make_float4(0.f, 0.f, 0.f, 0.f);
}

// ---------------- multi-weight GEMM ----------------
// out_w[M,128] = A[M,128] @ W_w[128,128] (+ bias_w)  for w < nw (<=5)
// 128 threads, block tile 128x128, thread tile 8 rows x 16 cols.
// rows = rt*4 + {0..3} and +64 ; cols = ct*4 + 32*m, m=0..3  (conflict-free LDS)
struct G5 {
    const float* W[5];
    const float* B[5];
    float*       O[5];
    int nw;
};

__global__ void __launch_bounds__(128) gemm_multi_kernel(
    const float* __restrict__ A, G5 g, int M)
{
    extern __shared__ float sm[];
    float* ws = sm;             // [64][128] W chunk (32768 B)
    float* as = sm + 8192;      // [128][132] A tile row-major (67584 B)
    float4* as4 = reinterpret_cast<float4*>(as);
    const int t = threadIdx.x;
    const int rt = t >> 3;          // 0..15
    const int ct = t & 7;           // 0..7
    const int brow = blockIdx.x * 128;

    // load A tile (row-major, stride 132 floats = 33 float4)
    {
        const float4* A4 = reinterpret_cast<const float4*>(A);
        #pragma unroll
        for (int j = 0; j < 32; j++) {
            int flat = j * 128 + t;
            int row = flat >> 5, k4 = flat & 31;
            float4 v = make_float4(0.f, 0.f, 0.f, 0.f);
            int gr = brow + row;
            if (gr < M) v = A4[(size_t)gr * 32 + k4];
            as4[row * 33 + k4] = v;
        }
    }

    int rowg[8];
    #pragma unroll
    for (int r8 = 0; r8 < 8; r8++) rowg[r8] = rt * 4 + (r8 & 3) + ((r8 >> 2) << 6);

    for (int w = 0; w < g.nw; w++) {
        const float* W = g.W[w];
        const float* bias = g.B[w];
        unsigned long long acc[8][8];
        {
            unsigned long long b[8];
            #pragma unroll
            for (int m = 0; m < 4; m++) {
                if (bias) {
                    ulonglong2 u = *reinterpret_cast<const ulonglong2*>(bias + ct * 4 + 32 * m);
                    b[2 * m] = u.x; b[2 * m + 1] = u.y;
                } else { b[2 * m] = 0ull; b[2 * m + 1] = 0ull; }
            }
            #pragma unroll
            for (int r8 = 0; r8 < 8; r8++)
                #pragma unroll
                for (int c = 0; c < 8; c++) acc[r8][c] = b[c];
        }

        #pragma unroll 1
        for (int ch = 0; ch < 2; ch++) {
            const int kc = ch * 64;
            __syncthreads();
            // load W chunk [64][128]
            {
                const float4* W4 = reinterpret_cast<const float4*>(W);
                float4* ws4 = reinterpret_cast<float4*>(ws);
                #pragma unroll
                for (int j = 0; j < 16; j++) {
                    int flat = j * 128 + t;
                    int wk = flat >> 5, c4 = flat & 31;
                    ws4[wk * 32 + c4] = W4[(size_t)(kc + wk) * 32 + c4];
                }
            }
            __syncthreads();

            #pragma unroll 2
            for (int k4 = 0; k4 < 16; k4++) {
                float4 a[8];
                const int kq = (kc >> 2) + k4;
                #pragma unroll
                for (int r8 = 0; r8 < 8; r8++) a[r8] = as4[rowg[r8] * 33 + kq];
                #pragma unroll
                for (int kk = 0; kk < 4; kk++) {
                    unsigned long long av[8];
                    #pragma unroll
                    for (int r8 = 0; r8 < 8; r8++) {
                        float s = (kk == 0) ? a[r8].x : (kk == 1) ? a[r8].y :
                                  (kk == 2) ? a[r8].z : a[r8].w;
                        av[r8] = pack2(s, s);
                    }
                    const float* wr = ws + (k4 * 4 + kk) * 128 + ct * 4;
                    #pragma unroll
                    for (int m = 0; m < 4; m++) {
                        ulonglong2 u = *reinterpret_cast<const ulonglong2*>(wr + 32 * m);
                        #pragma unroll
                        for (int r8 = 0; r8 < 8; r8++) {
                            acc[r8][2 * m]     = ffma2(av[r8], u.x, acc[r8][2 * m]);
                            acc[r8][2 * m + 1] = ffma2(av[r8], u.y, acc[r8][2 * m + 1]);
                        }
                    }
                }
            }
        }

        // store
        float* out = g.O[w];
        #pragma unroll
        for (int r8 = 0; r8 < 8; r8++) {
            int gr = brow + rowg[r8];
            if (gr < M) {
                float* po = out + (size_t)gr * 128 + ct * 4;
                #pragma unroll
                for (int m = 0; m < 4; m++) {
                    ulonglong2 u; u.x = acc[r8][2 * m]; u.y = acc[r8][2 * m + 1];
                    *reinterpret_cast<ulonglong2*>(po + 32 * m) = u;
                }
            }
        }
    }
}

// ---------------- embed stage1: out = LN(relu(in @ W + b)) ----------------
__global__ void __launch_bounds__(256) embed_ln_kernel(
    const float* __restrict__ in, const float* __restrict__ W, const float* __restrict__ bias,
    const float* __restrict__ lng, const float* __restrict__ lnb,
    float* __restrict__ out, int M, int Kin)
{
    const int w = blockIdx.x * 8 + (threadIdx.x >> 5);
    const int lane = threadIdx.x & 31;
    if (w >= M) return;
    const float* xr = in + (size_t)w * Kin;
    float x0 = (lane < Kin) ? xr[lane] : 0.f;
    float x1 = (lane + 32 < Kin) ? xr[lane + 32] : 0.f;

    float a[4];
    ld4(a, bias + lane * 4);
    for (int k = 0; k < Kin; k++) {
        float xk = __shfl_sync(0xffffffffu, (k < 32) ? x0 : x1, k & 31);
        float4 wv = *reinterpret_cast<const float4*>(W + k * 128 + lane * 4);
        a[0] = fmaf(xk, wv.x, a[0]);
        a[1] = fmaf(xk, wv.y, a[1]);
        a[2] = fmaf(xk, wv.z, a[2]);
        a[3] = fmaf(xk, wv.w, a[3]);
    }
    float s = 0.f, q = 0.f;
    #pragma unroll
    for (int i = 0; i < 4; i++) {
        a[i] = fmaxf(a[i], 0.f);
        s += a[i]; q = fmaf(a[i], a[i], q);
    }
    #pragma unroll
    for (int o = 16; o; o >>= 1) {
        s += __shfl_xor_sync(0xffffffffu, s, o);
        q += __shfl_xor_sync(0xffffffffu, q, o);
    }
    const float inv = 1.f / 128.f;
    float m = s * inv;
    float is = rsqrtf(fmaxf(q * inv - m * m, 0.f) + 1e-5f);
    float gg[4], gb[4], o4[4];
    ld4(gg, lng + lane * 4); ld4(gb, lnb + lane * 4);
    #pragma unroll
    for (int i = 0; i < 4; i++) o4[i] = (a[i] - m) * is * gg[i] + gb[i];
    st4(out + (size_t)w * 128 + lane * 4, o4);
}

// ---------------- edge layer (warp per edge) ----------------
__global__ void __launch_bounds__(256) edge_layer_kernel(
    const int* __restrict__ rows, const int* __restrict__ cols,
    float* __restrict__ e, const float* __restrict__ b1e,
    const float* __restrict__ A2, const float* __restrict__ A3,
    const float* __restrict__ B2, const float* __restrict__ B3,
    const float* __restrict__ lng, const float* __restrict__ lnb,
    float* __restrict__ acc, int E_)
{
    const int w = blockIdx.x * 8 + (threadIdx.x >> 5);
    const int lane = threadIdx.x & 31;
    if (w >= E_) return;
    const int r = rows[w], c = cols[w];
    const size_t eo = (size_t)w * 128 + lane * 4;
    const size_t ro = (size_t)r * 128 + lane * 4;
    const size_t co = (size_t)c * 128 + lane * 4;

    float ev[4], b1[4], b2r[4], b3r[4], a2r[4], b2c[4], b3c[4], a3c[4];
    ld4(ev, e + eo);  ld4(b1, b1e + eo);
    ld4(b2r, B2 + ro); ld4(b3r, B3 + ro); ld4(a2r, A2 + ro);
    ld4(b2c, B2 + co); ld4(b3c, B3 + co); ld4(a3c, A3 + co);

    float gji[4], gik[4];
    float s1 = 0.f, q1 = 0.f, s2 = 0.f, q2 = 0.f;
    #pragma unroll
    for (int i = 0; i < 4; i++) {
        float u = fmaxf(b1[i] + b2r[i] + b3c[i], 0.f);
        float v = fmaxf(b1[i] + b2c[i] + b3r[i], 0.f);
        gji[i] = u; gik[i] = v;
        s1 += u; q1 = fmaf(u, u, q1);
        s2 += v; q2 = fmaf(v, v, q2);
    }
    #pragma unroll
    for (int o = 16; o; o >>= 1) {
        s1 += __shfl_xor_sync(0xffffffffu, s1, o);
        q1 += __shfl_xor_sync(0xffffffffu, q1, o);
        s2 += __shfl_xor_sync(0xffffffffu, s2, o);
        q2 += __shfl_xor_sync(0xffffffffu, q2, o);
    }
    const float inv = 1.f / 128.f;
    float m1 = s1 * inv, m2 = s2 * inv;
    float is1 = rsqrtf(fmaxf(q1 * inv - m1 * m1, 0.f) + 1e-5f);
    float is2 = rsqrtf(fmaxf(q2 * inv - m2 * m2, 0.f) + 1e-5f);

    float gg[4], gb[4];
    ld4(gg, lng + lane * 4); ld4(gb, lnb + lane * 4);

    float eji[4], sg1[4], sg2[4];
    float t1 = 0.f, t2 = 0.f;
    #pragma unroll
    for (int i = 0; i < 4; i++) {
        eji[i]    = ev[i] + (gji[i] - m1) * is1 * gg[i] + gb[i];
        float eik = ev[i] + (gik[i] - m2) * is2 * gg[i] + gb[i];
        sg1[i] = __fdividef(1.f, 1.f + __expf(-eji[i])); t1 += sg1[i];
        sg2[i] = __fdividef(1.f, 1.f + __expf(-eik));    t2 += sg2[i];
    }
    #pragma unroll
    for (int o = 16; o; o >>= 1) {
        t1 += __shfl_xor_sync(0xffffffffu, t1, o);
        t2 += __shfl_xor_sync(0xffffffffu, t2, o);
    }
    float w1 = __fdividef(1.f, t1 + 1e-6f);
    float w2 = __fdividef(1.f, t2 + 1e-6f);

    float mji[4], mik[4];
    #pragma unroll
    for (int i = 0; i < 4; i++) {
        mji[i] = a2r[i] * sg1[i] * w1;
        mik[i] = a3c[i] * sg2[i] * w2;
    }
    red_add_v4(acc + co, mji);
    red_add_v4(acc + ro, mik);
    st4(e + eo, eji);
}

// ---------------- node update: h += LN(relu(A1h + acc)); acc = 0 ----------------
__global__ void __launch_bounds__(256) node_update_kernel(
    const float* __restrict__ A1, float* __restrict__ acc, float* __restrict__ h,
    const float* __restrict__ lng, const float* __restrict__ lnb, int M)
{
    const int w = blockIdx.x * 8 + (threadIdx.x >> 5);
    const int lane = threadIdx.x & 31;
    if (w >= M) return;
    const size_t off = (size_t)w * 128 + lane * 4;
    float a[4], cc[4], t[4];
    ld4(a, A1 + off); ld4(cc, acc + off);
    float s = 0.f, q = 0.f;
    #pragma unroll
    for (int i = 0; i < 4; i++) {
        t[i] = fmaxf(a[i] + cc[i], 0.f);
        s += t[i]; q = fmaf(t[i], t[i], q);
    }
    #pragma unroll
    for (int o = 16; o; o >>= 1) {
        s += __shfl_xor_sync(0xffffffffu, s, o);
        q += __shfl_xor_sync(0xffffffffu, q, o);
    }
    const float inv = 1.f / 128.f;
    float m = s * inv;
    float is = rsqrtf(fmaxf(q * inv - m * m, 0.f) + 1e-5f);
    float gg[4], gb[4], hv[4];
    ld4(gg, lng + lane * 4); ld4(gb, lnb + lane * 4);
    ld4(hv, h + off);
    #pragma unroll
    for (int i = 0; i < 4; i++) hv[i] += (t[i] - m) * is * gg[i] + gb[i];
    st4(h + off, hv);
    float z[4] = {0.f, 0.f, 0.f, 0.f};
    st4(acc + off, z);
}

// ---------------- final scorer (warp per edge) ----------------
__global__ void __launch_bounds__(256) final_kernel(
    const int* __restrict__ rows, const int* __restrict__ cols,
    const float* __restrict__ ha, const float* __restrict__ hb, const float* __restrict__ ec,
    const float* __restrict__ s1b, const float* __restrict__ s2w, const float* __restrict__ s2b,
    float* __restrict__ out, int E_)
{
    const int w = blockIdx.x * 8 + (threadIdx.x >> 5);
    const int lane = threadIdx.x & 31;
    if (w >= E_) return;
    const int r = rows[w], c = cols[w];
    float A[4], B[4], C[4], b4[4], wv[4];
    ld4(A, ha + (size_t)r * 128 + lane * 4);
    ld4(B, hb + (size_t)c * 128 + lane * 4);
    ld4(C, ec + (size_t)w * 128 + lane * 4);
    ld4(b4, s1b + lane * 4);
    ld4(wv, s2w + lane * 4);
    float p = 0.f;
    #pragma unroll
    for (int i = 0; i < 4; i++) {
        float u = fmaxf(A[i] + B[i] + C[i] + b4[i], 0.f);
        p = fmaf(u, wv[i], p);
    }
    #pragma unroll
    for (int o = 16; o; o >>= 1) p += __shfl_xor_sync(0xffffffffu, p, o);
    if (lane == 0) out[w] = p + s2b[0];
}

// ---------------- host ----------------
extern "C" void kernel_launch(void* const* d_in, const int* in_sizes, int n_in,
                              void* d_out, int out_size)
{
    const float* x    = (const float*)d_in[0];
    const float* ea   = (const float*)d_in[1];
    const int*   ei   = (const int*)  d_in[2];
    const float* W11w = (const float*)d_in[3];
    const float* W11b = (const float*)d_in[4];
    const float* W12w = (const float*)d_in[5];
    const float* W12b = (const float*)d_in[6];
    const float* W21w = (const float*)d_in[7];
    const float* W21b = (const float*)d_in[8];
    const float* W22w = (const float*)d_in[9];
    const float* W22b = (const float*)d_in[10];
    const float* ln1g = (const float*)d_in[11];
    const float* ln1b = (const float*)d_in[12];
    const float* ln2g = (const float*)d_in[13];
    const float* ln2b = (const float*)d_in[14];
    const float* Aw   = (const float*)d_in[15];
    const float* Ab   = (const float*)d_in[16];
    const float* Bw   = (const float*)d_in[17];
    const float* Bb   = (const float*)d_in[18];
    const float* lnhg = (const float*)d_in[19];
    const float* lnhb = (const float*)d_in[20];
    const float* lneg = (const float*)d_in[21];
    const float* lneb = (const float*)d_in[22];
    const float* s1w  = (const float*)d_in[23];
    const float* s1b  = (const float*)d_in[24];
    const float* s2w  = (const float*)d_in[25];
    const float* s2b  = (const float*)d_in[26];

    int Nn = in_sizes[0] / 64;
    int Ee = in_sizes[2] / 2;
    if (Nn > CAP_N) Nn = CAP_N;
    if (Ee > CAP_E) Ee = CAP_E;

    float *ph, *pacc, *pA1, *pA2, *pA3, *pB2, *pB3, *pe, *ptmp;
    cudaGetSymbolAddress((void**)&ph,   g_h);
    cudaGetSymbolAddress((void**)&pacc, g_acc);
    cudaGetSymbolAddress((void**)&pA1,  g_A1);
    cudaGetSymbolAddress((void**)&pA2,  g_A2);
    cudaGetSymbolAddress((void**)&pA3,  g_A3);
    cudaGetSymbolAddress((void**)&pB2,  g_B2);
    cudaGetSymbolAddress((void**)&pB3,  g_B3);
    cudaGetSymbolAddress((void**)&pe,   g_e);
    cudaGetSymbolAddress((void**)&ptmp, g_tmp);

    const int SMEM = (8192 + 128 * 132) * (int)sizeof(float);  // 100352 B
    static int smem_set = 0;
    cudaFuncSetAttribute(gemm_multi_kernel, cudaFuncAttributeMaxDynamicSharedMemorySize, SMEM);
    (void)smem_set;

    auto gemm1 = [&](const float* A, const float* W, const float* b, float* o, int M) {
        G5 g; g.nw = 1; g.W[0] = W; g.B[0] = b; g.O[0] = o;
        gemm_multi_kernel<<<(M + 127) / 128, 128, SMEM>>>(A, g, M);
    };

    // node embed: h = LN(relu(x@W11+b)) @ W12 + b     (uses acc as temp)
    embed_ln_kernel<<<(Nn + 7) / 8, 256>>>(x, W11w, W11b, ln1g, ln1b, pacc, Nn, 64);
    gemm1(pacc, W12w, W12b, ph, Nn);
    // edge embed: e = LN(relu(ea@W21+b)) @ W22 + b
    embed_ln_kernel<<<(Ee + 7) / 8, 256>>>(ea, W21w, W21b, ln2g, ln2b, ptmp, Ee, 32);
    gemm1(ptmp, W22w, W22b, pe, Ee);

    // zero the scatter accumulator
    zero_kernel<<<(Nn * 128 / 4 + 255) / 256, 256>>>(pacc, Nn * 128);

    for (int l = 0; l < 3; l++) {
        const float* Awl = Aw + (size_t)l * 3 * 128 * 128;
        const float* Abl = Ab + (size_t)l * 3 * 128;
        const float* Bwl = Bw + (size_t)l * 3 * 128 * 128;
        const float* Bbl = Bb + (size_t)l * 3 * 128;
        {
            G5 g; g.nw = 5;
            g.W[0] = Awl;          g.B[0] = Abl;        g.O[0] = pA1;
            g.W[1] = Awl + 16384;  g.B[1] = Abl + 128;  g.O[1] = pA2;
            g.W[2] = Awl + 32768;  g.B[2] = Abl + 256;  g.O[2] = pA3;
            g.W[3] = Bwl + 16384;  g.B[3] = Bbl + 128;  g.O[3] = pB2;
            g.W[4] = Bwl + 32768;  g.B[4] = Bbl + 256;  g.O[4] = pB3;
            gemm_multi_kernel<<<(Nn + 127) / 128, 128, SMEM>>>(ph, g, Nn);
        }
        gemm1(pe, Bwl, Bbl, ptmp, Ee);   // B1e
        edge_layer_kernel<<<(Ee + 7) / 8, 256>>>(ei, ei + Ee, pe, ptmp, pA2, pA3, pB2, pB3,
                                                 lneg + l * 128, lneb + l * 128, pacc, Ee);
        node_update_kernel<<<(Nn + 7) / 8, 256>>>(pA1, pacc, ph,
                                                  lnhg + l * 128, lnhb + l * 128, Nn);
    }

    // final scorer: score = relu(h[row]@Sa + h[col]@Sb + e@Sc + s1b) @ s2w + s2b
    {
        G5 g; g.nw = 2;
        g.W[0] = s1w;          g.B[0] = nullptr; g.O[0] = pA1;
        g.W[1] = s1w + 16384;  g.B[1] = nullptr; g.O[1] = pA2;
        gemm_multi_kernel<<<(Nn + 127) / 128, 128, SMEM>>>(ph, g, Nn);
    }
    gemm1(pe, s1w + 32768, nullptr, ptmp, Ee);   // ec
    final_kernel<<<(Ee + 7) / 8, 256>>>(ei, ei + Ee, pA1, pA2, ptmp,
                                        s1b, s2w, s2b, (float*)d_out, Ee);
}

// round 5
// speedup vs baseline: 1.4187x; 1.0003x over previous
#include <cuda_runtime.h>
#include <cstdint>

#define H128 128
static const int CAP_N = 50000;
static const int CAP_E = 800000;

// ---------------- scratch (device globals; no allocation allowed) ----------------
__device__ float g_h  [CAP_N * H128];
__device__ float g_acc[CAP_N * H128];
__device__ float g_A1 [CAP_N * H128];
__device__ float g_A2 [CAP_N * H128];
__device__ float g_A3 [CAP_N * H128];
__device__ float g_B2 [CAP_N * H128];
__device__ float g_B3 [CAP_N * H128];
__device__ float g_e  [CAP_E * H128];
__device__ float g_tmp[CAP_E * H128];

// ---------------- helpers ----------------
__device__ __forceinline__ unsigned long long ffma2(unsigned long long a, unsigned long long b,
                                                    unsigned long long c) {
    unsigned long long d;
    asm("fma.rn.f32x2 %0, %1, %2, %3;" : "=l"(d) : "l"(a), "l"(b), "l"(c));
    return d;
}
__device__ __forceinline__ unsigned long long pack2(float lo, float hi) {
    unsigned long long d;
    asm("mov.b64 %0, {%1, %2};" : "=l"(d) : "f"(lo), "f"(hi));
    return d;
}
__device__ __forceinline__ void red_add_v4(float* p, const float* v) {
    asm volatile("red.global.add.v4.f32 [%0], {%1, %2, %3, %4};"
                 :: "l"(p), "f"(v[0]), "f"(v[1]), "f"(v[2]), "f"(v[3]) : "memory");
}
__device__ __forceinline__ void ld4(float* d, const float* p) {
    float4 v = *reinterpret_cast<const float4*>(p);
    d[0] = v.x; d[1] = v.y; d[2] = v.z; d[3] = v.w;
}
__device__ __forceinline__ void st4(float* p, const float* d) {
    float4 v; v.x = d[0]; v.y = d[1]; v.z = d[2]; v.w = d[3];
    *reinterpret_cast<float4*>(p) = v;
}

// ---------------- zero ----------------
__global__ void zero_kernel(float* __restrict__ p, int n) {
    int i = (blockIdx.x * blockDim.x + threadIdx.x) * 4;
    if (i < n) *reinterpret_cast<float4*>(p + i) = make_float4(0.f, 0.f, 0.f, 0.f);
}

// ---------------- multi-weight GEMM ----------------
// out_w[M,128] = A[M,128] @ W_w[128,128] (+ bias_w)  for w < nw (<=5)
// 128 threads, block tile 128x128, thread tile 8 rows x 16 cols.
// rows = rt*4 + {0..3} and +64 ; cols = ct*4 + 32*m, m=0..3  (conflict-free LDS)
struct G5 {
    const float* W[5];
    const float* B[5];
    float*       O[5];
    int nw;
};

__global__ void __launch_bounds__(128) gemm_multi_kernel(
    const float* __restrict__ A, G5 g, int M)
{
    extern __shared__ float sm[];
    float* ws = sm;             // [64][128] W chunk (32768 B)
    float* as = sm + 8192;      // [128][132] A tile row-major (67584 B)
    float4* as4 = reinterpret_cast<float4*>(as);
    const int t = threadIdx.x;
    const int rt = t >> 3;          // 0..15
    const int ct = t & 7;           // 0..7
    const int brow = blockIdx.x * 128;

    // load A tile (row-major, stride 132 floats = 33 float4)
    {
        const float4* A4 = reinterpret_cast<const float4*>(A);
        #pragma unroll
        for (int j = 0; j < 32; j++) {
            int flat = j * 128 + t;
            int row = flat >> 5, k4 = flat & 31;
            float4 v = make_float4(0.f, 0.f, 0.f, 0.f);
            int gr = brow + row;
            if (gr < M) v = A4[(size_t)gr * 32 + k4];
            as4[row * 33 + k4] = v;
        }
    }

    int rowg[8];
    #pragma unroll
    for (int r8 = 0; r8 < 8; r8++) rowg[r8] = rt * 4 + (r8 & 3) + ((r8 >> 2) << 6);

    for (int w = 0; w < g.nw; w++) {
        const float* W = g.W[w];
        const float* bias = g.B[w];
        unsigned long long acc[8][8];
        {
            unsigned long long b[8];
            #pragma unroll
            for (int m = 0; m < 4; m++) {
                if (bias) {
                    ulonglong2 u = *reinterpret_cast<const ulonglong2*>(bias + ct * 4 + 32 * m);
                    b[2 * m] = u.x; b[2 * m + 1] = u.y;
                } else { b[2 * m] = 0ull; b[2 * m + 1] = 0ull; }
            }
            #pragma unroll
            for (int r8 = 0; r8 < 8; r8++)
                #pragma unroll
                for (int c = 0; c < 8; c++) acc[r8][c] = b[c];
        }

        #pragma unroll 1
        for (int ch = 0; ch < 2; ch++) {
            const int kc = ch * 64;
            __syncthreads();
            // load W chunk [64][128]
            {
                const float4* W4 = reinterpret_cast<const float4*>(W);
                float4* ws4 = reinterpret_cast<float4*>(ws);
                #pragma unroll
                for (int j = 0; j < 16; j++) {
                    int flat = j * 128 + t;
                    int wk = flat >> 5, c4 = flat & 31;
                    ws4[wk * 32 + c4] = W4[(size_t)(kc + wk) * 32 + c4];
                }
            }
            __syncthreads();

            #pragma unroll 2
            for (int k4 = 0; k4 < 16; k4++) {
                float4 a[8];
                const int kq = (kc >> 2) + k4;
                #pragma unroll
                for (int r8 = 0; r8 < 8; r8++) a[r8] = as4[rowg[r8] * 33 + kq];
                #pragma unroll
                for (int kk = 0; kk < 4; kk++) {
                    unsigned long long av[8];
                    #pragma unroll
                    for (int r8 = 0; r8 < 8; r8++) {
                        float s = (kk == 0) ? a[r8].x : (kk == 1) ? a[r8].y :
                                  (kk == 2) ? a[r8].z : a[r8].w;
                        av[r8] = pack2(s, s);
                    }
                    const float* wr = ws + (k4 * 4 + kk) * 128 + ct * 4;
                    #pragma unroll
                    for (int m = 0; m < 4; m++) {
                        ulonglong2 u = *reinterpret_cast<const ulonglong2*>(wr + 32 * m);
                        #pragma unroll
                        for (int r8 = 0; r8 < 8; r8++) {
                            acc[r8][2 * m]     = ffma2(av[r8], u.x, acc[r8][2 * m]);
                            acc[r8][2 * m + 1] = ffma2(av[r8], u.y, acc[r8][2 * m + 1]);
                        }
                    }
                }
            }
        }

        // store
        float* out = g.O[w];
        #pragma unroll
        for (int r8 = 0; r8 < 8; r8++) {
            int gr = brow + rowg[r8];
            if (gr < M) {
                float* po = out + (size_t)gr * 128 + ct * 4;
                #pragma unroll
                for (int m = 0; m < 4; m++) {
                    ulonglong2 u; u.x = acc[r8][2 * m]; u.y = acc[r8][2 * m + 1];
                    *reinterpret_cast<ulonglong2*>(po + 32 * m) = u;
                }
            }
        }
    }
}

// ---------------- embed stage1: out = LN(relu(in @ W + b)) ----------------
__global__ void __launch_bounds__(256) embed_ln_kernel(
    const float* __restrict__ in, const float* __restrict__ W, const float* __restrict__ bias,
    const float* __restrict__ lng, const float* __restrict__ lnb,
    float* __restrict__ out, int M, int Kin)
{
    const int w = blockIdx.x * 8 + (threadIdx.x >> 5);
    const int lane = threadIdx.x & 31;
    if (w >= M) return;
    const float* xr = in + (size_t)w * Kin;
    float x0 = (lane < Kin) ? xr[lane] : 0.f;
    float x1 = (lane + 32 < Kin) ? xr[lane + 32] : 0.f;

    float a[4];
    ld4(a, bias + lane * 4);
    for (int k = 0; k < Kin; k++) {
        float xk = __shfl_sync(0xffffffffu, (k < 32) ? x0 : x1, k & 31);
        float4 wv = *reinterpret_cast<const float4*>(W + k * 128 + lane * 4);
        a[0] = fmaf(xk, wv.x, a[0]);
        a[1] = fmaf(xk, wv.y, a[1]);
        a[2] = fmaf(xk, wv.z, a[2]);
        a[3] = fmaf(xk, wv.w, a[3]);
    }
    float s = 0.f, q = 0.f;
    #pragma unroll
    for (int i = 0; i < 4; i++) {
        a[i] = fmaxf(a[i], 0.f);
        s += a[i]; q = fmaf(a[i], a[i], q);
    }
    #pragma unroll
    for (int o = 16; o; o >>= 1) {
        s += __shfl_xor_sync(0xffffffffu, s, o);
        q += __shfl_xor_sync(0xffffffffu, q, o);
    }
    const float inv = 1.f / 128.f;
    float m = s * inv;
    float is = rsqrtf(fmaxf(q * inv - m * m, 0.f) + 1e-5f);
    float gg[4], gb[4], o4[4];
    ld4(gg, lng + lane * 4); ld4(gb, lnb + lane * 4);
    #pragma unroll
    for (int i = 0; i < 4; i++) o4[i] = (a[i] - m) * is * gg[i] + gb[i];
    st4(out + (size_t)w * 128 + lane * 4, o4);
}

// ---------------- edge layer (warp per edge) ----------------
__global__ void __launch_bounds__(256) edge_layer_kernel(
    const int* __restrict__ rows, const int* __restrict__ cols,
    float* __restrict__ e, const float* __restrict__ b1e,
    const float* __restrict__ A2, const float* __restrict__ A3,
    const float* __restrict__ B2, const float* __restrict__ B3,
    const float* __restrict__ lng, const float* __restrict__ lnb,
    float* __restrict__ acc, int E_)
{
    const int w = blockIdx.x * 8 + (threadIdx.x >> 5);
    const int lane = threadIdx.x & 31;
    if (w >= E_) return;
    const int r = rows[w], c = cols[w];
    const size_t eo = (size_t)w * 128 + lane * 4;
    const size_t ro = (size_t)r * 128 + lane * 4;
    const size_t co = (size_t)c * 128 + lane * 4;

    float ev[4], b1[4], b2r[4], b3r[4], a2r[4], b2c[4], b3c[4], a3c[4];
    ld4(ev, e + eo);  ld4(b1, b1e + eo);
    ld4(b2r, B2 + ro); ld4(b3r, B3 + ro); ld4(a2r, A2 + ro);
    ld4(b2c, B2 + co); ld4(b3c, B3 + co); ld4(a3c, A3 + co);

    float gji[4], gik[4];
    float s1 = 0.f, q1 = 0.f, s2 = 0.f, q2 = 0.f;
    #pragma unroll
    for (int i = 0; i < 4; i++) {
        float u = fmaxf(b1[i] + b2r[i] + b3c[i], 0.f);
        float v = fmaxf(b1[i] + b2c[i] + b3r[i], 0.f);
        gji[i] = u; gik[i] = v;
        s1 += u; q1 = fmaf(u, u, q1);
        s2 += v; q2 = fmaf(v, v, q2);
    }
    #pragma unroll
    for (int o = 16; o; o >>= 1) {
        s1 += __shfl_xor_sync(0xffffffffu, s1, o);
        q1 += __shfl_xor_sync(0xffffffffu, q1, o);
        s2 += __shfl_xor_sync(0xffffffffu, s2, o);
        q2 += __shfl_xor_sync(0xffffffffu, q2, o);
    }
    const float inv = 1.f / 128.f;
    float m1 = s1 * inv, m2 = s2 * inv;
    float is1 = rsqrtf(fmaxf(q1 * inv - m1 * m1, 0.f) + 1e-5f);
    float is2 = rsqrtf(fmaxf(q2 * inv - m2 * m2, 0.f) + 1e-5f);

    float gg[4], gb[4];
    ld4(gg, lng + lane * 4); ld4(gb, lnb + lane * 4);

    float eji[4], sg1[4], sg2[4];
    float t1 = 0.f, t2 = 0.f;
    #pragma unroll
    for (int i = 0; i < 4; i++) {
        eji[i]    = ev[i] + (gji[i] - m1) * is1 * gg[i] + gb[i];
        float eik = ev[i] + (gik[i] - m2) * is2 * gg[i] + gb[i];
        sg1[i] = __fdividef(1.f, 1.f + __expf(-eji[i])); t1 += sg1[i];
        sg2[i] = __fdividef(1.f, 1.f + __expf(-eik));    t2 += sg2[i];
    }
    #pragma unroll
    for (int o = 16; o; o >>= 1) {
        t1 += __shfl_xor_sync(0xffffffffu, t1, o);
        t2 += __shfl_xor_sync(0xffffffffu, t2, o);
    }
    float w1 = __fdividef(1.f, t1 + 1e-6f);
    float w2 = __fdividef(1.f, t2 + 1e-6f);

    float mji[4], mik[4];
    #pragma unroll
    for (int i = 0; i < 4; i++) {
        mji[i] = a2r[i] * sg1[i] * w1;
        mik[i] = a3c[i] * sg2[i] * w2;
    }
    red_add_v4(acc + co, mji);
    red_add_v4(acc + ro, mik);
    st4(e + eo, eji);
}

// ---------------- node update: h += LN(relu(A1h + acc)); acc = 0 ----------------
__global__ void __launch_bounds__(256) node_update_kernel(
    const float* __restrict__ A1, float* __restrict__ acc, float* __restrict__ h,
    const float* __restrict__ lng, const float* __restrict__ lnb, int M)
{
    const int w = blockIdx.x * 8 + (threadIdx.x >> 5);
    const int lane = threadIdx.x & 31;
    if (w >= M) return;
    const size_t off = (size_t)w * 128 + lane * 4;
    float a[4], cc[4], t[4];
    ld4(a, A1 + off); ld4(cc, acc + off);
    float s = 0.f, q = 0.f;
    #pragma unroll
    for (int i = 0; i < 4; i++) {
        t[i] = fmaxf(a[i] + cc[i], 0.f);
        s += t[i]; q = fmaf(t[i], t[i], q);
    }
    #pragma unroll
    for (int o = 16; o; o >>= 1) {
        s += __shfl_xor_sync(0xffffffffu, s, o);
        q += __shfl_xor_sync(0xffffffffu, q, o);
    }
    const float inv = 1.f / 128.f;
    float m = s * inv;
    float is = rsqrtf(fmaxf(q * inv - m * m, 0.f) + 1e-5f);
    float gg[4], gb[4], hv[4];
    ld4(gg, lng + lane * 4); ld4(gb, lnb + lane * 4);
    ld4(hv, h + off);
    #pragma unroll
    for (int i = 0; i < 4; i++) hv[i] += (t[i] - m) * is * gg[i] + gb[i];
    st4(h + off, hv);
    float z[4] = {0.f, 0.f, 0.f, 0.f};
    st4(acc + off, z);
}

// ---------------- final scorer (warp per edge) ----------------
__global__ void __launch_bounds__(256) final_kernel(
    const int* __restrict__ rows, const int* __restrict__ cols,
    const float* __restrict__ ha, const float* __restrict__ hb, const float* __restrict__ ec,
    const float* __restrict__ s1b, const float* __restrict__ s2w, const float* __restrict__ s2b,
    float* __restrict__ out, int E_)
{
    const int w = blockIdx.x * 8 + (threadIdx.x >> 5);
    const int lane = threadIdx.x & 31;
    if (w >= E_) return;
    const int r = rows[w], c = cols[w];
    float A[4], B[4], C[4], b4[4], wv[4];
    ld4(A, ha + (size_t)r * 128 + lane * 4);
    ld4(B, hb + (size_t)c * 128 + lane * 4);
    ld4(C, ec + (size_t)w * 128 + lane * 4);
    ld4(b4, s1b + lane * 4);
    ld4(wv, s2w + lane * 4);
    float p = 0.f;
    #pragma unroll
    for (int i = 0; i < 4; i++) {
        float u = fmaxf(A[i] + B[i] + C[i] + b4[i], 0.f);
        p = fmaf(u, wv[i], p);
    }
    #pragma unroll
    for (int o = 16; o; o >>= 1) p += __shfl_xor_sync(0xffffffffu, p, o);
    if (lane == 0) out[w] = p + s2b[0];
}

// ---------------- host ----------------
extern "C" void kernel_launch(void* const* d_in, const int* in_sizes, int n_in,
                              void* d_out, int out_size)
{
    const float* x    = (const float*)d_in[0];
    const float* ea   = (const float*)d_in[1];
    const int*   ei   = (const int*)  d_in[2];
    const float* W11w = (const float*)d_in[3];
    const float* W11b = (const float*)d_in[4];
    const float* W12w = (const float*)d_in[5];
    const float* W12b = (const float*)d_in[6];
    const float* W21w = (const float*)d_in[7];
    const float* W21b = (const float*)d_in[8];
    const float* W22w = (const float*)d_in[9];
    const float* W22b = (const float*)d_in[10];
    const float* ln1g = (const float*)d_in[11];
    const float* ln1b = (const float*)d_in[12];
    const float* ln2g = (const float*)d_in[13];
    const float* ln2b = (const float*)d_in[14];
    const float* Aw   = (const float*)d_in[15];
    const float* Ab   = (const float*)d_in[16];
    const float* Bw   = (const float*)d_in[17];
    const float* Bb   = (const float*)d_in[18];
    const float* lnhg = (const float*)d_in[19];
    const float* lnhb = (const float*)d_in[20];
    const float* lneg = (const float*)d_in[21];
    const float* lneb = (const float*)d_in[22];
    const float* s1w  = (const float*)d_in[23];
    const float* s1b  = (const float*)d_in[24];
    const float* s2w  = (const float*)d_in[25];
    const float* s2b  = (const float*)d_in[26];

    int Nn = in_sizes[0] / 64;
    int Ee = in_sizes[2] / 2;
    if (Nn > CAP_N) Nn = CAP_N;
    if (Ee > CAP_E) Ee = CAP_E;

    float *ph, *pacc, *pA1, *pA2, *pA3, *pB2, *pB3, *pe, *ptmp;
    cudaGetSymbolAddress((void**)&ph,   g_h);
    cudaGetSymbolAddress((void**)&pacc, g_acc);
    cudaGetSymbolAddress((void**)&pA1,  g_A1);
    cudaGetSymbolAddress((void**)&pA2,  g_A2);
    cudaGetSymbolAddress((void**)&pA3,  g_A3);
    cudaGetSymbolAddress((void**)&pB2,  g_B2);
    cudaGetSymbolAddress((void**)&pB3,  g_B3);
    cudaGetSymbolAddress((void**)&pe,   g_e);
    cudaGetSymbolAddress((void**)&ptmp, g_tmp);

    const int SMEM = (8192 + 128 * 132) * (int)sizeof(float);  // 100352 B
    static int smem_set = 0;
    cudaFuncSetAttribute(gemm_multi_kernel, cudaFuncAttributeMaxDynamicSharedMemorySize, SMEM);
    (void)smem_set;

    auto gemm1 = [&](const float* A, const float* W, const float* b, float* o, int M) {
        G5 g; g.nw = 1; g.W[0] = W; g.B[0] = b; g.O[0] = o;
        gemm_multi_kernel<<<(M + 127) / 128, 128, SMEM>>>(A, g, M);
    };

    // node embed: h = LN(relu(x@W11+b)) @ W12 + b     (uses acc as temp)
    embed_ln_kernel<<<(Nn + 7) / 8, 256>>>(x, W11w, W11b, ln1g, ln1b, pacc, Nn, 64);
    gemm1(pacc, W12w, W12b, ph, Nn);
    // edge embed: e = LN(relu(ea@W21+b)) @ W22 + b
    embed_ln_kernel<<<(Ee + 7) / 8, 256>>>(ea, W21w, W21b, ln2g, ln2b, ptmp, Ee, 32);
    gemm1(ptmp, W22w, W22b, pe, Ee);

    // zero the scatter accumulator
    zero_kernel<<<(Nn * 128 / 4 + 255) / 256, 256>>>(pacc, Nn * 128);

    for (int l = 0; l < 3; l++) {
        const float* Awl = Aw + (size_t)l * 3 * 128 * 128;
        const float* Abl = Ab + (size_t)l * 3 * 128;
        const float* Bwl = Bw + (size_t)l * 3 * 128 * 128;
        const float* Bbl = Bb + (size_t)l * 3 * 128;
        {
            G5 g; g.nw = 5;
            g.W[0] = Awl;          g.B[0] = Abl;        g.O[0] = pA1;
            g.W[1] = Awl + 16384;  g.B[1] = Abl + 128;  g.O[1] = pA2;
            g.W[2] = Awl + 32768;  g.B[2] = Abl + 256;  g.O[2] = pA3;
            g.W[3] = Bwl + 16384;  g.B[3] = Bbl + 128;  g.O[3] = pB2;
            g.W[4] = Bwl + 32768;  g.B[4] = Bbl + 256;  g.O[4] = pB3;
            gemm_multi_kernel<<<(Nn + 127) / 128, 128, SMEM>>>(ph, g, Nn);
        }
        gemm1(pe, Bwl, Bbl, ptmp, Ee);   // B1e
        edge_layer_kernel<<<(Ee + 7) / 8, 256>>>(ei, ei + Ee, pe, ptmp, pA2, pA3, pB2, pB3,
                                                 lneg + l * 128, lneb + l * 128, pacc, Ee);
        node_update_kernel<<<(Nn + 7) / 8, 256>>>(pA1, pacc, ph,
                                                  lnhg + l * 128, lnhb + l * 128, Nn);
    }

    // final scorer: score = relu(h[row]@Sa + h[col]@Sb + e@Sc + s1b) @ s2w + s2b
    {
        G5 g; g.nw = 2;
        g.W[0] = s1w;          g.B[0] = nullptr; g.O[0] = pA1;
        g.W[1] = s1w + 16384;  g.B[1] = nullptr; g.O[1] = pA2;
        gemm_multi_kernel<<<(Nn + 127) / 128, 128, SMEM>>>(ph, g, Nn);
    }
    gemm1(pe, s1w + 32768, nullptr, ptmp, Ee);   // ec
    final_kernel<<<(Ee + 7) / 8, 256>>>(ei, ei + Ee, pA1, pA2, ptmp,
                                        s1b, s2w, s2b, (float*)d_out, Ee);
}

// round 7
// speedup vs baseline: 1.9039x; 1.3420x over previous
#include <cuda_runtime.h>
#include <cstdint>

#define H128 128
static const int CAP_N = 50000;
static const int CAP_E = 800000;

// ---------------- scratch (device globals; no allocation allowed) ----------------
__device__ float g_h  [CAP_N * H128];
__device__ float g_acc[CAP_N * H128];
__device__ float g_A1 [CAP_N * H128];
__device__ float g_A2 [CAP_N * H128];
__device__ float g_A3 [CAP_N * H128];
__device__ float g_B2 [CAP_N * H128];
__device__ float g_B3 [CAP_N * H128];
__device__ float g_e  [CAP_E * H128];
__device__ float g_tmp[CAP_E * H128];

// ---------------- generic helpers ----------------
__device__ __forceinline__ void red_add_v4(float* p, const float* v) {
    asm volatile("red.global.add.v4.f32 [%0], {%1, %2, %3, %4};"
                 :: "l"(p), "f"(v[0]), "f"(v[1]), "f"(v[2]), "f"(v[3]) : "memory");
}
__device__ __forceinline__ void ld4(float* d, const float* p) {
    float4 v = *reinterpret_cast<const float4*>(p);
    d[0] = v.x; d[1] = v.y; d[2] = v.z; d[3] = v.w;
}
__device__ __forceinline__ void st4(float* p, const float* d) {
    float4 v; v.x = d[0]; v.y = d[1]; v.z = d[2]; v.w = d[3];
    *reinterpret_cast<float4*>(p) = v;
}
__device__ __forceinline__ uint32_t to_tf32(float x) {
    uint32_t r;
    asm("cvt.rna.tf32.f32 %0, %1;" : "=r"(r) : "f"(x));
    return r;
}
// mma.sync m16n8k8 tf32 (row.col), fp32 accumulate — portable PTX, works on compute_103
__device__ __forceinline__ void mma_tf32(float d[4], const uint32_t a[4], const uint32_t b[2],
                                         const float c[4]) {
    asm volatile(
        "mma.sync.aligned.m16n8k8.row.col.f32.tf32.tf32.f32 "
        "{%0,%1,%2,%3}, {%4,%5,%6,%7}, {%8,%9}, {%10,%11,%12,%13};"
        : "=f"(d[0]), "=f"(d[1]), "=f"(d[2]), "=f"(d[3])
        : "r"(a[0]), "r"(a[1]), "r"(a[2]), "r"(a[3]),
          "r"(b[0]), "r"(b[1]),
          "f"(c[0]), "f"(c[1]), "f"(c[2]), "f"(c[3]));
}

// ---------------- tensor-core GEMM via mma.sync tf32 ----------------
// out_w[M,128] = A[M,128] @ W_w[128,128] (+bias_w), w < nw (<=5), A tile shared.
struct G5 {
    const float* W[5];
    const float* B[5];
    float*       O[5];
    int nw;
};

static const int AS_STRIDE = 132;   // A smem stride (floats): frag banks 4*gid+tig, conflict-free
static const int WS_STRIDE = 136;   // W smem stride (floats): frag banks 8*tig+gid, conflict-free
static const int SM_A = 0;                          // A: 128 x 132
static const int SM_W = 128 * AS_STRIDE;            // W chunk: 64 x 136
static const int SM_FLOATS = SM_W + 64 * WS_STRIDE; // 25600 floats
static const int SM_BYTES = SM_FLOATS * 4;          // 102400 B -> 2 CTAs/SM

__global__ void __launch_bounds__(128, 2) gemm_mma_kernel(
    const float* __restrict__ A, G5 g, int M)
{
    extern __shared__ float sm[];
    uint32_t* as  = reinterpret_cast<uint32_t*>(sm + SM_A);
    uint32_t* wsm = reinterpret_cast<uint32_t*>(sm + SM_W);

    const int t = threadIdx.x;
    const int wid = t >> 5, lane = t & 31;
    const int gid = lane >> 2, tig = lane & 3;
    const int wm = wid & 1;    // warp row: 0/1 -> 64 rows each
    const int wn = wid >> 1;   // warp col: 0/1 -> 64 cols each
    const int brow = blockIdx.x * 128;

    // ---- load A tile, convert to tf32 ----
    {
        const float4* A4 = reinterpret_cast<const float4*>(A);
        #pragma unroll
        for (int j = 0; j < 32; j++) {
            int flat = j * 128 + t;
            int row = flat >> 5, k4 = flat & 31;
            int gr = brow + row;
            float4 v = make_float4(0.f, 0.f, 0.f, 0.f);
            if (gr < M) v = A4[(size_t)gr * 32 + k4];
            uint4 u; u.x = to_tf32(v.x); u.y = to_tf32(v.y); u.z = to_tf32(v.z); u.w = to_tf32(v.w);
            *reinterpret_cast<uint4*>(as + row * AS_STRIDE + k4 * 4) = u;
        }
    }

    for (int w = 0; w < g.nw; w++) {
        const float* W = g.W[w];
        float acc[4][8][4];
        #pragma unroll
        for (int mi = 0; mi < 4; mi++)
            #pragma unroll
            for (int ni = 0; ni < 8; ni++)
                #pragma unroll
                for (int q = 0; q < 4; q++) acc[mi][ni][q] = 0.f;

        #pragma unroll 1
        for (int ch = 0; ch < 2; ch++) {
            __syncthreads();
            // load W chunk rows [ch*64, ch*64+64), natural [k][n] layout, tf32
            {
                const float4* W4 = reinterpret_cast<const float4*>(W);
                #pragma unroll
                for (int j = 0; j < 16; j++) {
                    int flat = j * 128 + t;
                    int k = flat >> 5, c4 = flat & 31;
                    float4 v = W4[(size_t)(ch * 64 + k) * 32 + c4];
                    uint4 u; u.x = to_tf32(v.x); u.y = to_tf32(v.y);
                    u.z = to_tf32(v.z); u.w = to_tf32(v.w);
                    *reinterpret_cast<uint4*>(wsm + k * WS_STRIDE + c4 * 4) = u;
                }
            }
            __syncthreads();

            #pragma unroll
            for (int ks = 0; ks < 8; ks++) {
                const int k0 = ks * 8;
                uint32_t af[4][4];
                #pragma unroll
                for (int mi = 0; mi < 4; mi++) {
                    const uint32_t* pa = as + (wm * 64 + mi * 16 + gid) * AS_STRIDE + ch * 64 + k0;
                    af[mi][0] = pa[tig];
                    af[mi][1] = pa[8 * AS_STRIDE + tig];
                    af[mi][2] = pa[tig + 4];
                    af[mi][3] = pa[8 * AS_STRIDE + tig + 4];
                }
                uint32_t bf[8][2];
                #pragma unroll
                for (int ni = 0; ni < 8; ni++) {
                    const uint32_t* pb = wsm + (k0 + tig) * WS_STRIDE + wn * 64 + ni * 8 + gid;
                    bf[ni][0] = pb[0];
                    bf[ni][1] = pb[4 * WS_STRIDE];
                }
                #pragma unroll
                for (int mi = 0; mi < 4; mi++)
                    #pragma unroll
                    for (int ni = 0; ni < 8; ni++)
                        mma_tf32(acc[mi][ni], af[mi], bf[ni], acc[mi][ni]);
            }
        }

        // ---- bias + store ----
        float* O = g.O[w];
        const float* bias = g.B[w];
        #pragma unroll
        for (int ni = 0; ni < 8; ni++) {
            const int col = wn * 64 + ni * 8 + 2 * tig;
            float b0 = 0.f, b1 = 0.f;
            if (bias) { b0 = bias[col]; b1 = bias[col + 1]; }
            #pragma unroll
            for (int mi = 0; mi < 4; mi++) {
                const int row0 = brow + wm * 64 + mi * 16 + gid;
                if (row0 < M) {
                    float2 v; v.x = acc[mi][ni][0] + b0; v.y = acc[mi][ni][1] + b1;
                    *reinterpret_cast<float2*>(O + (size_t)row0 * 128 + col) = v;
                }
                if (row0 + 8 < M) {
                    float2 v; v.x = acc[mi][ni][2] + b0; v.y = acc[mi][ni][3] + b1;
                    *reinterpret_cast<float2*>(O + (size_t)(row0 + 8) * 128 + col) = v;
                }
            }
        }
    }
}

// ---------------- zero ----------------
__global__ void zero_kernel(float* __restrict__ p, int n) {
    int i = (blockIdx.x * blockDim.x + threadIdx.x) * 4;
    if (i < n) *reinterpret_cast<float4*>(p + i) = make_float4(0.f, 0.f, 0.f, 0.f);
}

// ---------------- embed stage1: out = LN(relu(in @ W + b)) ----------------
__global__ void __launch_bounds__(256) embed_ln_kernel(
    const float* __restrict__ in, const float* __restrict__ W, const float* __restrict__ bias,
    const float* __restrict__ lng, const float* __restrict__ lnb,
    float* __restrict__ out, int M, int Kin)
{
    const int w = blockIdx.x * 8 + (threadIdx.x >> 5);
    const int lane = threadIdx.x & 31;
    if (w >= M) return;
    const float* xr = in + (size_t)w * Kin;
    float x0 = (lane < Kin) ? xr[lane] : 0.f;
    float x1 = (lane + 32 < Kin) ? xr[lane + 32] : 0.f;

    float a[4];
    ld4(a, bias + lane * 4);
    for (int k = 0; k < Kin; k++) {
        float xk = __shfl_sync(0xffffffffu, (k < 32) ? x0 : x1, k & 31);
        float4 wv = *reinterpret_cast<const float4*>(W + k * 128 + lane * 4);
        a[0] = fmaf(xk, wv.x, a[0]);
        a[1] = fmaf(xk, wv.y, a[1]);
        a[2] = fmaf(xk, wv.z, a[2]);
        a[3] = fmaf(xk, wv.w, a[3]);
    }
    float s = 0.f, q = 0.f;
    #pragma unroll
    for (int i = 0; i < 4; i++) {
        a[i] = fmaxf(a[i], 0.f);
        s += a[i]; q = fmaf(a[i], a[i], q);
    }
    #pragma unroll
    for (int o = 16; o; o >>= 1) {
        s += __shfl_xor_sync(0xffffffffu, s, o);
        q += __shfl_xor_sync(0xffffffffu, q, o);
    }
    const float inv = 1.f / 128.f;
    float m = s * inv;
    float is = rsqrtf(fmaxf(q * inv - m * m, 0.f) + 1e-5f);
    float gg[4], gb[4], o4[4];
    ld4(gg, lng + lane * 4); ld4(gb, lnb + lane * 4);
    #pragma unroll
    for (int i = 0; i < 4; i++) o4[i] = (a[i] - m) * is * gg[i] + gb[i];
    st4(out + (size_t)w * 128 + lane * 4, o4);
}

// ---------------- edge layer (warp per edge) ----------------
__global__ void __launch_bounds__(256) edge_layer_kernel(
    const int* __restrict__ rows, const int* __restrict__ cols,
    float* __restrict__ e, const float* __restrict__ b1e,
    const float* __restrict__ A2, const float* __restrict__ A3,
    const float* __restrict__ B2, const float* __restrict__ B3,
    const float* __restrict__ lng, const float* __restrict__ lnb,
    float* __restrict__ acc, int E_)
{
    const int w = blockIdx.x * 8 + (threadIdx.x >> 5);
    const int lane = threadIdx.x & 31;
    if (w >= E_) return;
    const int r = rows[w], c = cols[w];
    const size_t eo = (size_t)w * 128 + lane * 4;
    const size_t ro = (size_t)r * 128 + lane * 4;
    const size_t co = (size_t)c * 128 + lane * 4;

    float ev[4], b1[4], b2r[4], b3r[4], a2r[4], b2c[4], b3c[4], a3c[4];
    ld4(ev, e + eo);  ld4(b1, b1e + eo);
    ld4(b2r, B2 + ro); ld4(b3r, B3 + ro); ld4(a2r, A2 + ro);
    ld4(b2c, B2 + co); ld4(b3c, B3 + co); ld4(a3c, A3 + co);

    float gji[4], gik[4];
    float s1 = 0.f, q1 = 0.f, s2 = 0.f, q2 = 0.f;
    #pragma unroll
    for (int i = 0; i < 4; i++) {
        float u = fmaxf(b1[i] + b2r[i] + b3c[i], 0.f);
        float v = fmaxf(b1[i] + b2c[i] + b3r[i], 0.f);
        gji[i] = u; gik[i] = v;
        s1 += u; q1 = fmaf(u, u, q1);
        s2 += v; q2 = fmaf(v, v, q2);
    }
    #pragma unroll
    for (int o = 16; o; o >>= 1) {
        s1 += __shfl_xor_sync(0xffffffffu, s1, o);
        q1 += __shfl_xor_sync(0xffffffffu, q1, o);
        s2 += __shfl_xor_sync(0xffffffffu, s2, o);
        q2 += __shfl_xor_sync(0xffffffffu, q2, o);
    }
    const float inv = 1.f / 128.f;
    float m1 = s1 * inv, m2 = s2 * inv;
    float is1 = rsqrtf(fmaxf(q1 * inv - m1 * m1, 0.f) + 1e-5f);
    float is2 = rsqrtf(fmaxf(q2 * inv - m2 * m2, 0.f) + 1e-5f);

    float gg[4], gb[4];
    ld4(gg, lng + lane * 4); ld4(gb, lnb + lane * 4);

    float eji[4], sg1[4], sg2[4];
    float t1 = 0.f, t2 = 0.f;
    #pragma unroll
    for (int i = 0; i < 4; i++) {
        eji[i]    = ev[i] + (gji[i] - m1) * is1 * gg[i] + gb[i];
        float eik = ev[i] + (gik[i] - m2) * is2 * gg[i] + gb[i];
        sg1[i] = __fdividef(1.f, 1.f + __expf(-eji[i])); t1 += sg1[i];
        sg2[i] = __fdividef(1.f, 1.f + __expf(-eik));    t2 += sg2[i];
    }
    #pragma unroll
    for (int o = 16; o; o >>= 1) {
        t1 += __shfl_xor_sync(0xffffffffu, t1, o);
        t2 += __shfl_xor_sync(0xffffffffu, t2, o);
    }
    float w1 = __fdividef(1.f, t1 + 1e-6f);
    float w2 = __fdividef(1.f, t2 + 1e-6f);

    float mji[4], mik[4];
    #pragma unroll
    for (int i = 0; i < 4; i++) {
        mji[i] = a2r[i] * sg1[i] * w1;
        mik[i] = a3c[i] * sg2[i] * w2;
    }
    red_add_v4(acc + co, mji);
    red_add_v4(acc + ro, mik);
    st4(e + eo, eji);
}

// ---------------- node update: h += LN(relu(A1h + acc)); acc = 0 ----------------
__global__ void __launch_bounds__(256) node_update_kernel(
    const float* __restrict__ A1, float* __restrict__ acc, float* __restrict__ h,
    const float* __restrict__ lng, const float* __restrict__ lnb, int M)
{
    const int w = blockIdx.x * 8 + (threadIdx.x >> 5);
    const int lane = threadIdx.x & 31;
    if (w >= M) return;
    const size_t off = (size_t)w * 128 + lane * 4;
    float a[4], cc[4], t[4];
    ld4(a, A1 + off); ld4(cc, acc + off);
    float s = 0.f, q = 0.f;
    #pragma unroll
    for (int i = 0; i < 4; i++) {
        t[i] = fmaxf(a[i] + cc[i], 0.f);
        s += t[i]; q = fmaf(t[i], t[i], q);
    }
    #pragma unroll
    for (int o = 16; o; o >>= 1) {
        s += __shfl_xor_sync(0xffffffffu, s, o);
        q += __shfl_xor_sync(0xffffffffu, q, o);
    }
    const float inv = 1.f / 128.f;
    float m = s * inv;
    float is = rsqrtf(fmaxf(q * inv - m * m, 0.f) + 1e-5f);
    float gg[4], gb[4], hv[4];
    ld4(gg, lng + lane * 4); ld4(gb, lnb + lane * 4);
    ld4(hv, h + off);
    #pragma unroll
    for (int i = 0; i < 4; i++) hv[i] += (t[i] - m) * is * gg[i] + gb[i];
    st4(h + off, hv);
    float z[4] = {0.f, 0.f, 0.f, 0.f};
    st4(acc + off, z);
}

// ---------------- final scorer (warp per edge) ----------------
__global__ void __launch_bounds__(256) final_kernel(
    const int* __restrict__ rows, const int* __restrict__ cols,
    const float* __restrict__ ha, const float* __restrict__ hb, const float* __restrict__ ec,
    const float* __restrict__ s1b, const float* __restrict__ s2w, const float* __restrict__ s2b,
    float* __restrict__ out, int E_)
{
    const int w = blockIdx.x * 8 + (threadIdx.x >> 5);
    const int lane = threadIdx.x & 31;
    if (w >= E_) return;
    const int r = rows[w], c = cols[w];
    float A[4], B[4], C[4], b4[4], wv[4];
    ld4(A, ha + (size_t)r * 128 + lane * 4);
    ld4(B, hb + (size_t)c * 128 + lane * 4);
    ld4(C, ec + (size_t)w * 128 + lane * 4);
    ld4(b4, s1b + lane * 4);
    ld4(wv, s2w + lane * 4);
    float p = 0.f;
    #pragma unroll
    for (int i = 0; i < 4; i++) {
        float u = fmaxf(A[i] + B[i] + C[i] + b4[i], 0.f);
        p = fmaf(u, wv[i], p);
    }
    #pragma unroll
    for (int o = 16; o; o >>= 1) p += __shfl_xor_sync(0xffffffffu, p, o);
    if (lane == 0) out[w] = p + s2b[0];
}

// ---------------- host ----------------
extern "C" void kernel_launch(void* const* d_in, const int* in_sizes, int n_in,
                              void* d_out, int out_size)
{
    const float* x    = (const float*)d_in[0];
    const float* ea   = (const float*)d_in[1];
    const int*   ei   = (const int*)  d_in[2];
    const float* W11w = (const float*)d_in[3];
    const float* W11b = (const float*)d_in[4];
    const float* W12w = (const float*)d_in[5];
    const float* W12b = (const float*)d_in[6];
    const float* W21w = (const float*)d_in[7];
    const float* W21b = (const float*)d_in[8];
    const float* W22w = (const float*)d_in[9];
    const float* W22b = (const float*)d_in[10];
    const float* ln1g = (const float*)d_in[11];
    const float* ln1b = (const float*)d_in[12];
    const float* ln2g = (const float*)d_in[13];
    const float* ln2b = (const float*)d_in[14];
    const float* Aw   = (const float*)d_in[15];
    const float* Ab   = (const float*)d_in[16];
    const float* Bw   = (const float*)d_in[17];
    const float* Bb   = (const float*)d_in[18];
    const float* lnhg = (const float*)d_in[19];
    const float* lnhb = (const float*)d_in[20];
    const float* lneg = (const float*)d_in[21];
    const float* lneb = (const float*)d_in[22];
    const float* s1w  = (const float*)d_in[23];
    const float* s1b  = (const float*)d_in[24];
    const float* s2w  = (const float*)d_in[25];
    const float* s2b  = (const float*)d_in[26];

    int Nn = in_sizes[0] / 64;
    int Ee = in_sizes[2] / 2;
    if (Nn > CAP_N) Nn = CAP_N;
    if (Ee > CAP_E) Ee = CAP_E;

    float *ph, *pacc, *pA1, *pA2, *pA3, *pB2, *pB3, *pe, *ptmp;
    cudaGetSymbolAddress((void**)&ph,   g_h);
    cudaGetSymbolAddress((void**)&pacc, g_acc);
    cudaGetSymbolAddress((void**)&pA1,  g_A1);
    cudaGetSymbolAddress((void**)&pA2,  g_A2);
    cudaGetSymbolAddress((void**)&pA3,  g_A3);
    cudaGetSymbolAddress((void**)&pB2,  g_B2);
    cudaGetSymbolAddress((void**)&pB3,  g_B3);
    cudaGetSymbolAddress((void**)&pe,   g_e);
    cudaGetSymbolAddress((void**)&ptmp, g_tmp);

    cudaFuncSetAttribute(gemm_mma_kernel, cudaFuncAttributeMaxDynamicSharedMemorySize, SM_BYTES);

    auto gemm_tc = [&](const float* A, G5& g, int M) {
        int tiles = (M + 127) / 128;
        gemm_mma_kernel<<<tiles, 128, SM_BYTES>>>(A, g, M);
    };
    auto gemm1 = [&](const float* A, const float* W, const float* b, float* o, int M) {
        G5 g; g.nw = 1; g.W[0] = W; g.B[0] = b; g.O[0] = o;
        gemm_tc(A, g, M);
    };

    // node embed: h = LN(relu(x@W11+b)) @ W12 + b     (uses acc as temp)
    embed_ln_kernel<<<(Nn + 7) / 8, 256>>>(x, W11w, W11b, ln1g, ln1b, pacc, Nn, 64);
    gemm1(pacc, W12w, W12b, ph, Nn);
    // edge embed: e = LN(relu(ea@W21+b)) @ W22 + b
    embed_ln_kernel<<<(Ee + 7) / 8, 256>>>(ea, W21w, W21b, ln2g, ln2b, ptmp, Ee, 32);
    gemm1(ptmp, W22w, W22b, pe, Ee);

    // zero the scatter accumulator
    zero_kernel<<<(Nn * 128 / 4 + 255) / 256, 256>>>(pacc, Nn * 128);

    for (int l = 0; l < 3; l++) {
        const float* Awl = Aw + (size_t)l * 3 * 128 * 128;
        const float* Abl = Ab + (size_t)l * 3 * 128;
        const float* Bwl = Bw + (size_t)l * 3 * 128 * 128;
        const float* Bbl = Bb + (size_t)l * 3 * 128;
        {
            G5 g; g.nw = 5;
            g.W[0] = Awl;          g.B[0] = Abl;        g.O[0] = pA1;
            g.W[1] = Awl + 16384;  g.B[1] = Abl + 128;  g.O[1] = pA2;
            g.W[2] = Awl + 32768;  g.B[2] = Abl + 256;  g.O[2] = pA3;
            g.W[3] = Bwl + 16384;  g.B[3] = Bbl + 128;  g.O[3] = pB2;
            g.W[4] = Bwl + 32768;  g.B[4] = Bbl + 256;  g.O[4] = pB3;
            gemm_tc(ph, g, Nn);
        }
        gemm1(pe, Bwl, Bbl, ptmp, Ee);   // B1e
        edge_layer_kernel<<<(Ee + 7) / 8, 256>>>(ei, ei + Ee, pe, ptmp, pA2, pA3, pB2, pB3,
                                                 lneg + l * 128, lneb + l * 128, pacc, Ee);
        node_update_kernel<<<(Nn + 7) / 8, 256>>>(pA1, pacc, ph,
                                                  lnhg + l * 128, lnhb + l * 128, Nn);
    }

    // final scorer: score = relu(h[row]@Sa + h[col]@Sb + e@Sc + s1b) @ s2w + s2b
    {
        G5 g; g.nw = 2;
        g.W[0] = s1w;          g.B[0] = nullptr; g.O[0] = pA1;
        g.W[1] = s1w + 16384;  g.B[1] = nullptr; g.O[1] = pA2;
        gemm_tc(ph, g, Nn);
    }
    gemm1(pe, s1w + 32768, nullptr, ptmp, Ee);   // ec
    final_kernel<<<(Ee + 7) / 8, 256>>>(ei, ei + Ee, pA1, pA2, ptmp,
                                        s1b, s2w, s2b, (float*)d_out, Ee);
}

// round 8
// speedup vs baseline: 2.1022x; 1.1041x over previous
#include <cuda_runtime.h>
#include <cstdint>

#define H128 128
static const int CAP_N = 50000;
static const int CAP_E = 800000;

// ---------------- scratch (device globals; no allocation allowed) ----------------
__device__ float g_h  [CAP_N * H128];
__device__ float g_acc[CAP_N * H128];
__device__ float g_A1 [CAP_N * H128];
__device__ float g_A2 [CAP_N * H128];
__device__ float g_A3 [CAP_N * H128];
__device__ float g_B2 [CAP_N * H128];
__device__ float g_B3 [CAP_N * H128];
__device__ float g_e  [CAP_E * H128];
__device__ float g_tmp[CAP_E * H128];

// ---------------- generic helpers ----------------
__device__ __forceinline__ void red_add_v4(float* p, const float* v) {
    asm volatile("red.global.add.v4.f32 [%0], {%1, %2, %3, %4};"
                 :: "l"(p), "f"(v[0]), "f"(v[1]), "f"(v[2]), "f"(v[3]) : "memory");
}
__device__ __forceinline__ void ld4(float* d, const float* p) {
    float4 v = *reinterpret_cast<const float4*>(p);
    d[0] = v.x; d[1] = v.y; d[2] = v.z; d[3] = v.w;
}
__device__ __forceinline__ void st4(float* p, const float* d) {
    float4 v; v.x = d[0]; v.y = d[1]; v.z = d[2]; v.w = d[3];
    *reinterpret_cast<float4*>(p) = v;
}
__device__ __forceinline__ uint32_t to_tf32(float x) {
    uint32_t r;
    asm("cvt.rna.tf32.f32 %0, %1;" : "=r"(r) : "f"(x));
    return r;
}
// mma.sync m16n8k8 tf32 (row.col), fp32 accumulate — portable PTX, works on compute_103
__device__ __forceinline__ void mma_tf32(float d[4], const uint32_t a[4], const uint32_t b[2],
                                         const float c[4]) {
    asm volatile(
        "mma.sync.aligned.m16n8k8.row.col.f32.tf32.tf32.f32 "
        "{%0,%1,%2,%3}, {%4,%5,%6,%7}, {%8,%9}, {%10,%11,%12,%13};"
        : "=f"(d[0]), "=f"(d[1]), "=f"(d[2]), "=f"(d[3])
        : "r"(a[0]), "r"(a[1]), "r"(a[2]), "r"(a[3]),
          "r"(b[0]), "r"(b[1]),
          "f"(c[0]), "f"(c[1]), "f"(c[2]), "f"(c[3]));
}

// ---------------- shared GEMM tile machinery (256 threads, 128x128 tile) ----------------
static const int AS_STRIDE = 132;   // A smem stride (floats), conflict-free frag loads
static const int WS_STRIDE = 136;   // W smem stride (floats), conflict-free frag loads
static const int SM_W = 128 * AS_STRIDE;            // W chunk after A tile
static const int SM_FLOATS = SM_W + 64 * WS_STRIDE;
static const int SM_BYTES = SM_FLOATS * 4;          // 102016 B -> 2 CTAs/SM

// load A[brow..brow+127][0..127] -> smem tf32 (zero-padded past M)
__device__ __forceinline__ void load_tile_tf32(const float* __restrict__ A, int M, int brow,
                                               uint32_t* as, int t) {
    const float4* A4 = reinterpret_cast<const float4*>(A);
    #pragma unroll
    for (int j = 0; j < 16; j++) {
        int flat = j * 256 + t;
        int row = flat >> 5, k4 = flat & 31;
        int gr = brow + row;
        float4 v = make_float4(0.f, 0.f, 0.f, 0.f);
        if (gr < M) v = A4[(size_t)gr * 32 + k4];
        uint4 u; u.x = to_tf32(v.x); u.y = to_tf32(v.y); u.z = to_tf32(v.z); u.w = to_tf32(v.w);
        *reinterpret_cast<uint4*>(as + row * AS_STRIDE + k4 * 4) = u;
    }
}

// compute dacc = Atile @ W ; warp tile 32x64: wm=wid&3 (m), wn=wid>>2 (n)
__device__ __forceinline__ void gemm_core_256(const uint32_t* as, uint32_t* wsm,
                                              const float* __restrict__ W,
                                              float dacc[2][8][4], int t) {
    const int wid = t >> 5, lane = t & 31;
    const int gid = lane >> 2, tig = lane & 3;
    const int m0 = (wid & 3) * 32, n0 = (wid >> 2) * 64;

    #pragma unroll
    for (int mi = 0; mi < 2; mi++)
        #pragma unroll
        for (int ni = 0; ni < 8; ni++)
            #pragma unroll
            for (int q = 0; q < 4; q++) dacc[mi][ni][q] = 0.f;

    #pragma unroll 1
    for (int ch = 0; ch < 2; ch++) {
        __syncthreads();
        {
            const float4* W4 = reinterpret_cast<const float4*>(W);
            #pragma unroll
            for (int j = 0; j < 8; j++) {
                int flat = j * 256 + t;
                int k = flat >> 5, c4 = flat & 31;
                float4 v = W4[(size_t)(ch * 64 + k) * 32 + c4];
                uint4 u; u.x = to_tf32(v.x); u.y = to_tf32(v.y);
                u.z = to_tf32(v.z); u.w = to_tf32(v.w);
                *reinterpret_cast<uint4*>(wsm + k * WS_STRIDE + c4 * 4) = u;
            }
        }
        __syncthreads();

        #pragma unroll
        for (int ks = 0; ks < 8; ks++) {
            const int k0 = ks * 8;
            uint32_t af[2][4];
            #pragma unroll
            for (int mi = 0; mi < 2; mi++) {
                const uint32_t* pa = as + (m0 + mi * 16 + gid) * AS_STRIDE + ch * 64 + k0;
                af[mi][0] = pa[tig];
                af[mi][1] = pa[8 * AS_STRIDE + tig];
                af[mi][2] = pa[tig + 4];
                af[mi][3] = pa[8 * AS_STRIDE + tig + 4];
            }
            uint32_t bf[8][2];
            #pragma unroll
            for (int ni = 0; ni < 8; ni++) {
                const uint32_t* pb = wsm + (k0 + tig) * WS_STRIDE + n0 + ni * 8 + gid;
                bf[ni][0] = pb[0];
                bf[ni][1] = pb[4 * WS_STRIDE];
            }
            #pragma unroll
            for (int mi = 0; mi < 2; mi++)
                #pragma unroll
                for (int ni = 0; ni < 8; ni++)
                    mma_tf32(dacc[mi][ni], af[mi], bf[ni], dacc[mi][ni]);
        }
    }
}

// store dacc (+bias) into smem tile ebt[128][AS_STRIDE]
__device__ __forceinline__ void store_dacc_smem(float* ebt, float dacc[2][8][4],
                                                const float* __restrict__ bias, int t) {
    const int wid = t >> 5, lane = t & 31;
    const int gid = lane >> 2, tig = lane & 3;
    const int m0 = (wid & 3) * 32, n0 = (wid >> 2) * 64;
    #pragma unroll
    for (int ni = 0; ni < 8; ni++) {
        const int col = n0 + ni * 8 + 2 * tig;
        float b0 = 0.f, b1 = 0.f;
        if (bias) { b0 = bias[col]; b1 = bias[col + 1]; }
        #pragma unroll
        for (int mi = 0; mi < 2; mi++) {
            const int row = m0 + mi * 16 + gid;
            float2 v0; v0.x = dacc[mi][ni][0] + b0; v0.y = dacc[mi][ni][1] + b1;
            float2 v1; v1.x = dacc[mi][ni][2] + b0; v1.y = dacc[mi][ni][3] + b1;
            *reinterpret_cast<float2*>(ebt + row * AS_STRIDE + col) = v0;
            *reinterpret_cast<float2*>(ebt + (row + 8) * AS_STRIDE + col) = v1;
        }
    }
}

// ---------------- standalone multi-weight GEMM ----------------
struct G5 {
    const float* W[5];
    const float* B[5];
    float*       O[5];
    int nw;
};

__global__ void __launch_bounds__(256, 2) gemm_mma_kernel(
    const float* __restrict__ A, G5 g, int M)
{
    extern __shared__ float sm[];
    uint32_t* as  = reinterpret_cast<uint32_t*>(sm);
    uint32_t* wsm = reinterpret_cast<uint32_t*>(sm + SM_W);
    const int t = threadIdx.x;
    const int wid = t >> 5, lane = t & 31;
    const int gid = lane >> 2, tig = lane & 3;
    const int m0 = (wid & 3) * 32, n0 = (wid >> 2) * 64;
    const int brow = blockIdx.x * 128;

    load_tile_tf32(A, M, brow, as, t);

    for (int w = 0; w < g.nw; w++) {
        float dacc[2][8][4];
        gemm_core_256(as, wsm, g.W[w], dacc, t);

        float* O = g.O[w];
        const float* bias = g.B[w];
        #pragma unroll
        for (int ni = 0; ni < 8; ni++) {
            const int col = n0 + ni * 8 + 2 * tig;
            float b0 = 0.f, b1 = 0.f;
            if (bias) { b0 = bias[col]; b1 = bias[col + 1]; }
            #pragma unroll
            for (int mi = 0; mi < 2; mi++) {
                const int row0 = brow + m0 + mi * 16 + gid;
                if (row0 < M) {
                    float2 v; v.x = dacc[mi][ni][0] + b0; v.y = dacc[mi][ni][1] + b1;
                    *reinterpret_cast<float2*>(O + (size_t)row0 * 128 + col) = v;
                }
                if (row0 + 8 < M) {
                    float2 v; v.x = dacc[mi][ni][2] + b0; v.y = dacc[mi][ni][3] + b1;
                    *reinterpret_cast<float2*>(O + (size_t)(row0 + 8) * 128 + col) = v;
                }
            }
        }
    }
}

// ---------------- fused edge layer: B1e GEMM + gated edge update ----------------
__global__ void __launch_bounds__(256, 2) edge_fused_kernel(
    const int* __restrict__ rows, const int* __restrict__ cols,
    float* __restrict__ e, const float* __restrict__ W, const float* __restrict__ bias,
    const float* __restrict__ A2, const float* __restrict__ A3,
    const float* __restrict__ B2, const float* __restrict__ B3,
    const float* __restrict__ lng, const float* __restrict__ lnb,
    float* __restrict__ acc, int E_)
{
    extern __shared__ float sm[];
    uint32_t* as  = reinterpret_cast<uint32_t*>(sm);
    uint32_t* wsm = reinterpret_cast<uint32_t*>(sm + SM_W);
    const int t = threadIdx.x;
    const int wid = t >> 5, lane = t & 31;
    const int brow = blockIdx.x * 128;

    // stage 1: b1e tile = e_tile @ W + bias  (tf32 MMA)
    load_tile_tf32(e, E_, brow, as, t);
    float dacc[2][8][4];
    gemm_core_256(as, wsm, W, dacc, t);
    __syncthreads();
    float* ebt = sm;                // overwrite A tile with fp32 b1e values
    store_dacc_smem(ebt, dacc, bias, t);
    __syncthreads();

    // stage 2: warp per edge
    float gg[4], gb[4];
    ld4(gg, lng + lane * 4); ld4(gb, lnb + lane * 4);
    const float inv = 1.f / 128.f;

    for (int i = 0; i < 16; i++) {
        const int le = wid * 16 + i;
        const int w = brow + le;
        if (w >= E_) break;
        const int r = rows[w], c = cols[w];
        const size_t eo = (size_t)w * 128 + lane * 4;
        const size_t ro = (size_t)r * 128 + lane * 4;
        const size_t co = (size_t)c * 128 + lane * 4;

        float ev[4], b1[4], b2r[4], b3r[4], a2r[4], b2c[4], b3c[4], a3c[4];
        ld4(b1, ebt + le * AS_STRIDE + lane * 4);
        ld4(ev, e + eo);
        ld4(b2r, B2 + ro); ld4(b3r, B3 + ro); ld4(a2r, A2 + ro);
        ld4(b2c, B2 + co); ld4(b3c, B3 + co); ld4(a3c, A3 + co);

        float gji[4], gik[4];
        float s1 = 0.f, q1 = 0.f, s2 = 0.f, q2 = 0.f;
        #pragma unroll
        for (int j = 0; j < 4; j++) {
            float u = fmaxf(b1[j] + b2r[j] + b3c[j], 0.f);
            float v = fmaxf(b1[j] + b2c[j] + b3r[j], 0.f);
            gji[j] = u; gik[j] = v;
            s1 += u; q1 = fmaf(u, u, q1);
            s2 += v; q2 = fmaf(v, v, q2);
        }
        #pragma unroll
        for (int o = 16; o; o >>= 1) {
            s1 += __shfl_xor_sync(0xffffffffu, s1, o);
            q1 += __shfl_xor_sync(0xffffffffu, q1, o);
            s2 += __shfl_xor_sync(0xffffffffu, s2, o);
            q2 += __shfl_xor_sync(0xffffffffu, q2, o);
        }
        float m1 = s1 * inv, m2 = s2 * inv;
        float is1 = rsqrtf(fmaxf(q1 * inv - m1 * m1, 0.f) + 1e-5f);
        float is2 = rsqrtf(fmaxf(q2 * inv - m2 * m2, 0.f) + 1e-5f);

        float eji[4], sg1[4], sg2[4];
        float t1 = 0.f, t2 = 0.f;
        #pragma unroll
        for (int j = 0; j < 4; j++) {
            eji[j]    = ev[j] + (gji[j] - m1) * is1 * gg[j] + gb[j];
            float eik = ev[j] + (gik[j] - m2) * is2 * gg[j] + gb[j];
            sg1[j] = __fdividef(1.f, 1.f + __expf(-eji[j])); t1 += sg1[j];
            sg2[j] = __fdividef(1.f, 1.f + __expf(-eik));    t2 += sg2[j];
        }
        #pragma unroll
        for (int o = 16; o; o >>= 1) {
            t1 += __shfl_xor_sync(0xffffffffu, t1, o);
            t2 += __shfl_xor_sync(0xffffffffu, t2, o);
        }
        float w1 = __fdividef(1.f, t1 + 1e-6f);
        float w2 = __fdividef(1.f, t2 + 1e-6f);

        float mji[4], mik[4];
        #pragma unroll
        for (int j = 0; j < 4; j++) {
            mji[j] = a2r[j] * sg1[j] * w1;
            mik[j] = a3c[j] * sg2[j] * w2;
        }
        red_add_v4(acc + co, mji);
        red_add_v4(acc + ro, mik);
        st4(e + eo, eji);
    }
}

// ---------------- fused final scorer: ec GEMM + relu-dot ----------------
__global__ void __launch_bounds__(256, 2) final_fused_kernel(
    const int* __restrict__ rows, const int* __restrict__ cols,
    const float* __restrict__ ha, const float* __restrict__ hb,
    const float* __restrict__ e, const float* __restrict__ W,
    const float* __restrict__ s1b, const float* __restrict__ s2w,
    const float* __restrict__ s2b, float* __restrict__ out, int E_)
{
    extern __shared__ float sm[];
    uint32_t* as  = reinterpret_cast<uint32_t*>(sm);
    uint32_t* wsm = reinterpret_cast<uint32_t*>(sm + SM_W);
    const int t = threadIdx.x;
    const int wid = t >> 5, lane = t & 31;
    const int brow = blockIdx.x * 128;

    load_tile_tf32(e, E_, brow, as, t);
    float dacc[2][8][4];
    gemm_core_256(as, wsm, W, dacc, t);
    __syncthreads();
    float* ebt = sm;
    store_dacc_smem(ebt, dacc, nullptr, t);
    __syncthreads();

    float b4[4], wv[4];
    ld4(b4, s1b + lane * 4);
    ld4(wv, s2w + lane * 4);
    const float s2b0 = s2b[0];

    for (int i = 0; i < 16; i++) {
        const int le = wid * 16 + i;
        const int w = brow + le;
        if (w >= E_) break;
        const int r = rows[w], c = cols[w];
        float A[4], B[4], C[4];
        ld4(A, ha + (size_t)r * 128 + lane * 4);
        ld4(B, hb + (size_t)c * 128 + lane * 4);
        ld4(C, ebt + le * AS_STRIDE + lane * 4);
        float p = 0.f;
        #pragma unroll
        for (int j = 0; j < 4; j++) {
            float u = fmaxf(A[j] + B[j] + C[j] + b4[j], 0.f);
            p = fmaf(u, wv[j], p);
        }
        #pragma unroll
        for (int o = 16; o; o >>= 1) p += __shfl_xor_sync(0xffffffffu, p, o);
        if (lane == 0) out[w] = p + s2b0;
    }
}

// ---------------- zero ----------------
__global__ void zero_kernel(float* __restrict__ p, int n) {
    int i = (blockIdx.x * blockDim.x + threadIdx.x) * 4;
    if (i < n) *reinterpret_cast<float4*>(p + i) = make_float4(0.f, 0.f, 0.f, 0.f);
}

// ---------------- embed stage1: out = LN(relu(in @ W + b)) ----------------
__global__ void __launch_bounds__(256) embed_ln_kernel(
    const float* __restrict__ in, const float* __restrict__ W, const float* __restrict__ bias,
    const float* __restrict__ lng, const float* __restrict__ lnb,
    float* __restrict__ out, int M, int Kin)
{
    const int w = blockIdx.x * 8 + (threadIdx.x >> 5);
    const int lane = threadIdx.x & 31;
    if (w >= M) return;
    const float* xr = in + (size_t)w * Kin;
    float x0 = (lane < Kin) ? xr[lane] : 0.f;
    float x1 = (lane + 32 < Kin) ? xr[lane + 32] : 0.f;

    float a[4];
    ld4(a, bias + lane * 4);
    for (int k = 0; k < Kin; k++) {
        float xk = __shfl_sync(0xffffffffu, (k < 32) ? x0 : x1, k & 31);
        float4 wv = *reinterpret_cast<const float4*>(W + k * 128 + lane * 4);
        a[0] = fmaf(xk, wv.x, a[0]);
        a[1] = fmaf(xk, wv.y, a[1]);
        a[2] = fmaf(xk, wv.z, a[2]);
        a[3] = fmaf(xk, wv.w, a[3]);
    }
    float s = 0.f, q = 0.f;
    #pragma unroll
    for (int i = 0; i < 4; i++) {
        a[i] = fmaxf(a[i], 0.f);
        s += a[i]; q = fmaf(a[i], a[i], q);
    }
    #pragma unroll
    for (int o = 16; o; o >>= 1) {
        s += __shfl_xor_sync(0xffffffffu, s, o);
        q += __shfl_xor_sync(0xffffffffu, q, o);
    }
    const float inv = 1.f / 128.f;
    float m = s * inv;
    float is = rsqrtf(fmaxf(q * inv - m * m, 0.f) + 1e-5f);
    float gg[4], gb[4], o4[4];
    ld4(gg, lng + lane * 4); ld4(gb, lnb + lane * 4);
    #pragma unroll
    for (int i = 0; i < 4; i++) o4[i] = (a[i] - m) * is * gg[i] + gb[i];
    st4(out + (size_t)w * 128 + lane * 4, o4);
}

// ---------------- node update: h += LN(relu(A1h + acc)); acc = 0 ----------------
__global__ void __launch_bounds__(256) node_update_kernel(
    const float* __restrict__ A1, float* __restrict__ acc, float* __restrict__ h,
    const float* __restrict__ lng, const float* __restrict__ lnb, int M)
{
    const int w = blockIdx.x * 8 + (threadIdx.x >> 5);
    const int lane = threadIdx.x & 31;
    if (w >= M) return;
    const size_t off = (size_t)w * 128 + lane * 4;
    float a[4], cc[4], t[4];
    ld4(a, A1 + off); ld4(cc, acc + off);
    float s = 0.f, q = 0.f;
    #pragma unroll
    for (int i = 0; i < 4; i++) {
        t[i] = fmaxf(a[i] + cc[i], 0.f);
        s += t[i]; q = fmaf(t[i], t[i], q);
    }
    #pragma unroll
    for (int o = 16; o; o >>= 1) {
        s += __shfl_xor_sync(0xffffffffu, s, o);
        q += __shfl_xor_sync(0xffffffffu, q, o);
    }
    const float inv = 1.f / 128.f;
    float m = s * inv;
    float is = rsqrtf(fmaxf(q * inv - m * m, 0.f) + 1e-5f);
    float gg[4], gb[4], hv[4];
    ld4(gg, lng + lane * 4); ld4(gb, lnb + lane * 4);
    ld4(hv, h + off);
    #pragma unroll
    for (int i = 0; i < 4; i++) hv[i] += (t[i] - m) * is * gg[i] + gb[i];
    st4(h + off, hv);
    float z[4] = {0.f, 0.f, 0.f, 0.f};
    st4(acc + off, z);
}

// ---------------- host ----------------
extern "C" void kernel_launch(void* const* d_in, const int* in_sizes, int n_in,
                              void* d_out, int out_size)
{
    const float* x    = (const float*)d_in[0];
    const float* ea   = (const float*)d_in[1];
    const int*   ei   = (const int*)  d_in[2];
    const float* W11w = (const float*)d_in[3];
    const float* W11b = (const float*)d_in[4];
    const float* W12w = (const float*)d_in[5];
    const float* W12b = (const float*)d_in[6];
    const float* W21w = (const float*)d_in[7];
    const float* W21b = (const float*)d_in[8];
    const float* W22w = (const float*)d_in[9];
    const float* W22b = (const float*)d_in[10];
    const float* ln1g = (const float*)d_in[11];
    const float* ln1b = (const float*)d_in[12];
    const float* ln2g = (const float*)d_in[13];
    const float* ln2b = (const float*)d_in[14];
    const float* Aw   = (const float*)d_in[15];
    const float* Ab   = (const float*)d_in[16];
    const float* Bw   = (const float*)d_in[17];
    const float* Bb   = (const float*)d_in[18];
    const float* lnhg = (const float*)d_in[19];
    const float* lnhb = (const float*)d_in[20];
    const float* lneg = (const float*)d_in[21];
    const float* lneb = (const float*)d_in[22];
    const float* s1w  = (const float*)d_in[23];
    const float* s1b  = (const float*)d_in[24];
    const float* s2w  = (const float*)d_in[25];
    const float* s2b  = (const float*)d_in[26];

    int Nn = in_sizes[0] / 64;
    int Ee = in_sizes[2] / 2;
    if (Nn > CAP_N) Nn = CAP_N;
    if (Ee > CAP_E) Ee = CAP_E;

    float *ph, *pacc, *pA1, *pA2, *pA3, *pB2, *pB3, *pe, *ptmp;
    cudaGetSymbolAddress((void**)&ph,   g_h);
    cudaGetSymbolAddress((void**)&pacc, g_acc);
    cudaGetSymbolAddress((void**)&pA1,  g_A1);
    cudaGetSymbolAddress((void**)&pA2,  g_A2);
    cudaGetSymbolAddress((void**)&pA3,  g_A3);
    cudaGetSymbolAddress((void**)&pB2,  g_B2);
    cudaGetSymbolAddress((void**)&pB3,  g_B3);
    cudaGetSymbolAddress((void**)&pe,   g_e);
    cudaGetSymbolAddress((void**)&ptmp, g_tmp);

    cudaFuncSetAttribute(gemm_mma_kernel,   cudaFuncAttributeMaxDynamicSharedMemorySize, SM_BYTES);
    cudaFuncSetAttribute(edge_fused_kernel, cudaFuncAttributeMaxDynamicSharedMemorySize, SM_BYTES);
    cudaFuncSetAttribute(final_fused_kernel,cudaFuncAttributeMaxDynamicSharedMemorySize, SM_BYTES);

    auto gemm_tc = [&](const float* A, G5& g, int M) {
        int tiles = (M + 127) / 128;
        gemm_mma_kernel<<<tiles, 256, SM_BYTES>>>(A, g, M);
    };
    auto gemm1 = [&](const float* A, const float* W, const float* b, float* o, int M) {
        G5 g; g.nw = 1; g.W[0] = W; g.B[0] = b; g.O[0] = o;
        gemm_tc(A, g, M);
    };

    const int etiles = (Ee + 127) / 128;

    // node embed: h = LN(relu(x@W11+b)) @ W12 + b     (uses acc as temp)
    embed_ln_kernel<<<(Nn + 7) / 8, 256>>>(x, W11w, W11b, ln1g, ln1b, pacc, Nn, 64);
    gemm1(pacc, W12w, W12b, ph, Nn);
    // edge embed: e = LN(relu(ea@W21+b)) @ W22 + b
    embed_ln_kernel<<<(Ee + 7) / 8, 256>>>(ea, W21w, W21b, ln2g, ln2b, ptmp, Ee, 32);
    gemm1(ptmp, W22w, W22b, pe, Ee);

    // zero the scatter accumulator
    zero_kernel<<<(Nn * 128 / 4 + 255) / 256, 256>>>(pacc, Nn * 128);

    for (int l = 0; l < 3; l++) {
        const float* Awl = Aw + (size_t)l * 3 * 128 * 128;
        const float* Abl = Ab + (size_t)l * 3 * 128;
        const float* Bwl = Bw + (size_t)l * 3 * 128 * 128;
        const float* Bbl = Bb + (size_t)l * 3 * 128;
        {
            G5 g; g.nw = 5;
            g.W[0] = Awl;          g.B[0] = Abl;        g.O[0] = pA1;
            g.W[1] = Awl + 16384;  g.B[1] = Abl + 128;  g.O[1] = pA2;
            g.W[2] = Awl + 32768;  g.B[2] = Abl + 256;  g.O[2] = pA3;
            g.W[3] = Bwl + 16384;  g.B[3] = Bbl + 128;  g.O[3] = pB2;
            g.W[4] = Bwl + 32768;  g.B[4] = Bbl + 256;  g.O[4] = pB3;
            gemm_tc(ph, g, Nn);
        }
        edge_fused_kernel<<<etiles, 256, SM_BYTES>>>(
            ei, ei + Ee, pe, Bwl, Bbl, pA2, pA3, pB2, pB3,
            lneg + l * 128, lneb + l * 128, pacc, Ee);
        node_update_kernel<<<(Nn + 7) / 8, 256>>>(pA1, pacc, ph,
                                                  lnhg + l * 128, lnhb + l * 128, Nn);
    }

    // final scorer: score = relu(h[row]@Sa + h[col]@Sb + e@Sc + s1b) @ s2w + s2b
    {
        G5 g; g.nw = 2;
        g.W[0] = s1w;          g.B[0] = nullptr; g.O[0] = pA1;
        g.W[1] = s1w + 16384;  g.B[1] = nullptr; g.O[1] = pA2;
        gemm_tc(ph, g, Nn);
    }
    final_fused_kernel<<<etiles, 256, SM_BYTES>>>(
        ei, ei + Ee, pA1, pA2, pe, s1w + 32768, s1b, s2w, s2b, (float*)d_out, Ee);
}

// round 10
// speedup vs baseline: 2.2097x; 1.0512x over previous
#include <cuda_runtime.h>
#include <cstdint>

#define H128 128
static const int CAP_N = 50000;
static const int CAP_E = 800000;

// ---------------- scratch (device globals; no allocation allowed) ----------------
__device__ float g_h  [CAP_N * H128];
__device__ float g_acc[CAP_N * H128];
__device__ float g_A1 [CAP_N * H128];
__device__ float g_A2 [CAP_N * H128];
__device__ float g_A3 [CAP_N * H128];
__device__ float g_B2 [CAP_N * H128];
__device__ float g_B3 [CAP_N * H128];
__device__ float g_e  [CAP_E * H128];
__device__ float g_tmp[CAP_E * H128];

// ---------------- L2 residency policies (createpolicy + cache_hint: any width) ----
__device__ __forceinline__ uint64_t pol_ef() {
    uint64_t p;
    asm("createpolicy.fractional.L2::evict_first.b64 %0, 1.0;" : "=l"(p));
    return p;
}
__device__ __forceinline__ uint64_t pol_el() {
    uint64_t p;
    asm("createpolicy.fractional.L2::evict_last.b64 %0, 1.0;" : "=l"(p));
    return p;
}

// ---------------- generic helpers ----------------
__device__ __forceinline__ void red_add_v4(float* p, const float* v) {
    asm volatile("red.global.add.v4.f32 [%0], {%1, %2, %3, %4};"
                 :: "l"(p), "f"(v[0]), "f"(v[1]), "f"(v[2]), "f"(v[3]) : "memory");
}
__device__ __forceinline__ void ld4(float* d, const float* p) {
    float4 v = *reinterpret_cast<const float4*>(p);
    d[0] = v.x; d[1] = v.y; d[2] = v.z; d[3] = v.w;
}
__device__ __forceinline__ void ld4_h(float* d, const float* p, uint64_t pol) {
    asm volatile("ld.global.L2::cache_hint.v4.f32 {%0,%1,%2,%3}, [%4], %5;"
                 : "=f"(d[0]), "=f"(d[1]), "=f"(d[2]), "=f"(d[3]) : "l"(p), "l"(pol));
}
__device__ __forceinline__ void st4(float* p, const float* d) {
    float4 v; v.x = d[0]; v.y = d[1]; v.z = d[2]; v.w = d[3];
    *reinterpret_cast<float4*>(p) = v;
}
__device__ __forceinline__ void st4_h(float* p, const float* d, uint64_t pol) {
    asm volatile("st.global.L2::cache_hint.v4.f32 [%0], {%1,%2,%3,%4}, %5;"
                 :: "l"(p), "f"(d[0]), "f"(d[1]), "f"(d[2]), "f"(d[3]), "l"(pol) : "memory");
}
__device__ __forceinline__ void st2_h(float* p, float a, float b, int hint) {
    if (hint == 2) {
        uint64_t pol = pol_el();
        asm volatile("st.global.L2::cache_hint.v2.f32 [%0], {%1,%2}, %3;"
                     :: "l"(p), "f"(a), "f"(b), "l"(pol) : "memory");
    } else if (hint == 1) {
        uint64_t pol = pol_ef();
        asm volatile("st.global.L2::cache_hint.v2.f32 [%0], {%1,%2}, %3;"
                     :: "l"(p), "f"(a), "f"(b), "l"(pol) : "memory");
    } else {
        float2 v; v.x = a; v.y = b;
        *reinterpret_cast<float2*>(p) = v;
    }
}
__device__ __forceinline__ uint32_t to_tf32(float x) {
    uint32_t r;
    asm("cvt.rna.tf32.f32 %0, %1;" : "=r"(r) : "f"(x));
    return r;
}
// mma.sync m16n8k8 tf32 (row.col), fp32 accumulate — portable PTX, works on compute_103
__device__ __forceinline__ void mma_tf32(float d[4], const uint32_t a[4], const uint32_t b[2],
                                         const float c[4]) {
    asm volatile(
        "mma.sync.aligned.m16n8k8.row.col.f32.tf32.tf32.f32 "
        "{%0,%1,%2,%3}, {%4,%5,%6,%7}, {%8,%9}, {%10,%11,%12,%13};"
        : "=f"(d[0]), "=f"(d[1]), "=f"(d[2]), "=f"(d[3])
        : "r"(a[0]), "r"(a[1]), "r"(a[2]), "r"(a[3]),
          "r"(b[0]), "r"(b[1]),
          "f"(c[0]), "f"(c[1]), "f"(c[2]), "f"(c[3]));
}

// ---------------- shared GEMM tile machinery (256 threads, 128x128 tile) ----------------
static const int AS_STRIDE = 132;
static const int WS_STRIDE = 136;
static const int SM_W = 128 * AS_STRIDE;
static const int SM_FLOATS = SM_W + 64 * WS_STRIDE;
static const int SM_BYTES = SM_FLOATS * 4;          // 102016 B -> 2 CTAs/SM

// load A[brow..brow+127][0..127] -> smem tf32 (zero-padded past M)
__device__ __forceinline__ void load_tile_tf32(const float* __restrict__ A, int M, int brow,
                                               uint32_t* as, int t, int ef) {
    const float4* A4 = reinterpret_cast<const float4*>(A);
    uint64_t pol = ef ? pol_ef() : 0;
    #pragma unroll
    for (int j = 0; j < 16; j++) {
        int flat = j * 256 + t;
        int row = flat >> 5, k4 = flat & 31;
        int gr = brow + row;
        float v[4] = {0.f, 0.f, 0.f, 0.f};
        if (gr < M) {
            const float* p = reinterpret_cast<const float*>(A4 + (size_t)gr * 32 + k4);
            if (ef) ld4_h(v, p, pol); else ld4(v, p);
        }
        uint4 u; u.x = to_tf32(v[0]); u.y = to_tf32(v[1]); u.z = to_tf32(v[2]); u.w = to_tf32(v[3]);
        *reinterpret_cast<uint4*>(as + row * AS_STRIDE + k4 * 4) = u;
    }
}

// compute dacc = Atile @ W ; warp tile 32x64: wm=wid&3 (m), wn=wid>>2 (n)
__device__ __forceinline__ void gemm_core_256(const uint32_t* as, uint32_t* wsm,
                                              const float* __restrict__ W,
                                              float dacc[2][8][4], int t) {
    const int wid = t >> 5, lane = t & 31;
    const int gid = lane >> 2, tig = lane & 3;
    const int m0 = (wid & 3) * 32, n0 = (wid >> 2) * 64;

    #pragma unroll
    for (int mi = 0; mi < 2; mi++)
        #pragma unroll
        for (int ni = 0; ni < 8; ni++)
            #pragma unroll
            for (int q = 0; q < 4; q++) dacc[mi][ni][q] = 0.f;

    #pragma unroll 1
    for (int ch = 0; ch < 2; ch++) {
        __syncthreads();
        {
            const float4* W4 = reinterpret_cast<const float4*>(W);
            #pragma unroll
            for (int j = 0; j < 8; j++) {
                int flat = j * 256 + t;
                int k = flat >> 5, c4 = flat & 31;
                float4 v = W4[(size_t)(ch * 64 + k) * 32 + c4];
                uint4 u; u.x = to_tf32(v.x); u.y = to_tf32(v.y);
                u.z = to_tf32(v.z); u.w = to_tf32(v.w);
                *reinterpret_cast<uint4*>(wsm + k * WS_STRIDE + c4 * 4) = u;
            }
        }
        __syncthreads();

        #pragma unroll
        for (int ks = 0; ks < 8; ks++) {
            const int k0 = ks * 8;
            uint32_t af[2][4];
            #pragma unroll
            for (int mi = 0; mi < 2; mi++) {
                const uint32_t* pa = as + (m0 + mi * 16 + gid) * AS_STRIDE + ch * 64 + k0;
                af[mi][0] = pa[tig];
                af[mi][1] = pa[8 * AS_STRIDE + tig];
                af[mi][2] = pa[tig + 4];
                af[mi][3] = pa[8 * AS_STRIDE + tig + 4];
            }
            uint32_t bf[8][2];
            #pragma unroll
            for (int ni = 0; ni < 8; ni++) {
                const uint32_t* pb = wsm + (k0 + tig) * WS_STRIDE + n0 + ni * 8 + gid;
                bf[ni][0] = pb[0];
                bf[ni][1] = pb[4 * WS_STRIDE];
            }
            #pragma unroll
            for (int mi = 0; mi < 2; mi++)
                #pragma unroll
                for (int ni = 0; ni < 8; ni++)
                    mma_tf32(dacc[mi][ni], af[mi], bf[ni], dacc[mi][ni]);
        }
    }
}

// store dacc (+bias) into smem tile ebt[128][AS_STRIDE]
__device__ __forceinline__ void store_dacc_smem(float* ebt, float dacc[2][8][4],
                                                const float* __restrict__ bias, int t) {
    const int wid = t >> 5, lane = t & 31;
    const int gid = lane >> 2, tig = lane & 3;
    const int m0 = (wid & 3) * 32, n0 = (wid >> 2) * 64;
    #pragma unroll
    for (int ni = 0; ni < 8; ni++) {
        const int col = n0 + ni * 8 + 2 * tig;
        float b0 = 0.f, b1 = 0.f;
        if (bias) { b0 = bias[col]; b1 = bias[col + 1]; }
        #pragma unroll
        for (int mi = 0; mi < 2; mi++) {
            const int row = m0 + mi * 16 + gid;
            float2 v0; v0.x = dacc[mi][ni][0] + b0; v0.y = dacc[mi][ni][1] + b1;
            float2 v1; v1.x = dacc[mi][ni][2] + b0; v1.y = dacc[mi][ni][3] + b1;
            *reinterpret_cast<float2*>(ebt + row * AS_STRIDE + col) = v0;
            *reinterpret_cast<float2*>(ebt + (row + 8) * AS_STRIDE + col) = v1;
        }
    }
}

// ---------------- standalone multi-weight GEMM ----------------
struct G5 {
    const float* W[5];
    const float* B[5];
    float*       O[5];
    int OH[5];   // per-output L2 hint: 0 none, 1 evict_first, 2 evict_last
    int nw;
    int IH;      // input tile hint: 0 none, 1 evict_first
};

__global__ void __launch_bounds__(256, 2) gemm_mma_kernel(
    const float* __restrict__ A, G5 g, int M)
{
    extern __shared__ float sm[];
    uint32_t* as  = reinterpret_cast<uint32_t*>(sm);
    uint32_t* wsm = reinterpret_cast<uint32_t*>(sm + SM_W);
    const int t = threadIdx.x;
    const int wid = t >> 5, lane = t & 31;
    const int gid = lane >> 2, tig = lane & 3;
    const int m0 = (wid & 3) * 32, n0 = (wid >> 2) * 64;
    const int brow = blockIdx.x * 128;

    load_tile_tf32(A, M, brow, as, t, g.IH);

    for (int w = 0; w < g.nw; w++) {
        float dacc[2][8][4];
        gemm_core_256(as, wsm, g.W[w], dacc, t);

        float* O = g.O[w];
        const float* bias = g.B[w];
        const int oh = g.OH[w];
        #pragma unroll
        for (int ni = 0; ni < 8; ni++) {
            const int col = n0 + ni * 8 + 2 * tig;
            float b0 = 0.f, b1 = 0.f;
            if (bias) { b0 = bias[col]; b1 = bias[col + 1]; }
            #pragma unroll
            for (int mi = 0; mi < 2; mi++) {
                const int row0 = brow + m0 + mi * 16 + gid;
                if (row0 < M)
                    st2_h(O + (size_t)row0 * 128 + col, dacc[mi][ni][0] + b0, dacc[mi][ni][1] + b1, oh);
                if (row0 + 8 < M)
                    st2_h(O + (size_t)(row0 + 8) * 128 + col, dacc[mi][ni][2] + b0, dacc[mi][ni][3] + b1, oh);
            }
        }
    }
}

// ---------------- fused edge layer: B1e GEMM + gated edge update ----------------
__global__ void __launch_bounds__(256, 2) edge_fused_kernel(
    const int* __restrict__ rows, const int* __restrict__ cols,
    float* __restrict__ e, const float* __restrict__ W, const float* __restrict__ bias,
    const float* __restrict__ A2, const float* __restrict__ A3,
    const float* __restrict__ B2, const float* __restrict__ B3,
    const float* __restrict__ lng, const float* __restrict__ lnb,
    float* __restrict__ acc, int E_)
{
    extern __shared__ float sm[];
    uint32_t* as  = reinterpret_cast<uint32_t*>(sm);
    uint32_t* wsm = reinterpret_cast<uint32_t*>(sm + SM_W);
    const int t = threadIdx.x;
    const int wid = t >> 5, lane = t & 31;
    const int brow = blockIdx.x * 128;

    // stage 1: b1e tile = e_tile @ W + bias  (tf32 MMA)
    load_tile_tf32(e, E_, brow, as, t, 1);
    float dacc[2][8][4];
    gemm_core_256(as, wsm, W, dacc, t);
    __syncthreads();
    float* ebt = sm;                // overwrite A tile with fp32 b1e values
    store_dacc_smem(ebt, dacc, bias, t);
    __syncthreads();

    // stage 2: warp per edge (16 edges per warp), batched index load
    int idx;
    {
        int epos = brow + wid * 16 + (lane & 15);
        if (epos >= E_) epos = E_ - 1;
        const int* bp = (lane < 16) ? rows : cols;
        idx = bp[epos];
    }

    const uint64_t pef = pol_ef();
    const uint64_t pel = pol_el();
    float gg[4], gb[4];
    ld4(gg, lng + lane * 4); ld4(gb, lnb + lane * 4);
    const float inv = 1.f / 128.f;

    for (int i = 0; i < 16; i++) {
        const int le = wid * 16 + i;
        const int w = brow + le;
        if (w >= E_) break;
        const int r = __shfl_sync(0xffffffffu, idx, i);
        const int c = __shfl_sync(0xffffffffu, idx, 16 + i);
        const size_t eo = (size_t)w * 128 + lane * 4;
        const size_t ro = (size_t)r * 128 + lane * 4;
        const size_t co = (size_t)c * 128 + lane * 4;

        float ev[4], b1[4], b2r[4], b3r[4], a2r[4], b2c[4], b3c[4], a3c[4];
        ld4(b1, ebt + le * AS_STRIDE + lane * 4);
        ld4_h(ev, e + eo, pef);
        ld4_h(b2r, B2 + ro, pel); ld4_h(b3r, B3 + ro, pel); ld4_h(a2r, A2 + ro, pel);
        ld4_h(b2c, B2 + co, pel); ld4_h(b3c, B3 + co, pel); ld4_h(a3c, A3 + co, pel);

        float gji[4], gik[4];
        float s1 = 0.f, q1 = 0.f, s2 = 0.f, q2 = 0.f;
        #pragma unroll
        for (int j = 0; j < 4; j++) {
            float u = fmaxf(b1[j] + b2r[j] + b3c[j], 0.f);
            float v = fmaxf(b1[j] + b2c[j] + b3r[j], 0.f);
            gji[j] = u; gik[j] = v;
            s1 += u; q1 = fmaf(u, u, q1);
            s2 += v; q2 = fmaf(v, v, q2);
        }
        #pragma unroll
        for (int o = 16; o; o >>= 1) {
            s1 += __shfl_xor_sync(0xffffffffu, s1, o);
            q1 += __shfl_xor_sync(0xffffffffu, q1, o);
            s2 += __shfl_xor_sync(0xffffffffu, s2, o);
            q2 += __shfl_xor_sync(0xffffffffu, q2, o);
        }
        float m1 = s1 * inv, m2 = s2 * inv;
        float is1 = rsqrtf(fmaxf(q1 * inv - m1 * m1, 0.f) + 1e-5f);
        float is2 = rsqrtf(fmaxf(q2 * inv - m2 * m2, 0.f) + 1e-5f);

        float eji[4], sg1[4], sg2[4];
        float t1 = 0.f, t2 = 0.f;
        #pragma unroll
        for (int j = 0; j < 4; j++) {
            eji[j]    = ev[j] + (gji[j] - m1) * is1 * gg[j] + gb[j];
            float eik = ev[j] + (gik[j] - m2) * is2 * gg[j] + gb[j];
            sg1[j] = __fdividef(1.f, 1.f + __expf(-eji[j])); t1 += sg1[j];
            sg2[j] = __fdividef(1.f, 1.f + __expf(-eik));    t2 += sg2[j];
        }
        #pragma unroll
        for (int o = 16; o; o >>= 1) {
            t1 += __shfl_xor_sync(0xffffffffu, t1, o);
            t2 += __shfl_xor_sync(0xffffffffu, t2, o);
        }
        float w1 = __fdividef(1.f, t1 + 1e-6f);
        float w2 = __fdividef(1.f, t2 + 1e-6f);

        float mji[4], mik[4];
        #pragma unroll
        for (int j = 0; j < 4; j++) {
            mji[j] = a2r[j] * sg1[j] * w1;
            mik[j] = a3c[j] * sg2[j] * w2;
        }
        red_add_v4(acc + co, mji);
        red_add_v4(acc + ro, mik);
        st4_h(e + eo, eji, pef);
    }
}

// ---------------- fused final scorer: ec GEMM + relu-dot ----------------
__global__ void __launch_bounds__(256, 2) final_fused_kernel(
    const int* __restrict__ rows, const int* __restrict__ cols,
    const float* __restrict__ ha, const float* __restrict__ hb,
    const float* __restrict__ e, const float* __restrict__ W,
    const float* __restrict__ s1b, const float* __restrict__ s2w,
    const float* __restrict__ s2b, float* __restrict__ out, int E_)
{
    extern __shared__ float sm[];
    uint32_t* as  = reinterpret_cast<uint32_t*>(sm);
    uint32_t* wsm = reinterpret_cast<uint32_t*>(sm + SM_W);
    const int t = threadIdx.x;
    const int wid = t >> 5, lane = t & 31;
    const int brow = blockIdx.x * 128;

    load_tile_tf32(e, E_, brow, as, t, 1);
    float dacc[2][8][4];
    gemm_core_256(as, wsm, W, dacc, t);
    __syncthreads();
    float* ebt = sm;
    store_dacc_smem(ebt, dacc, nullptr, t);
    __syncthreads();

    int idx;
    {
        int epos = brow + wid * 16 + (lane & 15);
        if (epos >= E_) epos = E_ - 1;
        const int* bp = (lane < 16) ? rows : cols;
        idx = bp[epos];
    }

    const uint64_t pel = pol_el();
    float b4[4], wv[4];
    ld4(b4, s1b + lane * 4);
    ld4(wv, s2w + lane * 4);
    const float s2b0 = s2b[0];

    for (int i = 0; i < 16; i++) {
        const int le = wid * 16 + i;
        const int w = brow + le;
        if (w >= E_) break;
        const int r = __shfl_sync(0xffffffffu, idx, i);
        const int c = __shfl_sync(0xffffffffu, idx, 16 + i);
        float A[4], B[4], C[4];
        ld4_h(A, ha + (size_t)r * 128 + lane * 4, pel);
        ld4_h(B, hb + (size_t)c * 128 + lane * 4, pel);
        ld4(C, ebt + le * AS_STRIDE + lane * 4);
        float p = 0.f;
        #pragma unroll
        for (int j = 0; j < 4; j++) {
            float u = fmaxf(A[j] + B[j] + C[j] + b4[j], 0.f);
            p = fmaf(u, wv[j], p);
        }
        #pragma unroll
        for (int o = 16; o; o >>= 1) p += __shfl_xor_sync(0xffffffffu, p, o);
        if (lane == 0) out[w] = p + s2b0;
    }
}

// ---------------- zero ----------------
__global__ void zero_kernel(float* __restrict__ p, int n) {
    int i = (blockIdx.x * blockDim.x + threadIdx.x) * 4;
    if (i < n) *reinterpret_cast<float4*>(p + i) = make_float4(0.f, 0.f, 0.f, 0.f);
}

// ---------------- embed stage1: out = LN(relu(in @ W + b)) ----------------
__global__ void __launch_bounds__(256) embed_ln_kernel(
    const float* __restrict__ in, const float* __restrict__ W, const float* __restrict__ bias,
    const float* __restrict__ lng, const float* __restrict__ lnb,
    float* __restrict__ out, int M, int Kin)
{
    const int w = blockIdx.x * 8 + (threadIdx.x >> 5);
    const int lane = threadIdx.x & 31;
    if (w >= M) return;
    const float* xr = in + (size_t)w * Kin;
    float x0 = (lane < Kin) ? xr[lane] : 0.f;
    float x1 = (lane + 32 < Kin) ? xr[lane + 32] : 0.f;

    float a[4];
    ld4(a, bias + lane * 4);
    for (int k = 0; k < Kin; k++) {
        float xk = __shfl_sync(0xffffffffu, (k < 32) ? x0 : x1, k & 31);
        float4 wv = *reinterpret_cast<const float4*>(W + k * 128 + lane * 4);
        a[0] = fmaf(xk, wv.x, a[0]);
        a[1] = fmaf(xk, wv.y, a[1]);
        a[2] = fmaf(xk, wv.z, a[2]);
        a[3] = fmaf(xk, wv.w, a[3]);
    }
    float s = 0.f, q = 0.f;
    #pragma unroll
    for (int i = 0; i < 4; i++) {
        a[i] = fmaxf(a[i], 0.f);
        s += a[i]; q = fmaf(a[i], a[i], q);
    }
    #pragma unroll
    for (int o = 16; o; o >>= 1) {
        s += __shfl_xor_sync(0xffffffffu, s, o);
        q += __shfl_xor_sync(0xffffffffu, q, o);
    }
    const float inv = 1.f / 128.f;
    float m = s * inv;
    float is = rsqrtf(fmaxf(q * inv - m * m, 0.f) + 1e-5f);
    float gg[4], gb[4], o4[4];
    ld4(gg, lng + lane * 4); ld4(gb, lnb + lane * 4);
    #pragma unroll
    for (int i = 0; i < 4; i++) o4[i] = (a[i] - m) * is * gg[i] + gb[i];
    uint64_t pef = pol_ef();
    st4_h(out + (size_t)w * 128 + lane * 4, o4, pef);
}

// ---------------- node update: h += LN(relu(A1h + acc)); acc = 0 ----------------
__global__ void __launch_bounds__(256) node_update_kernel(
    const float* __restrict__ A1, float* __restrict__ acc, float* __restrict__ h,
    const float* __restrict__ lng, const float* __restrict__ lnb, int M)
{
    const int w = blockIdx.x * 8 + (threadIdx.x >> 5);
    const int lane = threadIdx.x & 31;
    if (w >= M) return;
    const size_t off = (size_t)w * 128 + lane * 4;
    float a[4], cc[4], t[4];
    ld4(a, A1 + off); ld4(cc, acc + off);
    float s = 0.f, q = 0.f;
    #pragma unroll
    for (int i = 0; i < 4; i++) {
        t[i] = fmaxf(a[i] + cc[i], 0.f);
        s += t[i]; q = fmaf(t[i], t[i], q);
    }
    #pragma unroll
    for (int o = 16; o; o >>= 1) {
        s += __shfl_xor_sync(0xffffffffu, s, o);
        q += __shfl_xor_sync(0xffffffffu, q, o);
    }
    const float inv = 1.f / 128.f;
    float m = s * inv;
    float is = rsqrtf(fmaxf(q * inv - m * m, 0.f) + 1e-5f);
    float gg[4], gb[4], hv[4];
    ld4(gg, lng + lane * 4); ld4(gb, lnb + lane * 4);
    ld4(hv, h + off);
    #pragma unroll
    for (int i = 0; i < 4; i++) hv[i] += (t[i] - m) * is * gg[i] + gb[i];
    st4(h + off, hv);
    float z[4] = {0.f, 0.f, 0.f, 0.f};
    st4(acc + off, z);
}

// ---------------- host ----------------
extern "C" void kernel_launch(void* const* d_in, const int* in_sizes, int n_in,
                              void* d_out, int out_size)
{
    const float* x    = (const float*)d_in[0];
    const float* ea   = (const float*)d_in[1];
    const int*   ei   = (const int*)  d_in[2];
    const float* W11w = (const float*)d_in[3];
    const float* W11b = (const float*)d_in[4];
    const float* W12w = (const float*)d_in[5];
    const float* W12b = (const float*)d_in[6];
    const float* W21w = (const float*)d_in[7];
    const float* W21b = (const float*)d_in[8];
    const float* W22w = (const float*)d_in[9];
    const float* W22b = (const float*)d_in[10];
    const float* ln1g = (const float*)d_in[11];
    const float* ln1b = (const float*)d_in[12];
    const float* ln2g = (const float*)d_in[13];
    const float* ln2b = (const float*)d_in[14];
    const float* Aw   = (const float*)d_in[15];
    const float* Ab   = (const float*)d_in[16];
    const float* Bw   = (const float*)d_in[17];
    const float* Bb   = (const float*)d_in[18];
    const float* lnhg = (const float*)d_in[19];
    const float* lnhb = (const float*)d_in[20];
    const float* lneg = (const float*)d_in[21];
    const float* lneb = (const float*)d_in[22];
    const float* s1w  = (const float*)d_in[23];
    const float* s1b  = (const float*)d_in[24];
    const float* s2w  = (const float*)d_in[25];
    const float* s2b  = (const float*)d_in[26];

    int Nn = in_sizes[0] / 64;
    int Ee = in_sizes[2] / 2;
    if (Nn > CAP_N) Nn = CAP_N;
    if (Ee > CAP_E) Ee = CAP_E;

    float *ph, *pacc, *pA1, *pA2, *pA3, *pB2, *pB3, *pe, *ptmp;
    cudaGetSymbolAddress((void**)&ph,   g_h);
    cudaGetSymbolAddress((void**)&pacc, g_acc);
    cudaGetSymbolAddress((void**)&pA1,  g_A1);
    cudaGetSymbolAddress((void**)&pA2,  g_A2);
    cudaGetSymbolAddress((void**)&pA3,  g_A3);
    cudaGetSymbolAddress((void**)&pB2,  g_B2);
    cudaGetSymbolAddress((void**)&pB3,  g_B3);
    cudaGetSymbolAddress((void**)&pe,   g_e);
    cudaGetSymbolAddress((void**)&ptmp, g_tmp);

    cudaFuncSetAttribute(gemm_mma_kernel,   cudaFuncAttributeMaxDynamicSharedMemorySize, SM_BYTES);
    cudaFuncSetAttribute(edge_fused_kernel, cudaFuncAttributeMaxDynamicSharedMemorySize, SM_BYTES);
    cudaFuncSetAttribute(final_fused_kernel,cudaFuncAttributeMaxDynamicSharedMemorySize, SM_BYTES);

    auto gemm_tc = [&](const float* A, G5& g, int M) {
        int tiles = (M + 127) / 128;
        gemm_mma_kernel<<<tiles, 256, SM_BYTES>>>(A, g, M);
    };
    auto gemm1 = [&](const float* A, const float* W, const float* b, float* o, int M,
                     int ih, int oh) {
        G5 g; g.nw = 1; g.W[0] = W; g.B[0] = b; g.O[0] = o; g.OH[0] = oh; g.IH = ih;
        gemm_tc(A, g, M);
    };

    const int etiles = (Ee + 127) / 128;

    // node embed: h = LN(relu(x@W11+b)) @ W12 + b     (uses acc as temp)
    embed_ln_kernel<<<(Nn + 7) / 8, 256>>>(x, W11w, W11b, ln1g, ln1b, pacc, Nn, 64);
    gemm1(pacc, W12w, W12b, ph, Nn, 0, 0);
    // edge embed: e = LN(relu(ea@W21+b)) @ W22 + b
    embed_ln_kernel<<<(Ee + 7) / 8, 256>>>(ea, W21w, W21b, ln2g, ln2b, ptmp, Ee, 32);
    gemm1(ptmp, W22w, W22b, pe, Ee, 1, 1);

    // zero the scatter accumulator
    zero_kernel<<<(Nn * 128 / 4 + 255) / 256, 256>>>(pacc, Nn * 128);

    for (int l = 0; l < 3; l++) {
        const float* Awl = Aw + (size_t)l * 3 * 128 * 128;
        const float* Abl = Ab + (size_t)l * 3 * 128;
        const float* Bwl = Bw + (size_t)l * 3 * 128 * 128;
        const float* Bbl = Bb + (size_t)l * 3 * 128;
        {
            G5 g; g.nw = 5; g.IH = 0;
            g.W[0] = Awl;          g.B[0] = Abl;        g.O[0] = pA1; g.OH[0] = 0;
            g.W[1] = Awl + 16384;  g.B[1] = Abl + 128;  g.O[1] = pA2; g.OH[1] = 2;
            g.W[2] = Awl + 32768;  g.B[2] = Abl + 256;  g.O[2] = pA3; g.OH[2] = 2;
            g.W[3] = Bwl + 16384;  g.B[3] = Bbl + 128;  g.O[3] = pB2; g.OH[3] = 2;
            g.W[4] = Bwl + 32768;  g.B[4] = Bbl + 256;  g.O[4] = pB3; g.OH[4] = 2;
            gemm_tc(ph, g, Nn);
        }
        edge_fused_kernel<<<etiles, 256, SM_BYTES>>>(
            ei, ei + Ee, pe, Bwl, Bbl, pA2, pA3, pB2, pB3,
            lneg + l * 128, lneb + l * 128, pacc, Ee);
        node_update_kernel<<<(Nn + 7) / 8, 256>>>(pA1, pacc, ph,
                                                  lnhg + l * 128, lnhb + l * 128, Nn);
    }

    // final scorer: score = relu(h[row]@Sa + h[col]@Sb + e@Sc + s1b) @ s2w + s2b
    {
        G5 g; g.nw = 2; g.IH = 0;
        g.W[0] = s1w;          g.B[0] = nullptr; g.O[0] = pA1; g.OH[0] = 2;
        g.W[1] = s1w + 16384;  g.B[1] = nullptr; g.O[1] = pA2; g.OH[1] = 2;
        gemm_tc(ph, g, Nn);
    }
    final_fused_kernel<<<etiles, 256, SM_BYTES>>>(
        ei, ei + Ee, pA1, pA2, pe, s1w + 32768, s1b, s2w, s2b, (float*)d_out, Ee);
}

// round 12
// speedup vs baseline: 2.2748x; 1.0294x over previous
#include <cuda_runtime.h>
#include <cstdint>

#define H128 128
static const int CAP_N = 50000;
static const int CAP_E = 800000;

// ---------------- scratch (device globals; no allocation allowed) ----------------
__device__ float g_h  [CAP_N * H128];
__device__ float g_acc[CAP_N * H128];
__device__ float g_A1 [CAP_N * H128];
__device__ float g_A2 [CAP_N * H128];
__device__ float g_A3 [CAP_N * H128];
__device__ float g_B2 [CAP_N * H128];
__device__ float g_B3 [CAP_N * H128];
__device__ float g_e  [CAP_E * H128];
__device__ float g_tmp[CAP_E * H128];

// ---------------- L2 residency policies ----------------
__device__ __forceinline__ uint64_t pol_ef() {
    uint64_t p;
    asm("createpolicy.fractional.L2::evict_first.b64 %0, 1.0;" : "=l"(p));
    return p;
}
__device__ __forceinline__ uint64_t pol_el() {
    uint64_t p;
    asm("createpolicy.fractional.L2::evict_last.b64 %0, 1.0;" : "=l"(p));
    return p;
}

// ---------------- generic helpers ----------------
__device__ __forceinline__ uint32_t smem_u32(const void* p) {
    uint32_t a;
    asm("{ .reg .u64 t; cvta.to.shared.u64 t, %1; cvt.u32.u64 %0, t; }" : "=r"(a) : "l"(p));
    return a;
}
__device__ __forceinline__ void red_add_v4(float* p, const float* v) {
    asm volatile("red.global.add.v4.f32 [%0], {%1, %2, %3, %4};"
                 :: "l"(p), "f"(v[0]), "f"(v[1]), "f"(v[2]), "f"(v[3]) : "memory");
}
__device__ __forceinline__ void ld4(float* d, const float* p) {
    float4 v = *reinterpret_cast<const float4*>(p);
    d[0] = v.x; d[1] = v.y; d[2] = v.z; d[3] = v.w;
}
__device__ __forceinline__ void ld4_h(float* d, const float* p, uint64_t pol) {
    asm volatile("ld.global.L2::cache_hint.v4.f32 {%0,%1,%2,%3}, [%4], %5;"
                 : "=f"(d[0]), "=f"(d[1]), "=f"(d[2]), "=f"(d[3]) : "l"(p), "l"(pol));
}
__device__ __forceinline__ void lds4(float* d, uint32_t a) {
    asm volatile("ld.shared.v4.f32 {%0,%1,%2,%3}, [%4];"
                 : "=f"(d[0]), "=f"(d[1]), "=f"(d[2]), "=f"(d[3]) : "r"(a));
}
__device__ __forceinline__ void st4(float* p, const float* d) {
    float4 v; v.x = d[0]; v.y = d[1]; v.z = d[2]; v.w = d[3];
    *reinterpret_cast<float4*>(p) = v;
}
__device__ __forceinline__ void st4_h(float* p, const float* d, uint64_t pol) {
    asm volatile("st.global.L2::cache_hint.v4.f32 [%0], {%1,%2,%3,%4}, %5;"
                 :: "l"(p), "f"(d[0]), "f"(d[1]), "f"(d[2]), "f"(d[3]), "l"(pol) : "memory");
}
__device__ __forceinline__ void st2_h(float* p, float a, float b, int hint) {
    if (hint == 2) {
        uint64_t pol = pol_el();
        asm volatile("st.global.L2::cache_hint.v2.f32 [%0], {%1,%2}, %3;"
                     :: "l"(p), "f"(a), "f"(b), "l"(pol) : "memory");
    } else if (hint == 1) {
        uint64_t pol = pol_ef();
        asm volatile("st.global.L2::cache_hint.v2.f32 [%0], {%1,%2}, %3;"
                     :: "l"(p), "f"(a), "f"(b), "l"(pol) : "memory");
    } else {
        float2 v; v.x = a; v.y = b;
        *reinterpret_cast<float2*>(p) = v;
    }
}
// 16B async copy gmem->smem (plain form: cache_hint on LDGSTS traps on sm_103)
__device__ __forceinline__ void cpa16(uint32_t dst, const float* src) {
    asm volatile("cp.async.ca.shared.global [%0], [%1], 16;"
                 :: "r"(dst), "l"(src) : "memory");
}
__device__ __forceinline__ void cpa_commit() {
    asm volatile("cp.async.commit_group;" ::: "memory");
}
__device__ __forceinline__ void cpa_wait1() {
    asm volatile("cp.async.wait_group 1;" ::: "memory");
}
__device__ __forceinline__ uint32_t to_tf32(float x) {
    uint32_t r;
    asm("cvt.rna.tf32.f32 %0, %1;" : "=r"(r) : "f"(x));
    return r;
}
__device__ __forceinline__ void mma_tf32(float d[4], const uint32_t a[4], const uint32_t b[2],
                                         const float c[4]) {
    asm volatile(
        "mma.sync.aligned.m16n8k8.row.col.f32.tf32.tf32.f32 "
        "{%0,%1,%2,%3}, {%4,%5,%6,%7}, {%8,%9}, {%10,%11,%12,%13};"
        : "=f"(d[0]), "=f"(d[1]), "=f"(d[2]), "=f"(d[3])
        : "r"(a[0]), "r"(a[1]), "r"(a[2]), "r"(a[3]),
          "r"(b[0]), "r"(b[1]),
          "f"(c[0]), "f"(c[1]), "f"(c[2]), "f"(c[3]));
}

// ---------------- shared GEMM tile machinery (256 threads, 128x128 tile) ----------------
static const int AS_STRIDE = 132;
static const int WS_STRIDE = 136;
static const int SM_W = 128 * AS_STRIDE;            // 16896 floats = 67584 B
static const int SM_FLOATS = SM_W + 64 * WS_STRIDE; // + 8704 floats = 34816 B
static const int SM_BYTES = SM_FLOATS * 4;          // 102400 B -> 2 CTAs/SM

__device__ __forceinline__ void load_tile_tf32(const float* __restrict__ A, int M, int brow,
                                               uint32_t* as, int t, int ef) {
    const float4* A4 = reinterpret_cast<const float4*>(A);
    uint64_t pol = ef ? pol_ef() : 0;
    #pragma unroll
    for (int j = 0; j < 16; j++) {
        int flat = j * 256 + t;
        int row = flat >> 5, k4 = flat & 31;
        int gr = brow + row;
        float v[4] = {0.f, 0.f, 0.f, 0.f};
        if (gr < M) {
            const float* p = reinterpret_cast<const float*>(A4 + (size_t)gr * 32 + k4);
            if (ef) ld4_h(v, p, pol); else ld4(v, p);
        }
        uint4 u; u.x = to_tf32(v[0]); u.y = to_tf32(v[1]); u.z = to_tf32(v[2]); u.w = to_tf32(v[3]);
        *reinterpret_cast<uint4*>(as + row * AS_STRIDE + k4 * 4) = u;
    }
}

__device__ __forceinline__ void gemm_core_256(const uint32_t* as, uint32_t* wsm,
                                              const float* __restrict__ W,
                                              float dacc[2][8][4], int t) {
    const int wid = t >> 5, lane = t & 31;
    const int gid = lane >> 2, tig = lane & 3;
    const int m0 = (wid & 3) * 32, n0 = (wid >> 2) * 64;

    #pragma unroll
    for (int mi = 0; mi < 2; mi++)
        #pragma unroll
        for (int ni = 0; ni < 8; ni++)
            #pragma unroll
            for (int q = 0; q < 4; q++) dacc[mi][ni][q] = 0.f;

    #pragma unroll 1
    for (int ch = 0; ch < 2; ch++) {
        __syncthreads();
        {
            const float4* W4 = reinterpret_cast<const float4*>(W);
            #pragma unroll
            for (int j = 0; j < 8; j++) {
                int flat = j * 256 + t;
                int k = flat >> 5, c4 = flat & 31;
                float4 v = W4[(size_t)(ch * 64 + k) * 32 + c4];
                uint4 u; u.x = to_tf32(v.x); u.y = to_tf32(v.y);
                u.z = to_tf32(v.z); u.w = to_tf32(v.w);
                *reinterpret_cast<uint4*>(wsm + k * WS_STRIDE + c4 * 4) = u;
            }
        }
        __syncthreads();

        #pragma unroll
        for (int ks = 0; ks < 8; ks++) {
            const int k0 = ks * 8;
            uint32_t af[2][4];
            #pragma unroll
            for (int mi = 0; mi < 2; mi++) {
                const uint32_t* pa = as + (m0 + mi * 16 + gid) * AS_STRIDE + ch * 64 + k0;
                af[mi][0] = pa[tig];
                af[mi][1] = pa[8 * AS_STRIDE + tig];
                af[mi][2] = pa[tig + 4];
                af[mi][3] = pa[8 * AS_STRIDE + tig + 4];
            }
            uint32_t bf[8][2];
            #pragma unroll
            for (int ni = 0; ni < 8; ni++) {
                const uint32_t* pb = wsm + (k0 + tig) * WS_STRIDE + n0 + ni * 8 + gid;
                bf[ni][0] = pb[0];
                bf[ni][1] = pb[4 * WS_STRIDE];
            }
            #pragma unroll
            for (int mi = 0; mi < 2; mi++)
                #pragma unroll
                for (int ni = 0; ni < 8; ni++)
                    mma_tf32(dacc[mi][ni], af[mi], bf[ni], dacc[mi][ni]);
        }
    }
}

__device__ __forceinline__ void store_dacc_smem(float* ebt, float dacc[2][8][4],
                                                const float* __restrict__ bias, int t) {
    const int wid = t >> 5, lane = t & 31;
    const int gid = lane >> 2, tig = lane & 3;
    const int m0 = (wid & 3) * 32, n0 = (wid >> 2) * 64;
    #pragma unroll
    for (int ni = 0; ni < 8; ni++) {
        const int col = n0 + ni * 8 + 2 * tig;
        float b0 = 0.f, b1 = 0.f;
        if (bias) { b0 = bias[col]; b1 = bias[col + 1]; }
        #pragma unroll
        for (int mi = 0; mi < 2; mi++) {
            const int row = m0 + mi * 16 + gid;
            float2 v0; v0.x = dacc[mi][ni][0] + b0; v0.y = dacc[mi][ni][1] + b1;
            float2 v1; v1.x = dacc[mi][ni][2] + b0; v1.y = dacc[mi][ni][3] + b1;
            *reinterpret_cast<float2*>(ebt + row * AS_STRIDE + col) = v0;
            *reinterpret_cast<float2*>(ebt + (row + 8) * AS_STRIDE + col) = v1;
        }
    }
}

// ---------------- standalone multi-weight GEMM ----------------
struct G5 {
    const float* W[5];
    const float* B[5];
    float*       O[5];
    int OH[5];
    int nw;
    int IH;
};

__global__ void __launch_bounds__(256, 2) gemm_mma_kernel(
    const float* __restrict__ A, G5 g, int M)
{
    extern __shared__ float sm[];
    uint32_t* as  = reinterpret_cast<uint32_t*>(sm);
    uint32_t* wsm = reinterpret_cast<uint32_t*>(sm + SM_W);
    const int t = threadIdx.x;
    const int wid = t >> 5, lane = t & 31;
    const int gid = lane >> 2, tig = lane & 3;
    const int m0 = (wid & 3) * 32, n0 = (wid >> 2) * 64;
    const int brow = blockIdx.x * 128;

    load_tile_tf32(A, M, brow, as, t, g.IH);

    for (int w = 0; w < g.nw; w++) {
        float dacc[2][8][4];
        gemm_core_256(as, wsm, g.W[w], dacc, t);

        float* O = g.O[w];
        const float* bias = g.B[w];
        const int oh = g.OH[w];
        #pragma unroll
        for (int ni = 0; ni < 8; ni++) {
            const int col = n0 + ni * 8 + 2 * tig;
            float b0 = 0.f, b1 = 0.f;
            if (bias) { b0 = bias[col]; b1 = bias[col + 1]; }
            #pragma unroll
            for (int mi = 0; mi < 2; mi++) {
                const int row0 = brow + m0 + mi * 16 + gid;
                if (row0 < M)
                    st2_h(O + (size_t)row0 * 128 + col, dacc[mi][ni][0] + b0, dacc[mi][ni][1] + b1, oh);
                if (row0 + 8 < M)
                    st2_h(O + (size_t)(row0 + 8) * 128 + col, dacc[mi][ni][2] + b0, dacc[mi][ni][3] + b1, oh);
            }
        }
    }
}

// ---------------- fused edge layer: B1e GEMM + gated edge update (cp.async pipelined) ----
__global__ void __launch_bounds__(256, 2) edge_fused_kernel(
    const int* __restrict__ rows, const int* __restrict__ cols,
    float* __restrict__ e, const float* __restrict__ W, const float* __restrict__ bias,
    const float* __restrict__ A2, const float* __restrict__ A3,
    const float* __restrict__ B2, const float* __restrict__ B3,
    const float* __restrict__ lng, const float* __restrict__ lnb,
    float* __restrict__ acc, int E_)
{
    extern __shared__ float sm[];
    uint32_t* as  = reinterpret_cast<uint32_t*>(sm);
    uint32_t* wsm = reinterpret_cast<uint32_t*>(sm + SM_W);
    const int t = threadIdx.x;
    const int wid = t >> 5, lane = t & 31;
    const int brow = blockIdx.x * 128;

    // stage 1: b1e tile = e_tile @ W + bias
    load_tile_tf32(e, E_, brow, as, t, 1);
    float dacc[2][8][4];
    gemm_core_256(as, wsm, W, dacc, t);
    __syncthreads();
    float* ebt = sm;
    store_dacc_smem(ebt, dacc, bias, t);
    __syncthreads();

    // stage 2: warp per edge with cp.async double-buffered B-gather prefetch.
    // W-region smem is dead now: per warp 2 buffers x 4 vectors x 512B = 4KB.
    int idx;
    {
        int epos = brow + wid * 16 + (lane & 15);
        if (epos >= E_) epos = E_ - 1;
        const int* bp = (lane < 16) ? rows : cols;
        idx = bp[epos];
    }

    const uint64_t pef = pol_ef();
    const uint64_t pel = pol_el();
    const uint32_t pfw = smem_u32(sm) + (uint32_t)SM_W * 4 + (uint32_t)wid * 4096;
    const uint32_t loff = (uint32_t)lane * 16;

    // prologue: prefetch edge 0 B-gathers into buf 0
    {
        int r0 = __shfl_sync(0xffffffffu, idx, 0);
        int c0 = __shfl_sync(0xffffffffu, idx, 16);
        uint32_t b = pfw + loff;
        cpa16(b,        B2 + (size_t)r0 * 128 + lane * 4);
        cpa16(b + 512,  B3 + (size_t)r0 * 128 + lane * 4);
        cpa16(b + 1024, B2 + (size_t)c0 * 128 + lane * 4);
        cpa16(b + 1536, B3 + (size_t)c0 * 128 + lane * 4);
        cpa_commit();
    }

    float gg[4], gb[4];
    ld4(gg, lng + lane * 4); ld4(gb, lnb + lane * 4);
    const float inv = 1.f / 128.f;

    #pragma unroll 1
    for (int i = 0; i < 16; i++) {
        const int le = wid * 16 + i;
        const int w = brow + le;
        if (w >= E_) break;
        const int r = __shfl_sync(0xffffffffu, idx, i);
        const int c = __shfl_sync(0xffffffffu, idx, 16 + i);

        // prefetch edge i+1 (clamped at tail) into buf (i+1)&1
        {
            const int ipn = (i < 15) ? i + 1 : 15;
            int rn = __shfl_sync(0xffffffffu, idx, ipn);
            int cn = __shfl_sync(0xffffffffu, idx, 16 + ipn);
            uint32_t b = pfw + ((i + 1) & 1) * 2048 + loff;
            cpa16(b,        B2 + (size_t)rn * 128 + lane * 4);
            cpa16(b + 512,  B3 + (size_t)rn * 128 + lane * 4);
            cpa16(b + 1024, B2 + (size_t)cn * 128 + lane * 4);
            cpa16(b + 1536, B3 + (size_t)cn * 128 + lane * 4);
            cpa_commit();
        }

        const size_t eo = (size_t)w * 128 + lane * 4;
        const size_t ro = (size_t)r * 128 + lane * 4;
        const size_t co = (size_t)c * 128 + lane * 4;

        // direct loads: only consumed late in the iteration
        float a2r[4], a3c[4], ev[4], b1[4];
        ld4_h(a2r, A2 + ro, pel);
        ld4_h(a3c, A3 + co, pel);
        ld4_h(ev, e + eo, pef);
        ld4(b1, ebt + le * AS_STRIDE + lane * 4);

        // wait for edge i's prefetched B-gathers
        cpa_wait1();
        float b2r[4], b3r[4], b2c[4], b3c[4];
        const uint32_t bb = pfw + (i & 1) * 2048 + loff;
        lds4(b2r, bb);
        lds4(b3r, bb + 512);
        lds4(b2c, bb + 1024);
        lds4(b3c, bb + 1536);

        float gji[4], gik[4];
        float s1 = 0.f, q1 = 0.f, s2 = 0.f, q2 = 0.f;
        #pragma unroll
        for (int j = 0; j < 4; j++) {
            float u = fmaxf(b1[j] + b2r[j] + b3c[j], 0.f);
            float v = fmaxf(b1[j] + b2c[j] + b3r[j], 0.f);
            gji[j] = u; gik[j] = v;
            s1 += u; q1 = fmaf(u, u, q1);
            s2 += v; q2 = fmaf(v, v, q2);
        }
        #pragma unroll
        for (int o = 16; o; o >>= 1) {
            s1 += __shfl_xor_sync(0xffffffffu, s1, o);
            q1 += __shfl_xor_sync(0xffffffffu, q1, o);
            s2 += __shfl_xor_sync(0xffffffffu, s2, o);
            q2 += __shfl_xor_sync(0xffffffffu, q2, o);
        }
        float m1 = s1 * inv, m2 = s2 * inv;
        float is1 = rsqrtf(fmaxf(q1 * inv - m1 * m1, 0.f) + 1e-5f);
        float is2 = rsqrtf(fmaxf(q2 * inv - m2 * m2, 0.f) + 1e-5f);

        float eji[4], sg1[4], sg2[4];
        float t1 = 0.f, t2 = 0.f;
        #pragma unroll
        for (int j = 0; j < 4; j++) {
            eji[j]    = ev[j] + (gji[j] - m1) * is1 * gg[j] + gb[j];
            float eik = ev[j] + (gik[j] - m2) * is2 * gg[j] + gb[j];
            sg1[j] = __fdividef(1.f, 1.f + __expf(-eji[j])); t1 += sg1[j];
            sg2[j] = __fdividef(1.f, 1.f + __expf(-eik));    t2 += sg2[j];
        }
        #pragma unroll
        for (int o = 16; o; o >>= 1) {
            t1 += __shfl_xor_sync(0xffffffffu, t1, o);
            t2 += __shfl_xor_sync(0xffffffffu, t2, o);
        }
        float w1 = __fdividef(1.f, t1 + 1e-6f);
        float w2 = __fdividef(1.f, t2 + 1e-6f);

        float mji[4], mik[4];
        #pragma unroll
        for (int j = 0; j < 4; j++) {
            mji[j] = a2r[j] * sg1[j] * w1;
            mik[j] = a3c[j] * sg2[j] * w2;
        }
        red_add_v4(acc + co, mji);
        red_add_v4(acc + ro, mik);
        st4_h(e + eo, eji, pef);
    }
}

// ---------------- fused final scorer: ec GEMM + relu-dot (cp.async pipelined) ----------
__global__ void __launch_bounds__(256, 2) final_fused_kernel(
    const int* __restrict__ rows, const int* __restrict__ cols,
    const float* __restrict__ ha, const float* __restrict__ hb,
    const float* __restrict__ e, const float* __restrict__ W,
    const float* __restrict__ s1b, const float* __restrict__ s2w,
    const float* __restrict__ s2b, float* __restrict__ out, int E_)
{
    extern __shared__ float sm[];
    uint32_t* as  = reinterpret_cast<uint32_t*>(sm);
    uint32_t* wsm = reinterpret_cast<uint32_t*>(sm + SM_W);
    const int t = threadIdx.x;
    const int wid = t >> 5, lane = t & 31;
    const int brow = blockIdx.x * 128;

    load_tile_tf32(e, E_, brow, as, t, 1);
    float dacc[2][8][4];
    gemm_core_256(as, wsm, W, dacc, t);
    __syncthreads();
    float* ebt = sm;
    store_dacc_smem(ebt, dacc, nullptr, t);
    __syncthreads();

    int idx;
    {
        int epos = brow + wid * 16 + (lane & 15);
        if (epos >= E_) epos = E_ - 1;
        const int* bp = (lane < 16) ? rows : cols;
        idx = bp[epos];
    }

    const uint32_t pfw = smem_u32(sm) + (uint32_t)SM_W * 4 + (uint32_t)wid * 2048;
    const uint32_t loff = (uint32_t)lane * 16;

    {
        int r0 = __shfl_sync(0xffffffffu, idx, 0);
        int c0 = __shfl_sync(0xffffffffu, idx, 16);
        uint32_t b = pfw + loff;
        cpa16(b,       ha + (size_t)r0 * 128 + lane * 4);
        cpa16(b + 512, hb + (size_t)c0 * 128 + lane * 4);
        cpa_commit();
    }

    float b4[4], wv[4];
    ld4(b4, s1b + lane * 4);
    ld4(wv, s2w + lane * 4);
    const float s2b0 = s2b[0];

    #pragma unroll 1
    for (int i = 0; i < 16; i++) {
        const int le = wid * 16 + i;
        const int w = brow + le;
        if (w >= E_) break;

        {
            const int ipn = (i < 15) ? i + 1 : 15;
            int rn = __shfl_sync(0xffffffffu, idx, ipn);
            int cn = __shfl_sync(0xffffffffu, idx, 16 + ipn);
            uint32_t b = pfw + ((i + 1) & 1) * 1024 + loff;
            cpa16(b,       ha + (size_t)rn * 128 + lane * 4);
            cpa16(b + 512, hb + (size_t)cn * 128 + lane * 4);
            cpa_commit();
        }

        float C[4];
        ld4(C, ebt + le * AS_STRIDE + lane * 4);

        cpa_wait1();
        float A[4], B[4];
        const uint32_t bb = pfw + (i & 1) * 1024 + loff;
        lds4(A, bb);
        lds4(B, bb + 512);

        float p = 0.f;
        #pragma unroll
        for (int j = 0; j < 4; j++) {
            float u = fmaxf(A[j] + B[j] + C[j] + b4[j], 0.f);
            p = fmaf(u, wv[j], p);
        }
        #pragma unroll
        for (int o = 16; o; o >>= 1) p += __shfl_xor_sync(0xffffffffu, p, o);
        if (lane == 0) out[w] = p + s2b0;
    }
}

// ---------------- zero ----------------
__global__ void zero_kernel(float* __restrict__ p, int n) {
    int i = (blockIdx.x * blockDim.x + threadIdx.x) * 4;
    if (i < n) *reinterpret_cast<float4*>(p + i) = make_float4(0.f, 0.f, 0.f, 0.f);
}

// ---------------- embed stage1: out = LN(relu(in @ W + b)) ----------------
__global__ void __launch_bounds__(256) embed_ln_kernel(
    const float* __restrict__ in, const float* __restrict__ W, const float* __restrict__ bias,
    const float* __restrict__ lng, const float* __restrict__ lnb,
    float* __restrict__ out, int M, int Kin)
{
    const int w = blockIdx.x * 8 + (threadIdx.x >> 5);
    const int lane = threadIdx.x & 31;
    if (w >= M) return;
    const float* xr = in + (size_t)w * Kin;
    float x0 = (lane < Kin) ? xr[lane] : 0.f;
    float x1 = (lane + 32 < Kin) ? xr[lane + 32] : 0.f;

    float a[4];
    ld4(a, bias + lane * 4);
    for (int k = 0; k < Kin; k++) {
        float xk = __shfl_sync(0xffffffffu, (k < 32) ? x0 : x1, k & 31);
        float4 wv = *reinterpret_cast<const float4*>(W + k * 128 + lane * 4);
        a[0] = fmaf(xk, wv.x, a[0]);
        a[1] = fmaf(xk, wv.y, a[1]);
        a[2] = fmaf(xk, wv.z, a[2]);
        a[3] = fmaf(xk, wv.w, a[3]);
    }
    float s = 0.f, q = 0.f;
    #pragma unroll
    for (int i = 0; i < 4; i++) {
        a[i] = fmaxf(a[i], 0.f);
        s += a[i]; q = fmaf(a[i], a[i], q);
    }
    #pragma unroll
    for (int o = 16; o; o >>= 1) {
        s += __shfl_xor_sync(0xffffffffu, s, o);
        q += __shfl_xor_sync(0xffffffffu, q, o);
    }
    const float inv = 1.f / 128.f;
    float m = s * inv;
    float is = rsqrtf(fmaxf(q * inv - m * m, 0.f) + 1e-5f);
    float gg[4], gb[4], o4[4];
    ld4(gg, lng + lane * 4); ld4(gb, lnb + lane * 4);
    #pragma unroll
    for (int i = 0; i < 4; i++) o4[i] = (a[i] - m) * is * gg[i] + gb[i];
    uint64_t pef = pol_ef();
    st4_h(out + (size_t)w * 128 + lane * 4, o4, pef);
}

// ---------------- node update: h += LN(relu(A1h + acc)); acc = 0 ----------------
__global__ void __launch_bounds__(256) node_update_kernel(
    const float* __restrict__ A1, float* __restrict__ acc, float* __restrict__ h,
    const float* __restrict__ lng, const float* __restrict__ lnb, int M)
{
    const int w = blockIdx.x * 8 + (threadIdx.x >> 5);
    const int lane = threadIdx.x & 31;
    if (w >= M) return;
    const size_t off = (size_t)w * 128 + lane * 4;
    float a[4], cc[4], t[4];
    ld4(a, A1 + off); ld4(cc, acc + off);
    float s = 0.f, q = 0.f;
    #pragma unroll
    for (int i = 0; i < 4; i++) {
        t[i] = fmaxf(a[i] + cc[i], 0.f);
        s += t[i]; q = fmaf(t[i], t[i], q);
    }
    #pragma unroll
    for (int o = 16; o; o >>= 1) {
        s += __shfl_xor_sync(0xffffffffu, s, o);
        q += __shfl_xor_sync(0xffffffffu, q, o);
    }
    const float inv = 1.f / 128.f;
    float m = s * inv;
    float is = rsqrtf(fmaxf(q * inv - m * m, 0.f) + 1e-5f);
    float gg[4], gb[4], hv[4];
    ld4(gg, lng + lane * 4); ld4(gb, lnb + lane * 4);
    ld4(hv, h + off);
    #pragma unroll
    for (int i = 0; i < 4; i++) hv[i] += (t[i] - m) * is * gg[i] + gb[i];
    st4(h + off, hv);
    float z[4] = {0.f, 0.f, 0.f, 0.f};
    st4(acc + off, z);
}

// ---------------- host ----------------
extern "C" void kernel_launch(void* const* d_in, const int* in_sizes, int n_in,
                              void* d_out, int out_size)
{
    const float* x    = (const float*)d_in[0];
    const float* ea   = (const float*)d_in[1];
    const int*   ei   = (const int*)  d_in[2];
    const float* W11w = (const float*)d_in[3];
    const float* W11b = (const float*)d_in[4];
    const float* W12w = (const float*)d_in[5];
    const float* W12b = (const float*)d_in[6];
    const float* W21w = (const float*)d_in[7];
    const float* W21b = (const float*)d_in[8];
    const float* W22w = (const float*)d_in[9];
    const float* W22b = (const float*)d_in[10];
    const float* ln1g = (const float*)d_in[11];
    const float* ln1b = (const float*)d_in[12];
    const float* ln2g = (const float*)d_in[13];
    const float* ln2b = (const float*)d_in[14];
    const float* Aw   = (const float*)d_in[15];
    const float* Ab   = (const float*)d_in[16];
    const float* Bw   = (const float*)d_in[17];
    const float* Bb   = (const float*)d_in[18];
    const float* lnhg = (const float*)d_in[19];
    const float* lnhb = (const float*)d_in[20];
    const float* lneg = (const float*)d_in[21];
    const float* lneb = (const float*)d_in[22];
    const float* s1w  = (const float*)d_in[23];
    const float* s1b  = (const float*)d_in[24];
    const float* s2w  = (const float*)d_in[25];
    const float* s2b  = (const float*)d_in[26];

    int Nn = in_sizes[0] / 64;
    int Ee = in_sizes[2] / 2;
    if (Nn > CAP_N) Nn = CAP_N;
    if (Ee > CAP_E) Ee = CAP_E;

    float *ph, *pacc, *pA1, *pA2, *pA3, *pB2, *pB3, *pe, *ptmp;
    cudaGetSymbolAddress((void**)&ph,   g_h);
    cudaGetSymbolAddress((void**)&pacc, g_acc);
    cudaGetSymbolAddress((void**)&pA1,  g_A1);
    cudaGetSymbolAddress((void**)&pA2,  g_A2);
    cudaGetSymbolAddress((void**)&pA3,  g_A3);
    cudaGetSymbolAddress((void**)&pB2,  g_B2);
    cudaGetSymbolAddress((void**)&pB3,  g_B3);
    cudaGetSymbolAddress((void**)&pe,   g_e);
    cudaGetSymbolAddress((void**)&ptmp, g_tmp);

    cudaFuncSetAttribute(gemm_mma_kernel,   cudaFuncAttributeMaxDynamicSharedMemorySize, SM_BYTES);
    cudaFuncSetAttribute(edge_fused_kernel, cudaFuncAttributeMaxDynamicSharedMemorySize, SM_BYTES);
    cudaFuncSetAttribute(final_fused_kernel,cudaFuncAttributeMaxDynamicSharedMemorySize, SM_BYTES);

    auto gemm_tc = [&](const float* A, G5& g, int M) {
        int tiles = (M + 127) / 128;
        gemm_mma_kernel<<<tiles, 256, SM_BYTES>>>(A, g, M);
    };
    auto gemm1 = [&](const float* A, const float* W, const float* b, float* o, int M,
                     int ih, int oh) {
        G5 g; g.nw = 1; g.W[0] = W; g.B[0] = b; g.O[0] = o; g.OH[0] = oh; g.IH = ih;
        gemm_tc(A, g, M);
    };

    const int etiles = (Ee + 127) / 128;

    // node embed: h = LN(relu(x@W11+b)) @ W12 + b     (uses acc as temp)
    embed_ln_kernel<<<(Nn + 7) / 8, 256>>>(x, W11w, W11b, ln1g, ln1b, pacc, Nn, 64);
    gemm1(pacc, W12w, W12b, ph, Nn, 0, 0);
    // edge embed: e = LN(relu(ea@W21+b)) @ W22 + b
    embed_ln_kernel<<<(Ee + 7) / 8, 256>>>(ea, W21w, W21b, ln2g, ln2b, ptmp, Ee, 32);
    gemm1(ptmp, W22w, W22b, pe, Ee, 1, 1);

    // zero the scatter accumulator
    zero_kernel<<<(Nn * 128 / 4 + 255) / 256, 256>>>(pacc, Nn * 128);

    for (int l = 0; l < 3; l++) {
        const float* Awl = Aw + (size_t)l * 3 * 128 * 128;
        const float* Abl = Ab + (size_t)l * 3 * 128;
        const float* Bwl = Bw + (size_t)l * 3 * 128 * 128;
        const float* Bbl = Bb + (size_t)l * 3 * 128;
        {
            G5 g; g.nw = 5; g.IH = 0;
            g.W[0] = Awl;          g.B[0] = Abl;        g.O[0] = pA1; g.OH[0] = 0;
            g.W[1] = Awl + 16384;  g.B[1] = Abl + 128;  g.O[1] = pA2; g.OH[1] = 2;
            g.W[2] = Awl + 32768;  g.B[2] = Abl + 256;  g.O[2] = pA3; g.OH[2] = 2;
            g.W[3] = Bwl + 16384;  g.B[3] = Bbl + 128;  g.O[3] = pB2; g.OH[3] = 2;
            g.W[4] = Bwl + 32768;  g.B[4] = Bbl + 256;  g.O[4] = pB3; g.OH[4] = 2;
            gemm_tc(ph, g, Nn);
        }
        edge_fused_kernel<<<etiles, 256, SM_BYTES>>>(
            ei, ei + Ee, pe, Bwl, Bbl, pA2, pA3, pB2, pB3,
            lneg + l * 128, lneb + l * 128, pacc, Ee);
        node_update_kernel<<<(Nn + 7) / 8, 256>>>(pA1, pacc, ph,
                                                  lnhg + l * 128, lnhb + l * 128, Nn);
    }

    // final scorer: score = relu(h[row]@Sa + h[col]@Sb + e@Sc + s1b) @ s2w + s2b
    {
        G5 g; g.nw = 2; g.IH = 0;
        g.W[0] = s1w;          g.B[0] = nullptr; g.O[0] = pA1; g.OH[0] = 2;
        g.W[1] = s1w + 16384;  g.B[1] = nullptr; g.O[1] = pA2; g.OH[1] = 2;
        gemm_tc(ph, g, Nn);
    }
    final_fused_kernel<<<etiles, 256, SM_BYTES>>>(
        ei, ei + Ee, pA1, pA2, pe, s1w + 32768, s1b, s2w, s2b, (float*)d_out, Ee);
}